// round 6
// baseline (speedup 1.0000x reference)
#include <cuda_runtime.h>
#include <cuda_bf16.h>
#include <cuda_fp16.h>
#include <math.h>

// ---------------------------------------------------------------------------
// Contrast on legacy mma.sync m16n8k16 (baseline PTX; harness targets sm_103).
// Operands pre-split in GMEM (bf16 hi/lo or fp16). GEMM mainloop:
// cp.async double-buffered staging + ldmatrix fragment loads, 1 sync/ktile.
// ---------------------------------------------------------------------------

namespace {
constexpr int KBLK  = 1032;        // u32 words per k16-block: 128*8 + 8 pad
constexpr int SLAB  = 4 * KBLK;    // words per matrix-half per BK=64 tile
constexpr int SLABB = SLAB * 4;    // bytes
}

// ------------------------------ scratch (u32 words) -------------------------
__device__ unsigned g_Zh [8388608], g_Zl [8388608];   // split(za|zb) 16384x1024
__device__ unsigned g_Hh [8388608], g_Hl [8388608];   // H split     16384x1024
__device__ unsigned g_Ph [4194304], g_Pl [4194304];   // P split     16384x512
__device__ unsigned g_Qh [4194304], g_Ql [4194304];
__device__ unsigned g_Kh [4194304], g_Kl [4194304];
__device__ unsigned g_Vh [4194304];                   // V fp16      16384x512
__device__ unsigned g_VT [4194304];                   // V^T fp16 per half [512,8192]
__device__ unsigned g_W1h[524288],  g_W1l[524288];
__device__ unsigned g_W2h[262144],  g_W2l[262144];
__device__ unsigned g_Wqh[131072],  g_Wql[131072];
__device__ unsigned g_Wkh[131072],  g_Wkl[131072];
__device__ unsigned g_Wvh[131072],  g_Wvl[131072];
__device__ float    g_S  [67108864];                  // fp32 scores
__device__ unsigned g_Sh [33554432];                  // fp16 softmaxed scores

// ------------------------------ helpers ------------------------------------
__device__ __forceinline__ void mma_bf16(float* c, const unsigned* a,
                                         unsigned b0, unsigned b1) {
    asm volatile(
        "mma.sync.aligned.m16n8k16.row.col.f32.bf16.bf16.f32 "
        "{%0,%1,%2,%3}, {%4,%5,%6,%7}, {%8,%9}, {%0,%1,%2,%3};"
        : "+f"(c[0]), "+f"(c[1]), "+f"(c[2]), "+f"(c[3])
        : "r"(a[0]), "r"(a[1]), "r"(a[2]), "r"(a[3]), "r"(b0), "r"(b1));
}

__device__ __forceinline__ void mma_fp16(float* c, const unsigned* a,
                                         unsigned b0, unsigned b1) {
    asm volatile(
        "mma.sync.aligned.m16n8k16.row.col.f32.f16.f16.f32 "
        "{%0,%1,%2,%3}, {%4,%5,%6,%7}, {%8,%9}, {%0,%1,%2,%3};"
        : "+f"(c[0]), "+f"(c[1]), "+f"(c[2]), "+f"(c[3])
        : "r"(a[0]), "r"(a[1]), "r"(a[2]), "r"(a[3]), "r"(b0), "r"(b1));
}

__device__ __forceinline__ void ldsm_x4(unsigned* r, unsigned addr) {
    asm volatile("ldmatrix.sync.aligned.m8n8.x4.shared.b16 {%0,%1,%2,%3}, [%4];"
        : "=r"(r[0]), "=r"(r[1]), "=r"(r[2]), "=r"(r[3]) : "r"(addr));
}

__device__ __forceinline__ void cp16(unsigned dst, const void* src) {
    asm volatile("cp.async.cg.shared.global [%0], [%1], 16;" :: "r"(dst), "l"(src));
}

__device__ __forceinline__ unsigned smem_u32(const void* p) {
    unsigned a;
    asm("{ .reg .u64 t; cvta.to.shared.u64 t, %1; cvt.u32.u64 %0, t; }"
        : "=r"(a) : "l"(p));
    return a;
}

__device__ __forceinline__ void split2(float x, float y, unsigned& hi, unsigned& lo) {
    __nv_bfloat16 hx = __float2bfloat16(x);
    __nv_bfloat16 hy = __float2bfloat16(y);
    __nv_bfloat16 lx = __float2bfloat16(x - __bfloat162float(hx));
    __nv_bfloat16 ly = __float2bfloat16(y - __bfloat162float(hy));
    hi = ((unsigned)__bfloat16_as_ushort(hy) << 16) | (unsigned)__bfloat16_as_ushort(hx);
    lo = ((unsigned)__bfloat16_as_ushort(ly) << 16) | (unsigned)__bfloat16_as_ushort(lx);
}

__device__ __forceinline__ unsigned packh2(float x, float y) {
    __half2 h = __floats2half2_rn(x, y);
    return *reinterpret_cast<unsigned*>(&h);
}

// --------------------------- input split -----------------------------------
__global__ void __launch_bounds__(256, 8)
split_in(const float* __restrict__ za, const float* __restrict__ zb,
         unsigned* __restrict__ Zh, unsigned* __restrict__ Zl)
{
    const size_t t = (size_t)blockIdx.x * 256 + threadIdx.x;
    const size_t f = t * 4;
    const float4 v = (f < (size_t)8388608)
        ? *reinterpret_cast<const float4*>(za + f)
        : *reinterpret_cast<const float4*>(zb + (f - 8388608));
    uint2 h, l;
    split2(v.x, v.y, h.x, l.x);
    split2(v.z, v.w, h.y, l.y);
    *reinterpret_cast<uint2*>(Zh + t * 2) = h;
    *reinterpret_cast<uint2*>(Zl + t * 2) = l;
}

// --------------------------- weight transpose + split -----------------------
__global__ void __launch_bounds__(256, 4)
transpose_split(const float* __restrict__ src, unsigned* __restrict__ dh,
                unsigned* __restrict__ dl, int R, int C)
{
    __shared__ float t[32][33];
    const int bx = blockIdx.x * 32;
    const int by = blockIdx.y * 32;
    const int x  = bx + threadIdx.x;
    #pragma unroll
    for (int i = threadIdx.y; i < 32; i += 8)
        t[i][threadIdx.x] = src[(size_t)(by + i) * C + x];
    __syncthreads();
    const int xo = by + threadIdx.x;
    unsigned short* ph = reinterpret_cast<unsigned short*>(dh);
    unsigned short* pl = reinterpret_cast<unsigned short*>(dl);
    #pragma unroll
    for (int i = threadIdx.y; i < 32; i += 8) {
        const float v = t[threadIdx.x][i];
        const __nv_bfloat16 h = __float2bfloat16(v);
        const __nv_bfloat16 l = __float2bfloat16(v - __bfloat162float(h));
        ph[(size_t)(bx + i) * R + xo] = __bfloat16_as_ushort(h);
        pl[(size_t)(bx + i) * R + xo] = __bfloat16_as_ushort(l);
    }
}

// --------------------------- fp16 transpose --------------------------------
__global__ void __launch_bounds__(256, 4)
transpose_h(const unsigned* __restrict__ srcw, unsigned* __restrict__ dstw, int R, int C)
{
    __shared__ unsigned short t[32][34];
    const unsigned short* src = reinterpret_cast<const unsigned short*>(srcw);
    unsigned short* dst = reinterpret_cast<unsigned short*>(dstw);
    const int bx = blockIdx.x * 32;
    const int by = blockIdx.y * 32;
    const int x  = bx + threadIdx.x;
    #pragma unroll
    for (int i = threadIdx.y; i < 32; i += 8)
        t[i][threadIdx.x] = src[(size_t)(by + i) * C + x];
    __syncthreads();
    const int xo = by + threadIdx.x;
    #pragma unroll
    for (int i = threadIdx.y; i < 32; i += 8)
        dst[(size_t)(bx + i) * R + xo] = t[threadIdx.x][i];
}

// ------------------------------ GEMM ---------------------------------------
// C = epi(A[M,K] @ B[N,K]^T), operands pre-packed 16-bit (u32 pitch K/2).
// PREC 0: bf16 split-3.  PREC 1: fp16 single.
// EPI 0: v*=scale ; EPI 1: v+=bias ; EPI 2: elu(v+bias)
// OFMT 0: f32 Cf ; OFMT 1: split bf16 Ch/Cl ; OFMT 2: fp16 Ch
template <int EPI, int PREC, int OFMT>
__global__ void __launch_bounds__(256, 1)
gemm_mm(const unsigned* __restrict__ Ah, const unsigned* __restrict__ Al,
        const unsigned* __restrict__ Bh, const unsigned* __restrict__ Bl,
        const float* __restrict__ bias,
        float* __restrict__ Cf, unsigned* __restrict__ Ch, unsigned* __restrict__ Cl,
        int M, int N, int K, int ldc, int coff, float scale)
{
    extern __shared__ unsigned sm[];
    const unsigned tilesb = smem_u32(sm);
    constexpr unsigned NHALF = (PREC == 0) ? 4u : 2u;        // matrix-halves
    constexpr unsigned YOFFB = (PREC == 0) ? 2u * SLABB : SLABB;
    constexpr unsigned BUFB  = NHALF * SLABB;                 // bytes per buffer

    const int tid  = threadIdx.x;
    const int bm   = blockIdx.y * 128;
    const int bn   = blockIdx.x * 128;
    const int warp = tid >> 5;
    const int lane = tid & 31;
    const int wm   = (warp >> 2) * 64;
    const int wn   = (warp & 3) * 32;
    const int g    = lane >> 2;
    const int tk   = lane & 3;
    const int t2   = tk * 2;

    // ldmatrix addresses (buffer 0; add blk/buf byte offsets at use)
    const int mi = lane >> 3;
    const int rl = (lane & 7) + ((mi & 1) << 3);
    const int kg = mi >> 1;
    unsigned relA[4], relB[2];
    #pragma unroll
    for (int mf = 0; mf < 4; mf++) {
        const int row = wm + mf * 16 + rl;
        const int w   = (kg << 2) ^ (((row >> 2) & 1) << 2);
        relA[mf] = tilesb + 4u * (unsigned)(row * 8 + w);
    }
    #pragma unroll
    for (int p = 0; p < 2; p++) {
        const int nf  = 2 * p + (mi >> 1);
        const int row = wn + nf * 8 + (lane & 7);
        const int w   = ((mi & 1) << 2) ^ (((row >> 2) & 1) << 2);
        relB[p] = tilesb + YOFFB + 4u * (unsigned)(row * 8 + w);
    }

    // staging mapping
    const int srow  = tid >> 3;
    const int scol8 = (tid & 7) * 8;
    const int sblk  = scol8 >> 4;
    const int sw0   = ((scol8 & 15) >> 1) ^ (((srow >> 2) & 1) * 4);
    const unsigned sidx = (unsigned)(sblk * KBLK + srow * 8 + sw0);
    const int kw = K >> 1;

    float acc[4][4][4];
    #pragma unroll
    for (int i = 0; i < 4; i++)
        #pragma unroll
        for (int j = 0; j < 4; j++)
            #pragma unroll
            for (int e = 0; e < 4; e++) acc[i][j][e] = 0.f;

    auto stage = [&](int kt, unsigned bufb) {
        const int w0 = kt * 32 + (scol8 >> 1);
        const unsigned d0 = tilesb + bufb + 4u * sidx;
        #pragma unroll
        for (int i = 0; i < 4; i++) {
            const size_t ro = (size_t)(bm + srow + 32 * i) * kw + w0;
            cp16(d0 + 1024u * i, Ah + ro);
            if (PREC == 0) cp16(d0 + 1024u * i + SLABB, Al + ro);
        }
        #pragma unroll
        for (int i = 0; i < 4; i++) {
            const size_t ro = (size_t)(bn + srow + 32 * i) * kw + w0;
            cp16(d0 + 1024u * i + YOFFB, Bh + ro);
            if (PREC == 0) cp16(d0 + 1024u * i + YOFFB + SLABB, Bl + ro);
        }
        asm volatile("cp.async.commit_group;" ::: "memory");
    };

    auto compute = [&](unsigned bufb) {
        #pragma unroll
        for (int blk = 0; blk < 4; blk++) {
            const unsigned off = bufb + (unsigned)(blk * (KBLK * 4));
            unsigned a[4][4], b[2][4];
            #pragma unroll
            for (int mf = 0; mf < 4; mf++) ldsm_x4(a[mf], relA[mf] + off);
            #pragma unroll
            for (int p = 0; p < 2; p++)    ldsm_x4(b[p],  relB[p] + off);
            #pragma unroll
            for (int mf = 0; mf < 4; mf++)
                #pragma unroll
                for (int nf = 0; nf < 4; nf++) {
                    const unsigned b0 = b[nf >> 1][(nf & 1) * 2];
                    const unsigned b1 = b[nf >> 1][(nf & 1) * 2 + 1];
                    if (PREC == 0) mma_bf16(acc[mf][nf], a[mf], b0, b1);
                    else           mma_fp16(acc[mf][nf], a[mf], b0, b1);
                }
            if (PREC == 0) {
                unsigned bl2[2][4];
                #pragma unroll
                for (int p = 0; p < 2; p++) ldsm_x4(bl2[p], relB[p] + off + SLABB);
                #pragma unroll
                for (int mf = 0; mf < 4; mf++)
                    #pragma unroll
                    for (int nf = 0; nf < 4; nf++)
                        mma_bf16(acc[mf][nf], a[mf],
                                 bl2[nf >> 1][(nf & 1) * 2], bl2[nf >> 1][(nf & 1) * 2 + 1]);
                unsigned al2[4][4];
                #pragma unroll
                for (int mf = 0; mf < 4; mf++) ldsm_x4(al2[mf], relA[mf] + off + SLABB);
                #pragma unroll
                for (int mf = 0; mf < 4; mf++)
                    #pragma unroll
                    for (int nf = 0; nf < 4; nf++)
                        mma_bf16(acc[mf][nf], al2[mf],
                                 b[nf >> 1][(nf & 1) * 2], b[nf >> 1][(nf & 1) * 2 + 1]);
            }
        }
    };

    const int ktiles = K / 64;
    stage(0, 0u);
    for (int kt = 0; kt < ktiles; kt++) {
        asm volatile("cp.async.wait_group 0;" ::: "memory");
        __syncthreads();
        if (kt + 1 < ktiles) stage(kt + 1, (unsigned)((kt + 1) & 1) * BUFB);
        compute((unsigned)(kt & 1) * BUFB);
    }

    // epilogue
    #pragma unroll
    for (int mf = 0; mf < 4; mf++) {
        #pragma unroll
        for (int nf = 0; nf < 4; nf++) {
            const int row = bm + wm + mf * 16 + g;
            const int col = bn + wn + nf * 8 + t2;
            float v0 = acc[mf][nf][0], v1 = acc[mf][nf][1];
            float v2 = acc[mf][nf][2], v3 = acc[mf][nf][3];
            if (EPI == 0) {
                v0 *= scale; v1 *= scale; v2 *= scale; v3 *= scale;
            } else {
                const float bb0 = bias[col], bb1 = bias[col + 1];
                v0 += bb0; v1 += bb1; v2 += bb0; v3 += bb1;
                if (EPI == 2) {
                    v0 = v0 > 0.f ? v0 : expm1f(v0);
                    v1 = v1 > 0.f ? v1 : expm1f(v1);
                    v2 = v2 > 0.f ? v2 : expm1f(v2);
                    v3 = v3 > 0.f ? v3 : expm1f(v3);
                }
            }
            if (OFMT == 0) {
                *reinterpret_cast<float2*>(Cf + (size_t)row * ldc + coff + col)       = make_float2(v0, v1);
                *reinterpret_cast<float2*>(Cf + (size_t)(row + 8) * ldc + coff + col) = make_float2(v2, v3);
            } else if (OFMT == 1) {
                unsigned h, l;
                split2(v0, v1, h, l);
                Ch[(size_t)row * ldc + (col >> 1)] = h;
                Cl[(size_t)row * ldc + (col >> 1)] = l;
                split2(v2, v3, h, l);
                Ch[(size_t)(row + 8) * ldc + (col >> 1)] = h;
                Cl[(size_t)(row + 8) * ldc + (col >> 1)] = l;
            } else {
                Ch[(size_t)row * ldc + (col >> 1)]       = packh2(v0, v1);
                Ch[(size_t)(row + 8) * ldc + (col >> 1)] = packh2(v2, v3);
            }
        }
    }
}

// ------------------------------ softmax ------------------------------------
__global__ void __launch_bounds__(256, 1)
softmax_rows(const float* __restrict__ S, unsigned* __restrict__ Sh)
{
    const int row = blockIdx.x;
    const float4* p = reinterpret_cast<const float4*>(S + (size_t)row * 8192);
    const int tid = threadIdx.x;

    float4 v[8];
    #pragma unroll
    for (int i = 0; i < 8; i++) v[i] = p[tid + 256 * i];

    float m = -3.402823e38f;
    #pragma unroll
    for (int i = 0; i < 8; i++)
        m = fmaxf(m, fmaxf(fmaxf(v[i].x, v[i].y), fmaxf(v[i].z, v[i].w)));

    __shared__ float red[8];
    #pragma unroll
    for (int o = 16; o; o >>= 1) m = fmaxf(m, __shfl_xor_sync(0xffffffffu, m, o));
    if ((tid & 31) == 0) red[tid >> 5] = m;
    __syncthreads();
    float mm = red[0];
    #pragma unroll
    for (int i = 1; i < 8; i++) mm = fmaxf(mm, red[i]);

    float s = 0.f;
    #pragma unroll
    for (int i = 0; i < 8; i++) {
        v[i].x = __expf(v[i].x - mm); s += v[i].x;
        v[i].y = __expf(v[i].y - mm); s += v[i].y;
        v[i].z = __expf(v[i].z - mm); s += v[i].z;
        v[i].w = __expf(v[i].w - mm); s += v[i].w;
    }
    #pragma unroll
    for (int o = 16; o; o >>= 1) s += __shfl_xor_sync(0xffffffffu, s, o);
    __syncthreads();
    if ((tid & 31) == 0) red[tid >> 5] = s;
    __syncthreads();
    float st = 0.f;
    #pragma unroll
    for (int i = 0; i < 8; i++) st += red[i];
    const float inv = 1.0f / st;

    unsigned* q = Sh + (size_t)row * 4096;
    #pragma unroll
    for (int i = 0; i < 8; i++) {
        uint2 w;
        w.x = packh2(v[i].x * inv, v[i].y * inv);
        w.y = packh2(v[i].z * inv, v[i].w * inv);
        *reinterpret_cast<uint2*>(q + (tid + 256 * i) * 2) = w;
    }
}

// ------------------------------ launcher -----------------------------------
extern "C" void kernel_launch(void* const* d_in, const int* in_sizes, int n_in,
                              void* d_out, int out_size)
{
    const float* za = (const float*)d_in[0];
    const float* zb = (const float*)d_in[1];
    const float* W1 = (const float*)d_in[2];
    const float* b1 = (const float*)d_in[3];
    const float* W2 = (const float*)d_in[4];
    const float* b2 = (const float*)d_in[5];
    const float* Wq = (const float*)d_in[6];
    const float* bq = (const float*)d_in[7];
    const float* Wk = (const float*)d_in[8];
    const float* bk = (const float*)d_in[9];
    const float* Wv = (const float*)d_in[10];
    const float* bv = (const float*)d_in[11];
    float* out = (float*)d_out;

    unsigned *Zh, *Zl, *Hh, *Hl, *Ph, *Pl, *Qh, *Ql, *Kh, *Kl, *Vh, *VT;
    unsigned *W1h, *W1l, *W2h, *W2l, *Wqh, *Wql, *Wkh, *Wkl, *Wvh, *Wvl, *Sh;
    float *S;
    cudaGetSymbolAddress((void**)&Zh,  g_Zh);  cudaGetSymbolAddress((void**)&Zl,  g_Zl);
    cudaGetSymbolAddress((void**)&Hh,  g_Hh);  cudaGetSymbolAddress((void**)&Hl,  g_Hl);
    cudaGetSymbolAddress((void**)&Ph,  g_Ph);  cudaGetSymbolAddress((void**)&Pl,  g_Pl);
    cudaGetSymbolAddress((void**)&Qh,  g_Qh);  cudaGetSymbolAddress((void**)&Ql,  g_Ql);
    cudaGetSymbolAddress((void**)&Kh,  g_Kh);  cudaGetSymbolAddress((void**)&Kl,  g_Kl);
    cudaGetSymbolAddress((void**)&Vh,  g_Vh);  cudaGetSymbolAddress((void**)&VT,  g_VT);
    cudaGetSymbolAddress((void**)&W1h, g_W1h); cudaGetSymbolAddress((void**)&W1l, g_W1l);
    cudaGetSymbolAddress((void**)&W2h, g_W2h); cudaGetSymbolAddress((void**)&W2l, g_W2l);
    cudaGetSymbolAddress((void**)&Wqh, g_Wqh); cudaGetSymbolAddress((void**)&Wql, g_Wql);
    cudaGetSymbolAddress((void**)&Wkh, g_Wkh); cudaGetSymbolAddress((void**)&Wkl, g_Wkl);
    cudaGetSymbolAddress((void**)&Wvh, g_Wvh); cudaGetSymbolAddress((void**)&Wvl, g_Wvl);
    cudaGetSymbolAddress((void**)&S,   g_S);   cudaGetSymbolAddress((void**)&Sh,  g_Sh);

    const int smem_split  = 2 * 4 * SLABB;   // 132096 B (double-buffered)
    const int smem_single = 2 * 2 * SLABB;   // 66048 B
    cudaFuncSetAttribute(gemm_mm<0,0,0>, cudaFuncAttributeMaxDynamicSharedMemorySize, smem_split);
    cudaFuncSetAttribute(gemm_mm<1,0,1>, cudaFuncAttributeMaxDynamicSharedMemorySize, smem_split);
    cudaFuncSetAttribute(gemm_mm<2,0,1>, cudaFuncAttributeMaxDynamicSharedMemorySize, smem_split);
    cudaFuncSetAttribute(gemm_mm<1,0,2>, cudaFuncAttributeMaxDynamicSharedMemorySize, smem_split);
    cudaFuncSetAttribute(gemm_mm<0,1,0>, cudaFuncAttributeMaxDynamicSharedMemorySize, smem_single);

    const dim3 blk(256);
    const dim3 tblk(32, 8);
    const float inv_scale = 1.0f / 16.0f;   // 1/sqrt(OUT/2)
    const size_t HALFW = (size_t)8192 * 256;
    const size_t HVTW  = (size_t)512 * 4096;

    // launches 1-5 (prep), so launch #6 (ncu -s 5 -c 1) is the L1 GEMM
    split_in<<<16384, blk>>>(za, zb, Zh, Zl);
    transpose_split<<<dim3(32, 32), tblk>>>(W1, W1h, W1l, 1024, 1024);
    transpose_split<<<dim3(16, 32), tblk>>>(W2, W2h, W2l, 1024, 512);
    transpose_split<<<dim3(16, 16), tblk>>>(Wq, Wqh, Wql, 512, 512);
    transpose_split<<<dim3(16, 16), tblk>>>(Wk, Wkh, Wkl, 512, 512);

    // #6: proj layer 1: H = ELU(Z @ W1^T + b1)   [16384 x 1024]
    gemm_mm<2,0,1><<<dim3(8, 128), blk, smem_split>>>(
        Zh, Zl, W1h, W1l, b1, nullptr, Hh, Hl, 16384, 1024, 1024, 512, 0, 1.f);

    transpose_split<<<dim3(16, 16), tblk>>>(Wv, Wvh, Wvl, 512, 512);

    // proj layer 2: P = H @ W2^T + b2            [16384 x 512]
    gemm_mm<1,0,1><<<dim3(4, 128), blk, smem_split>>>(
        Hh, Hl, W2h, W2l, b2, nullptr, Ph, Pl, 16384, 512, 1024, 256, 0, 1.f);
    // QKV
    gemm_mm<1,0,1><<<dim3(4, 128), blk, smem_split>>>(
        Ph, Pl, Wqh, Wql, bq, nullptr, Qh, Ql, 16384, 512, 512, 256, 0, 1.f);
    gemm_mm<1,0,1><<<dim3(4, 128), blk, smem_split>>>(
        Ph, Pl, Wkh, Wkl, bk, nullptr, Kh, Kl, 16384, 512, 512, 256, 0, 1.f);
    gemm_mm<1,0,2><<<dim3(4, 128), blk, smem_split>>>(
        Ph, Pl, Wvh, Wvl, bv, nullptr, Vh, nullptr, 16384, 512, 512, 256, 0, 1.f);
    // V^T per half (fp16)
    transpose_h<<<dim3(16, 256), tblk>>>(Vh,         VT,        8192, 512);
    transpose_h<<<dim3(16, 256), tblk>>>(Vh + HALFW, VT + HVTW, 8192, 512);

    // direction A
    gemm_mm<0,0,0><<<dim3(64, 64), blk, smem_split>>>(
        Qh, Ql, Kh + HALFW, Kl + HALFW, nullptr, S, nullptr, nullptr,
        8192, 8192, 512, 8192, 0, inv_scale);
    softmax_rows<<<8192, blk>>>(S, Sh);
    gemm_mm<0,1,0><<<dim3(4, 64), blk, smem_single>>>(
        Sh, nullptr, VT + HVTW, nullptr, nullptr, out, nullptr, nullptr,
        8192, 512, 8192, 1024, 0, 1.f);

    // direction B
    gemm_mm<0,0,0><<<dim3(64, 64), blk, smem_split>>>(
        Qh + HALFW, Ql + HALFW, Kh, Kl, nullptr, S, nullptr, nullptr,
        8192, 8192, 512, 8192, 0, inv_scale);
    softmax_rows<<<8192, blk>>>(S, Sh);
    gemm_mm<0,1,0><<<dim3(4, 64), blk, smem_single>>>(
        Sh, nullptr, VT, nullptr, nullptr, out, nullptr, nullptr,
        8192, 512, 8192, 1024, 512, 1.f);
}

// round 7
// speedup vs baseline: 1.1709x; 1.1709x over previous
#include <cuda_runtime.h>
#include <cuda_bf16.h>
#include <cuda_fp16.h>
#include <math.h>

// ---------------------------------------------------------------------------
// Contrast on legacy mma.sync m16n8k16 (baseline PTX; harness targets sm_103).
// Operands pre-split in GMEM (bf16 hi/lo or fp16). GEMM mainloop: 3-stage
// cp.async ring (BK=32, 99KB smem, 2 CTAs/SM) + ldmatrix fragment loads,
// one __syncthreads per ktile.
// ---------------------------------------------------------------------------

namespace {
constexpr int KBLK  = 1032;            // u32 words per k16-block: 128*8 + 8 pad
constexpr unsigned SLB = 2u * KBLK * 4u;   // bytes per matrix-half per BK=32 tile
}

// ------------------------------ scratch (u32 words) -------------------------
__device__ unsigned g_Zh [8388608], g_Zl [8388608];   // split(za|zb) 16384x1024
__device__ unsigned g_Hh [8388608], g_Hl [8388608];   // H split     16384x1024
__device__ unsigned g_Ph [4194304], g_Pl [4194304];   // P split     16384x512
__device__ unsigned g_Qh [4194304], g_Ql [4194304];
__device__ unsigned g_Kh [4194304], g_Kl [4194304];
__device__ unsigned g_Vh [4194304];                   // V fp16      16384x512
__device__ unsigned g_VT [4194304];                   // V^T fp16 per half [512,8192]
__device__ unsigned g_W1h[524288],  g_W1l[524288];
__device__ unsigned g_W2h[262144],  g_W2l[262144];
__device__ unsigned g_Wqh[131072],  g_Wql[131072];
__device__ unsigned g_Wkh[131072],  g_Wkl[131072];
__device__ unsigned g_Wvh[131072],  g_Wvl[131072];
__device__ float    g_S  [67108864];                  // fp32 scores
__device__ unsigned g_Sh [33554432];                  // fp16 softmaxed scores

// ------------------------------ helpers ------------------------------------
__device__ __forceinline__ void mma_bf16(float* c, const unsigned* a,
                                         unsigned b0, unsigned b1) {
    asm volatile(
        "mma.sync.aligned.m16n8k16.row.col.f32.bf16.bf16.f32 "
        "{%0,%1,%2,%3}, {%4,%5,%6,%7}, {%8,%9}, {%0,%1,%2,%3};"
        : "+f"(c[0]), "+f"(c[1]), "+f"(c[2]), "+f"(c[3])
        : "r"(a[0]), "r"(a[1]), "r"(a[2]), "r"(a[3]), "r"(b0), "r"(b1));
}

__device__ __forceinline__ void mma_fp16(float* c, const unsigned* a,
                                         unsigned b0, unsigned b1) {
    asm volatile(
        "mma.sync.aligned.m16n8k16.row.col.f32.f16.f16.f32 "
        "{%0,%1,%2,%3}, {%4,%5,%6,%7}, {%8,%9}, {%0,%1,%2,%3};"
        : "+f"(c[0]), "+f"(c[1]), "+f"(c[2]), "+f"(c[3])
        : "r"(a[0]), "r"(a[1]), "r"(a[2]), "r"(a[3]), "r"(b0), "r"(b1));
}

__device__ __forceinline__ void ldsm_x4(unsigned* r, unsigned addr) {
    asm volatile("ldmatrix.sync.aligned.m8n8.x4.shared.b16 {%0,%1,%2,%3}, [%4];"
        : "=r"(r[0]), "=r"(r[1]), "=r"(r[2]), "=r"(r[3]) : "r"(addr));
}

__device__ __forceinline__ void cp16(unsigned dst, const void* src) {
    asm volatile("cp.async.cg.shared.global [%0], [%1], 16;" :: "r"(dst), "l"(src));
}

__device__ __forceinline__ unsigned smem_u32(const void* p) {
    unsigned a;
    asm("{ .reg .u64 t; cvta.to.shared.u64 t, %1; cvt.u32.u64 %0, t; }"
        : "=r"(a) : "l"(p));
    return a;
}

__device__ __forceinline__ void split2(float x, float y, unsigned& hi, unsigned& lo) {
    __nv_bfloat16 hx = __float2bfloat16(x);
    __nv_bfloat16 hy = __float2bfloat16(y);
    __nv_bfloat16 lx = __float2bfloat16(x - __bfloat162float(hx));
    __nv_bfloat16 ly = __float2bfloat16(y - __bfloat162float(hy));
    hi = ((unsigned)__bfloat16_as_ushort(hy) << 16) | (unsigned)__bfloat16_as_ushort(hx);
    lo = ((unsigned)__bfloat16_as_ushort(ly) << 16) | (unsigned)__bfloat16_as_ushort(lx);
}

__device__ __forceinline__ unsigned packh2(float x, float y) {
    __half2 h = __floats2half2_rn(x, y);
    return *reinterpret_cast<unsigned*>(&h);
}

// --------------------------- input split -----------------------------------
__global__ void __launch_bounds__(256, 8)
split_in(const float* __restrict__ za, const float* __restrict__ zb,
         unsigned* __restrict__ Zh, unsigned* __restrict__ Zl)
{
    const size_t t = (size_t)blockIdx.x * 256 + threadIdx.x;
    const size_t f = t * 4;
    const float4 v = (f < (size_t)8388608)
        ? *reinterpret_cast<const float4*>(za + f)
        : *reinterpret_cast<const float4*>(zb + (f - 8388608));
    uint2 h, l;
    split2(v.x, v.y, h.x, l.x);
    split2(v.z, v.w, h.y, l.y);
    *reinterpret_cast<uint2*>(Zh + t * 2) = h;
    *reinterpret_cast<uint2*>(Zl + t * 2) = l;
}

// --------------------------- weight transpose + split -----------------------
__global__ void __launch_bounds__(256, 4)
transpose_split(const float* __restrict__ src, unsigned* __restrict__ dh,
                unsigned* __restrict__ dl, int R, int C)
{
    __shared__ float t[32][33];
    const int bx = blockIdx.x * 32;
    const int by = blockIdx.y * 32;
    const int x  = bx + threadIdx.x;
    #pragma unroll
    for (int i = threadIdx.y; i < 32; i += 8)
        t[i][threadIdx.x] = src[(size_t)(by + i) * C + x];
    __syncthreads();
    const int xo = by + threadIdx.x;
    unsigned short* ph = reinterpret_cast<unsigned short*>(dh);
    unsigned short* pl = reinterpret_cast<unsigned short*>(dl);
    #pragma unroll
    for (int i = threadIdx.y; i < 32; i += 8) {
        const float v = t[threadIdx.x][i];
        const __nv_bfloat16 h = __float2bfloat16(v);
        const __nv_bfloat16 l = __float2bfloat16(v - __bfloat162float(h));
        ph[(size_t)(bx + i) * R + xo] = __bfloat16_as_ushort(h);
        pl[(size_t)(bx + i) * R + xo] = __bfloat16_as_ushort(l);
    }
}

// --------------------------- fp16 transpose --------------------------------
__global__ void __launch_bounds__(256, 4)
transpose_h(const unsigned* __restrict__ srcw, unsigned* __restrict__ dstw, int R, int C)
{
    __shared__ unsigned short t[32][34];
    const unsigned short* src = reinterpret_cast<const unsigned short*>(srcw);
    unsigned short* dst = reinterpret_cast<unsigned short*>(dstw);
    const int bx = blockIdx.x * 32;
    const int by = blockIdx.y * 32;
    const int x  = bx + threadIdx.x;
    #pragma unroll
    for (int i = threadIdx.y; i < 32; i += 8)
        t[i][threadIdx.x] = src[(size_t)(by + i) * C + x];
    __syncthreads();
    const int xo = by + threadIdx.x;
    #pragma unroll
    for (int i = threadIdx.y; i < 32; i += 8)
        dst[(size_t)(bx + i) * R + xo] = t[threadIdx.x][i];
}

// ------------------------------ GEMM ---------------------------------------
// C = epi(A[M,K] @ B[N,K]^T), operands pre-packed 16-bit (u32 pitch K/2).
// PREC 0: bf16 split-3.  PREC 1: fp16 single.
// EPI 0: v*=scale ; EPI 1: v+=bias ; EPI 2: elu(v+bias)
// OFMT 0: f32 Cf ; OFMT 1: split bf16 Ch/Cl ; OFMT 2: fp16 Ch
template <int EPI, int PREC, int OFMT>
__global__ void __launch_bounds__(256, 2)
gemm_mm(const unsigned* __restrict__ Ah, const unsigned* __restrict__ Al,
        const unsigned* __restrict__ Bh, const unsigned* __restrict__ Bl,
        const float* __restrict__ bias,
        float* __restrict__ Cf, unsigned* __restrict__ Ch, unsigned* __restrict__ Cl,
        int M, int N, int K, int ldc, int coff, float scale)
{
    extern __shared__ unsigned sm[];
    const unsigned tilesb = smem_u32(sm);
    constexpr unsigned YOFFB = (PREC == 0) ? 2u * SLB : SLB;    // B-hi offset
    constexpr unsigned BUFB  = (PREC == 0) ? 4u * SLB : 2u * SLB;

    const int tid  = threadIdx.x;
    const int bm   = blockIdx.y * 128;
    const int bn   = blockIdx.x * 128;
    const int warp = tid >> 5;
    const int lane = tid & 31;
    const int wm   = (warp >> 2) * 64;
    const int wn   = (warp & 3) * 32;
    const int g    = lane >> 2;
    const int t2   = (lane & 3) * 2;

    // ldmatrix relative addresses (buffer 0, k-block 0)
    const int mi = lane >> 3;
    const int rl = (lane & 7) + ((mi & 1) << 3);
    const int kg = mi >> 1;
    unsigned relA[4], relB[2];
    #pragma unroll
    for (int mf = 0; mf < 4; mf++) {
        const int row = wm + mf * 16 + rl;
        const int w   = (kg << 2) ^ (((row >> 2) & 1) << 2);
        relA[mf] = tilesb + 4u * (unsigned)(row * 8 + w);
    }
    #pragma unroll
    for (int p = 0; p < 2; p++) {
        const int nf  = 2 * p + (mi >> 1);
        const int row = wn + nf * 8 + (lane & 7);
        const int w   = ((mi & 1) << 2) ^ (((row >> 2) & 1) << 2);
        relB[p] = tilesb + YOFFB + 4u * (unsigned)(row * 8 + w);
    }

    // staging mapping: 4 threads per 128-row, 2 row-passes
    const int srow  = tid >> 2;               // 0..63 (+64)
    const int scol8 = (tid & 3) * 8;          // 0,8,16,24
    const int sblk  = scol8 >> 4;             // k16-block 0..1
    const int sw0   = ((scol8 & 15) >> 1) ^ (((srow >> 2) & 1) * 4);
    const unsigned sidx0 = (unsigned)(sblk * KBLK + srow * 8 + sw0);
    const int kw = K >> 1;

    float acc[4][4][4];
    #pragma unroll
    for (int i = 0; i < 4; i++)
        #pragma unroll
        for (int j = 0; j < 4; j++)
            #pragma unroll
            for (int e = 0; e < 4; e++) acc[i][j][e] = 0.f;

    auto stage = [&](int kt, unsigned bufb) {
        const int w0 = kt * 16 + (scol8 >> 1);
        const unsigned d0 = tilesb + bufb + 4u * sidx0;
        #pragma unroll
        for (int i = 0; i < 2; i++) {
            const size_t ro = (size_t)(bm + srow + 64 * i) * kw + w0;
            cp16(d0 + 2048u * i, Ah + ro);
            if (PREC == 0) cp16(d0 + 2048u * i + SLB, Al + ro);
        }
        #pragma unroll
        for (int i = 0; i < 2; i++) {
            const size_t ro = (size_t)(bn + srow + 64 * i) * kw + w0;
            cp16(d0 + 2048u * i + YOFFB, Bh + ro);
            if (PREC == 0) cp16(d0 + 2048u * i + YOFFB + SLB, Bl + ro);
        }
        asm volatile("cp.async.commit_group;" ::: "memory");
    };

    auto compute = [&](unsigned bufb) {
        #pragma unroll
        for (int blk = 0; blk < 2; blk++) {
            const unsigned off = bufb + (unsigned)(blk * (KBLK * 4));
            unsigned a[4][4], b[2][4];
            #pragma unroll
            for (int mf = 0; mf < 4; mf++) ldsm_x4(a[mf], relA[mf] + off);
            #pragma unroll
            for (int p = 0; p < 2; p++)    ldsm_x4(b[p],  relB[p] + off);
            #pragma unroll
            for (int mf = 0; mf < 4; mf++)
                #pragma unroll
                for (int nf = 0; nf < 4; nf++) {
                    const unsigned b0 = b[nf >> 1][(nf & 1) * 2];
                    const unsigned b1 = b[nf >> 1][(nf & 1) * 2 + 1];
                    if (PREC == 0) mma_bf16(acc[mf][nf], a[mf], b0, b1);
                    else           mma_fp16(acc[mf][nf], a[mf], b0, b1);
                }
            if (PREC == 0) {
                unsigned bl2[2][4];
                #pragma unroll
                for (int p = 0; p < 2; p++) ldsm_x4(bl2[p], relB[p] + off + SLB);
                #pragma unroll
                for (int mf = 0; mf < 4; mf++)
                    #pragma unroll
                    for (int nf = 0; nf < 4; nf++)
                        mma_bf16(acc[mf][nf], a[mf],
                                 bl2[nf >> 1][(nf & 1) * 2], bl2[nf >> 1][(nf & 1) * 2 + 1]);
                unsigned al2[4][4];
                #pragma unroll
                for (int mf = 0; mf < 4; mf++) ldsm_x4(al2[mf], relA[mf] + off + SLB);
                #pragma unroll
                for (int mf = 0; mf < 4; mf++)
                    #pragma unroll
                    for (int nf = 0; nf < 4; nf++)
                        mma_bf16(acc[mf][nf], al2[mf],
                                 b[nf >> 1][(nf & 1) * 2], b[nf >> 1][(nf & 1) * 2 + 1]);
            }
        }
    };

    const int ktiles = K / 32;
    stage(0, 0u);
    stage(1, BUFB);
    for (int kt = 0; kt < ktiles; kt++) {
        if (kt + 1 < ktiles) asm volatile("cp.async.wait_group 1;" ::: "memory");
        else                 asm volatile("cp.async.wait_group 0;" ::: "memory");
        __syncthreads();
        if (kt + 2 < ktiles) stage(kt + 2, (unsigned)((kt + 2) % 3) * BUFB);
        compute((unsigned)(kt % 3) * BUFB);
    }

    // epilogue
    #pragma unroll
    for (int mf = 0; mf < 4; mf++) {
        #pragma unroll
        for (int nf = 0; nf < 4; nf++) {
            const int row = bm + wm + mf * 16 + g;
            const int col = bn + wn + nf * 8 + t2;
            float v0 = acc[mf][nf][0], v1 = acc[mf][nf][1];
            float v2 = acc[mf][nf][2], v3 = acc[mf][nf][3];
            if (EPI == 0) {
                v0 *= scale; v1 *= scale; v2 *= scale; v3 *= scale;
            } else {
                const float bb0 = bias[col], bb1 = bias[col + 1];
                v0 += bb0; v1 += bb1; v2 += bb0; v3 += bb1;
                if (EPI == 2) {
                    v0 = v0 > 0.f ? v0 : expm1f(v0);
                    v1 = v1 > 0.f ? v1 : expm1f(v1);
                    v2 = v2 > 0.f ? v2 : expm1f(v2);
                    v3 = v3 > 0.f ? v3 : expm1f(v3);
                }
            }
            if (OFMT == 0) {
                *reinterpret_cast<float2*>(Cf + (size_t)row * ldc + coff + col)       = make_float2(v0, v1);
                *reinterpret_cast<float2*>(Cf + (size_t)(row + 8) * ldc + coff + col) = make_float2(v2, v3);
            } else if (OFMT == 1) {
                unsigned h, l;
                split2(v0, v1, h, l);
                Ch[(size_t)row * ldc + (col >> 1)] = h;
                Cl[(size_t)row * ldc + (col >> 1)] = l;
                split2(v2, v3, h, l);
                Ch[(size_t)(row + 8) * ldc + (col >> 1)] = h;
                Cl[(size_t)(row + 8) * ldc + (col >> 1)] = l;
            } else {
                Ch[(size_t)row * ldc + (col >> 1)]       = packh2(v0, v1);
                Ch[(size_t)(row + 8) * ldc + (col >> 1)] = packh2(v2, v3);
            }
        }
    }
}

// ------------------------------ softmax ------------------------------------
__global__ void __launch_bounds__(256, 1)
softmax_rows(const float* __restrict__ S, unsigned* __restrict__ Sh)
{
    const int row = blockIdx.x;
    const float4* p = reinterpret_cast<const float4*>(S + (size_t)row * 8192);
    const int tid = threadIdx.x;

    float4 v[8];
    #pragma unroll
    for (int i = 0; i < 8; i++) v[i] = p[tid + 256 * i];

    float m = -3.402823e38f;
    #pragma unroll
    for (int i = 0; i < 8; i++)
        m = fmaxf(m, fmaxf(fmaxf(v[i].x, v[i].y), fmaxf(v[i].z, v[i].w)));

    __shared__ float red[8];
    #pragma unroll
    for (int o = 16; o; o >>= 1) m = fmaxf(m, __shfl_xor_sync(0xffffffffu, m, o));
    if ((tid & 31) == 0) red[tid >> 5] = m;
    __syncthreads();
    float mm = red[0];
    #pragma unroll
    for (int i = 1; i < 8; i++) mm = fmaxf(mm, red[i]);

    float s = 0.f;
    #pragma unroll
    for (int i = 0; i < 8; i++) {
        v[i].x = __expf(v[i].x - mm); s += v[i].x;
        v[i].y = __expf(v[i].y - mm); s += v[i].y;
        v[i].z = __expf(v[i].z - mm); s += v[i].z;
        v[i].w = __expf(v[i].w - mm); s += v[i].w;
    }
    #pragma unroll
    for (int o = 16; o; o >>= 1) s += __shfl_xor_sync(0xffffffffu, s, o);
    __syncthreads();
    if ((tid & 31) == 0) red[tid >> 5] = s;
    __syncthreads();
    float st = 0.f;
    #pragma unroll
    for (int i = 0; i < 8; i++) st += red[i];
    const float inv = 1.0f / st;

    unsigned* q = Sh + (size_t)row * 4096;
    #pragma unroll
    for (int i = 0; i < 8; i++) {
        uint2 w;
        w.x = packh2(v[i].x * inv, v[i].y * inv);
        w.y = packh2(v[i].z * inv, v[i].w * inv);
        *reinterpret_cast<uint2*>(q + (tid + 256 * i) * 2) = w;
    }
}

// ------------------------------ launcher -----------------------------------
extern "C" void kernel_launch(void* const* d_in, const int* in_sizes, int n_in,
                              void* d_out, int out_size)
{
    const float* za = (const float*)d_in[0];
    const float* zb = (const float*)d_in[1];
    const float* W1 = (const float*)d_in[2];
    const float* b1 = (const float*)d_in[3];
    const float* W2 = (const float*)d_in[4];
    const float* b2 = (const float*)d_in[5];
    const float* Wq = (const float*)d_in[6];
    const float* bq = (const float*)d_in[7];
    const float* Wk = (const float*)d_in[8];
    const float* bk = (const float*)d_in[9];
    const float* Wv = (const float*)d_in[10];
    const float* bv = (const float*)d_in[11];
    float* out = (float*)d_out;

    unsigned *Zh, *Zl, *Hh, *Hl, *Ph, *Pl, *Qh, *Ql, *Kh, *Kl, *Vh, *VT;
    unsigned *W1h, *W1l, *W2h, *W2l, *Wqh, *Wql, *Wkh, *Wkl, *Wvh, *Wvl, *Sh;
    float *S;
    cudaGetSymbolAddress((void**)&Zh,  g_Zh);  cudaGetSymbolAddress((void**)&Zl,  g_Zl);
    cudaGetSymbolAddress((void**)&Hh,  g_Hh);  cudaGetSymbolAddress((void**)&Hl,  g_Hl);
    cudaGetSymbolAddress((void**)&Ph,  g_Ph);  cudaGetSymbolAddress((void**)&Pl,  g_Pl);
    cudaGetSymbolAddress((void**)&Qh,  g_Qh);  cudaGetSymbolAddress((void**)&Ql,  g_Ql);
    cudaGetSymbolAddress((void**)&Kh,  g_Kh);  cudaGetSymbolAddress((void**)&Kl,  g_Kl);
    cudaGetSymbolAddress((void**)&Vh,  g_Vh);  cudaGetSymbolAddress((void**)&VT,  g_VT);
    cudaGetSymbolAddress((void**)&W1h, g_W1h); cudaGetSymbolAddress((void**)&W1l, g_W1l);
    cudaGetSymbolAddress((void**)&W2h, g_W2h); cudaGetSymbolAddress((void**)&W2l, g_W2l);
    cudaGetSymbolAddress((void**)&Wqh, g_Wqh); cudaGetSymbolAddress((void**)&Wql, g_Wql);
    cudaGetSymbolAddress((void**)&Wkh, g_Wkh); cudaGetSymbolAddress((void**)&Wkl, g_Wkl);
    cudaGetSymbolAddress((void**)&Wvh, g_Wvh); cudaGetSymbolAddress((void**)&Wvl, g_Wvl);
    cudaGetSymbolAddress((void**)&S,   g_S);   cudaGetSymbolAddress((void**)&Sh,  g_Sh);

    const int smem_split  = 3 * 4 * (int)SLB;   // 99072 B (3-stage ring)
    const int smem_single = 3 * 2 * (int)SLB;   // 49536 B
    cudaFuncSetAttribute(gemm_mm<0,0,0>, cudaFuncAttributeMaxDynamicSharedMemorySize, smem_split);
    cudaFuncSetAttribute(gemm_mm<1,0,1>, cudaFuncAttributeMaxDynamicSharedMemorySize, smem_split);
    cudaFuncSetAttribute(gemm_mm<2,0,1>, cudaFuncAttributeMaxDynamicSharedMemorySize, smem_split);
    cudaFuncSetAttribute(gemm_mm<1,0,2>, cudaFuncAttributeMaxDynamicSharedMemorySize, smem_split);
    cudaFuncSetAttribute(gemm_mm<0,1,0>, cudaFuncAttributeMaxDynamicSharedMemorySize, smem_single);

    const dim3 blk(256);
    const dim3 tblk(32, 8);
    const float inv_scale = 1.0f / 16.0f;   // 1/sqrt(OUT/2)
    const size_t HALFW = (size_t)8192 * 256;
    const size_t HVTW  = (size_t)512 * 4096;

    // prep (launches 1-4)
    split_in<<<16384, blk>>>(za, zb, Zh, Zl);
    transpose_split<<<dim3(32, 32), tblk>>>(W1, W1h, W1l, 1024, 1024);
    transpose_split<<<dim3(16, 32), tblk>>>(W2, W2h, W2l, 1024, 512);
    transpose_split<<<dim3(16, 16), tblk>>>(Wq, Wqh, Wql, 512, 512);

    // #5: proj layer 1: H = ELU(Z @ W1^T + b1)   [16384 x 1024]
    gemm_mm<2,0,1><<<dim3(8, 128), blk, smem_split>>>(
        Zh, Zl, W1h, W1l, b1, nullptr, Hh, Hl, 16384, 1024, 1024, 512, 0, 1.f);
    // #6: proj layer 2: P = H @ W2^T + b2        [16384 x 512]
    gemm_mm<1,0,1><<<dim3(4, 128), blk, smem_split>>>(
        Hh, Hl, W2h, W2l, b2, nullptr, Ph, Pl, 16384, 512, 1024, 256, 0, 1.f);

    transpose_split<<<dim3(16, 16), tblk>>>(Wk, Wkh, Wkl, 512, 512);
    transpose_split<<<dim3(16, 16), tblk>>>(Wv, Wvh, Wvl, 512, 512);

    // QKV
    gemm_mm<1,0,1><<<dim3(4, 128), blk, smem_split>>>(
        Ph, Pl, Wqh, Wql, bq, nullptr, Qh, Ql, 16384, 512, 512, 256, 0, 1.f);
    gemm_mm<1,0,1><<<dim3(4, 128), blk, smem_split>>>(
        Ph, Pl, Wkh, Wkl, bk, nullptr, Kh, Kl, 16384, 512, 512, 256, 0, 1.f);
    gemm_mm<1,0,2><<<dim3(4, 128), blk, smem_split>>>(
        Ph, Pl, Wvh, Wvl, bv, nullptr, Vh, nullptr, 16384, 512, 512, 256, 0, 1.f);
    // V^T per half (fp16)
    transpose_h<<<dim3(16, 256), tblk>>>(Vh,         VT,        8192, 512);
    transpose_h<<<dim3(16, 256), tblk>>>(Vh + HALFW, VT + HVTW, 8192, 512);

    // direction A
    gemm_mm<0,0,0><<<dim3(64, 64), blk, smem_split>>>(
        Qh, Ql, Kh + HALFW, Kl + HALFW, nullptr, S, nullptr, nullptr,
        8192, 8192, 512, 8192, 0, inv_scale);
    softmax_rows<<<8192, blk>>>(S, Sh);
    gemm_mm<0,1,0><<<dim3(4, 64), blk, smem_single>>>(
        Sh, nullptr, VT + HVTW, nullptr, nullptr, out, nullptr, nullptr,
        8192, 512, 8192, 1024, 0, 1.f);

    // direction B
    gemm_mm<0,0,0><<<dim3(64, 64), blk, smem_split>>>(
        Qh + HALFW, Ql + HALFW, Kh, Kl, nullptr, S, nullptr, nullptr,
        8192, 8192, 512, 8192, 0, inv_scale);
    softmax_rows<<<8192, blk>>>(S, Sh);
    gemm_mm<0,1,0><<<dim3(4, 64), blk, smem_single>>>(
        Sh, nullptr, VT, nullptr, nullptr, out, nullptr, nullptr,
        8192, 512, 8192, 1024, 512, 1.f);
}

// round 8
// speedup vs baseline: 1.3310x; 1.1367x over previous
#include <cuda_runtime.h>
#include <cuda_bf16.h>
#include <cuda_fp16.h>
#include <math.h>

// ---------------------------------------------------------------------------
// Contrast on legacy mma.sync m16n8k16 (baseline PTX; harness targets sm_103).
// proj/QKV: bf16 split-3 (near-exact). Scores: fp16 split-2 (Q fp16 single,
// K fp16 hi/lo). AV: fp16 single. 3-stage cp.async ring, ldmatrix fragments.
// ---------------------------------------------------------------------------

namespace {
constexpr int KBLK  = 1032;            // u32 words per k16-block: 128*8 + 8 pad
constexpr unsigned SLB = 2u * KBLK * 4u;   // bytes per matrix-half per BK=32 tile
}

// ------------------------------ scratch (u32 words) -------------------------
__device__ unsigned g_Zh [8388608], g_Zl [8388608];   // split(za|zb) 16384x1024
__device__ unsigned g_Hh [8388608], g_Hl [8388608];   // H split     16384x1024
__device__ unsigned g_Ph [4194304], g_Pl [4194304];   // P split     16384x512
__device__ unsigned g_Qh [4194304];                   // Q fp16      16384x512
__device__ unsigned g_Kh [4194304], g_Kl [4194304];   // K fp16 hi/lo
__device__ unsigned g_Vh [4194304];                   // V fp16      16384x512
__device__ unsigned g_VT [4194304];                   // V^T fp16 per half [512,8192]
__device__ unsigned g_W1h[524288],  g_W1l[524288];
__device__ unsigned g_W2h[262144],  g_W2l[262144];
__device__ unsigned g_Wqh[131072],  g_Wql[131072];
__device__ unsigned g_Wkh[131072],  g_Wkl[131072];
__device__ unsigned g_Wvh[131072],  g_Wvl[131072];
__device__ float    g_S  [67108864];                  // fp32 scores
__device__ unsigned g_Sh [33554432];                  // fp16 softmaxed scores

// ------------------------------ helpers ------------------------------------
__device__ __forceinline__ void mma_bf16(float* c, const unsigned* a,
                                         unsigned b0, unsigned b1) {
    asm volatile(
        "mma.sync.aligned.m16n8k16.row.col.f32.bf16.bf16.f32 "
        "{%0,%1,%2,%3}, {%4,%5,%6,%7}, {%8,%9}, {%0,%1,%2,%3};"
        : "+f"(c[0]), "+f"(c[1]), "+f"(c[2]), "+f"(c[3])
        : "r"(a[0]), "r"(a[1]), "r"(a[2]), "r"(a[3]), "r"(b0), "r"(b1));
}

__device__ __forceinline__ void mma_fp16(float* c, const unsigned* a,
                                         unsigned b0, unsigned b1) {
    asm volatile(
        "mma.sync.aligned.m16n8k16.row.col.f32.f16.f16.f32 "
        "{%0,%1,%2,%3}, {%4,%5,%6,%7}, {%8,%9}, {%0,%1,%2,%3};"
        : "+f"(c[0]), "+f"(c[1]), "+f"(c[2]), "+f"(c[3])
        : "r"(a[0]), "r"(a[1]), "r"(a[2]), "r"(a[3]), "r"(b0), "r"(b1));
}

__device__ __forceinline__ void ldsm_x4(unsigned* r, unsigned addr) {
    asm volatile("ldmatrix.sync.aligned.m8n8.x4.shared.b16 {%0,%1,%2,%3}, [%4];"
        : "=r"(r[0]), "=r"(r[1]), "=r"(r[2]), "=r"(r[3]) : "r"(addr));
}

__device__ __forceinline__ void cp16(unsigned dst, const void* src) {
    asm volatile("cp.async.cg.shared.global [%0], [%1], 16;" :: "r"(dst), "l"(src));
}

__device__ __forceinline__ unsigned smem_u32(const void* p) {
    unsigned a;
    asm("{ .reg .u64 t; cvta.to.shared.u64 t, %1; cvt.u32.u64 %0, t; }"
        : "=r"(a) : "l"(p));
    return a;
}

__device__ __forceinline__ void split2(float x, float y, unsigned& hi, unsigned& lo) {
    __nv_bfloat16 hx = __float2bfloat16(x);
    __nv_bfloat16 hy = __float2bfloat16(y);
    __nv_bfloat16 lx = __float2bfloat16(x - __bfloat162float(hx));
    __nv_bfloat16 ly = __float2bfloat16(y - __bfloat162float(hy));
    hi = ((unsigned)__bfloat16_as_ushort(hy) << 16) | (unsigned)__bfloat16_as_ushort(hx);
    lo = ((unsigned)__bfloat16_as_ushort(ly) << 16) | (unsigned)__bfloat16_as_ushort(lx);
}

__device__ __forceinline__ unsigned packh2(float x, float y) {
    __half2 h = __floats2half2_rn(x, y);
    return *reinterpret_cast<unsigned*>(&h);
}

// fp16 hi/lo split of a float pair
__device__ __forceinline__ void splith2(float x, float y, unsigned& hi, unsigned& lo) {
    __half2 h = __floats2half2_rn(x, y);
    float2 f = __half22float2(h);
    __half2 l = __floats2half2_rn(x - f.x, y - f.y);
    hi = *reinterpret_cast<unsigned*>(&h);
    lo = *reinterpret_cast<unsigned*>(&l);
}

// --------------------------- input split -----------------------------------
__global__ void __launch_bounds__(256, 8)
split_in(const float* __restrict__ za, const float* __restrict__ zb,
         unsigned* __restrict__ Zh, unsigned* __restrict__ Zl)
{
    const size_t t = (size_t)blockIdx.x * 256 + threadIdx.x;
    const size_t f = t * 4;
    const float4 v = (f < (size_t)8388608)
        ? *reinterpret_cast<const float4*>(za + f)
        : *reinterpret_cast<const float4*>(zb + (f - 8388608));
    uint2 h, l;
    split2(v.x, v.y, h.x, l.x);
    split2(v.z, v.w, h.y, l.y);
    *reinterpret_cast<uint2*>(Zh + t * 2) = h;
    *reinterpret_cast<uint2*>(Zl + t * 2) = l;
}

// --------------------------- weight transpose + split -----------------------
__global__ void __launch_bounds__(256, 4)
transpose_split(const float* __restrict__ src, unsigned* __restrict__ dh,
                unsigned* __restrict__ dl, int R, int C)
{
    __shared__ float t[32][33];
    const int bx = blockIdx.x * 32;
    const int by = blockIdx.y * 32;
    const int x  = bx + threadIdx.x;
    #pragma unroll
    for (int i = threadIdx.y; i < 32; i += 8)
        t[i][threadIdx.x] = src[(size_t)(by + i) * C + x];
    __syncthreads();
    const int xo = by + threadIdx.x;
    unsigned short* ph = reinterpret_cast<unsigned short*>(dh);
    unsigned short* pl = reinterpret_cast<unsigned short*>(dl);
    #pragma unroll
    for (int i = threadIdx.y; i < 32; i += 8) {
        const float v = t[threadIdx.x][i];
        const __nv_bfloat16 h = __float2bfloat16(v);
        const __nv_bfloat16 l = __float2bfloat16(v - __bfloat162float(h));
        ph[(size_t)(bx + i) * R + xo] = __bfloat16_as_ushort(h);
        pl[(size_t)(bx + i) * R + xo] = __bfloat16_as_ushort(l);
    }
}

// --------------------------- fp16 transpose --------------------------------
__global__ void __launch_bounds__(256, 4)
transpose_h(const unsigned* __restrict__ srcw, unsigned* __restrict__ dstw, int R, int C)
{
    __shared__ unsigned short t[32][34];
    const unsigned short* src = reinterpret_cast<const unsigned short*>(srcw);
    unsigned short* dst = reinterpret_cast<unsigned short*>(dstw);
    const int bx = blockIdx.x * 32;
    const int by = blockIdx.y * 32;
    const int x  = bx + threadIdx.x;
    #pragma unroll
    for (int i = threadIdx.y; i < 32; i += 8)
        t[i][threadIdx.x] = src[(size_t)(by + i) * C + x];
    __syncthreads();
    const int xo = by + threadIdx.x;
    #pragma unroll
    for (int i = threadIdx.y; i < 32; i += 8)
        dst[(size_t)(bx + i) * R + xo] = t[threadIdx.x][i];
}

// ------------------------------ GEMM ---------------------------------------
// C = epi(A[M,K] @ B[N,K]^T), operands pre-packed 16-bit (u32 pitch K/2).
// PREC 0: bf16 split-3 (Ah/Al, Bh/Bl).
// PREC 1: fp16 single (Ah, Bh).
// PREC 2: fp16 split-2 (A = Ah single; B = Bh + Bl).
// EPI 0: v*=scale ; EPI 1: v+=bias ; EPI 2: elu(v+bias)
// OFMT 0: f32 Cf ; OFMT 1: split bf16 Ch/Cl ; OFMT 2: fp16 Ch ; OFMT 3: fp16 Ch/Cl
template <int EPI, int PREC, int OFMT>
__global__ void __launch_bounds__(256, 2)
gemm_mm(const unsigned* __restrict__ Ah, const unsigned* __restrict__ Al,
        const unsigned* __restrict__ Bh, const unsigned* __restrict__ Bl,
        const float* __restrict__ bias,
        float* __restrict__ Cf, unsigned* __restrict__ Ch, unsigned* __restrict__ Cl,
        int M, int N, int K, int ldc, int coff, float scale)
{
    extern __shared__ unsigned sm[];
    const unsigned tilesb = smem_u32(sm);
    constexpr unsigned YOFFB = (PREC == 0) ? 2u * SLB : SLB;    // B-hi offset
    constexpr unsigned BUFB  = (PREC == 0) ? 4u * SLB
                             : (PREC == 2) ? 3u * SLB : 2u * SLB;

    const int tid  = threadIdx.x;
    const int bm   = blockIdx.y * 128;
    const int bn   = blockIdx.x * 128;
    const int warp = tid >> 5;
    const int lane = tid & 31;
    const int wm   = (warp >> 2) * 64;
    const int wn   = (warp & 3) * 32;
    const int g    = lane >> 2;
    const int t2   = (lane & 3) * 2;

    // ldmatrix relative addresses (buffer 0, k-block 0)
    const int mi = lane >> 3;
    const int rl = (lane & 7) + ((mi & 1) << 3);
    const int kg = mi >> 1;
    unsigned relA[4], relB[2];
    #pragma unroll
    for (int mf = 0; mf < 4; mf++) {
        const int row = wm + mf * 16 + rl;
        const int w   = (kg << 2) ^ (((row >> 2) & 1) << 2);
        relA[mf] = tilesb + 4u * (unsigned)(row * 8 + w);
    }
    #pragma unroll
    for (int p = 0; p < 2; p++) {
        const int nf  = 2 * p + (mi >> 1);
        const int row = wn + nf * 8 + (lane & 7);
        const int w   = ((mi & 1) << 2) ^ (((row >> 2) & 1) << 2);
        relB[p] = tilesb + YOFFB + 4u * (unsigned)(row * 8 + w);
    }

    // staging mapping: 4 threads per 128-row, 2 row-passes
    const int srow  = tid >> 2;               // 0..63 (+64)
    const int scol8 = (tid & 3) * 8;          // 0,8,16,24
    const int sblk  = scol8 >> 4;             // k16-block 0..1
    const int sw0   = ((scol8 & 15) >> 1) ^ (((srow >> 2) & 1) * 4);
    const unsigned sidx0 = (unsigned)(sblk * KBLK + srow * 8 + sw0);
    const int kw = K >> 1;

    float acc[4][4][4];
    #pragma unroll
    for (int i = 0; i < 4; i++)
        #pragma unroll
        for (int j = 0; j < 4; j++)
            #pragma unroll
            for (int e = 0; e < 4; e++) acc[i][j][e] = 0.f;

    auto stage = [&](int kt, unsigned bufb) {
        const int w0 = kt * 16 + (scol8 >> 1);
        const unsigned d0 = tilesb + bufb + 4u * sidx0;
        #pragma unroll
        for (int i = 0; i < 2; i++) {
            const size_t ro = (size_t)(bm + srow + 64 * i) * kw + w0;
            cp16(d0 + 2048u * i, Ah + ro);
            if (PREC == 0) cp16(d0 + 2048u * i + SLB, Al + ro);
        }
        #pragma unroll
        for (int i = 0; i < 2; i++) {
            const size_t ro = (size_t)(bn + srow + 64 * i) * kw + w0;
            cp16(d0 + 2048u * i + YOFFB, Bh + ro);
            if (PREC == 0 || PREC == 2) cp16(d0 + 2048u * i + YOFFB + SLB, Bl + ro);
        }
        asm volatile("cp.async.commit_group;" ::: "memory");
    };

    auto compute = [&](unsigned bufb) {
        #pragma unroll
        for (int blk = 0; blk < 2; blk++) {
            const unsigned off = bufb + (unsigned)(blk * (KBLK * 4));
            unsigned a[4][4], b[2][4];
            #pragma unroll
            for (int mf = 0; mf < 4; mf++) ldsm_x4(a[mf], relA[mf] + off);
            #pragma unroll
            for (int p = 0; p < 2; p++)    ldsm_x4(b[p],  relB[p] + off);
            #pragma unroll
            for (int mf = 0; mf < 4; mf++)
                #pragma unroll
                for (int nf = 0; nf < 4; nf++) {
                    const unsigned b0 = b[nf >> 1][(nf & 1) * 2];
                    const unsigned b1 = b[nf >> 1][(nf & 1) * 2 + 1];
                    if (PREC == 0) mma_bf16(acc[mf][nf], a[mf], b0, b1);
                    else           mma_fp16(acc[mf][nf], a[mf], b0, b1);
                }
            if (PREC == 0 || PREC == 2) {
                unsigned bl2[2][4];
                #pragma unroll
                for (int p = 0; p < 2; p++) ldsm_x4(bl2[p], relB[p] + off + SLB);
                #pragma unroll
                for (int mf = 0; mf < 4; mf++)
                    #pragma unroll
                    for (int nf = 0; nf < 4; nf++) {
                        const unsigned b0 = bl2[nf >> 1][(nf & 1) * 2];
                        const unsigned b1 = bl2[nf >> 1][(nf & 1) * 2 + 1];
                        if (PREC == 0) mma_bf16(acc[mf][nf], a[mf], b0, b1);
                        else           mma_fp16(acc[mf][nf], a[mf], b0, b1);
                    }
            }
            if (PREC == 0) {
                unsigned al2[4][4];
                #pragma unroll
                for (int mf = 0; mf < 4; mf++) ldsm_x4(al2[mf], relA[mf] + off + SLB);
                #pragma unroll
                for (int mf = 0; mf < 4; mf++)
                    #pragma unroll
                    for (int nf = 0; nf < 4; nf++)
                        mma_bf16(acc[mf][nf], al2[mf],
                                 b[nf >> 1][(nf & 1) * 2], b[nf >> 1][(nf & 1) * 2 + 1]);
            }
        }
    };

    const int ktiles = K / 32;
    stage(0, 0u);
    stage(1, BUFB);
    for (int kt = 0; kt < ktiles; kt++) {
        if (kt + 1 < ktiles) asm volatile("cp.async.wait_group 1;" ::: "memory");
        else                 asm volatile("cp.async.wait_group 0;" ::: "memory");
        __syncthreads();
        if (kt + 2 < ktiles) stage(kt + 2, (unsigned)((kt + 2) % 3) * BUFB);
        compute((unsigned)(kt % 3) * BUFB);
    }

    // epilogue
    #pragma unroll
    for (int mf = 0; mf < 4; mf++) {
        #pragma unroll
        for (int nf = 0; nf < 4; nf++) {
            const int row = bm + wm + mf * 16 + g;
            const int col = bn + wn + nf * 8 + t2;
            float v0 = acc[mf][nf][0], v1 = acc[mf][nf][1];
            float v2 = acc[mf][nf][2], v3 = acc[mf][nf][3];
            if (EPI == 0) {
                v0 *= scale; v1 *= scale; v2 *= scale; v3 *= scale;
            } else {
                const float bb0 = bias[col], bb1 = bias[col + 1];
                v0 += bb0; v1 += bb1; v2 += bb0; v3 += bb1;
                if (EPI == 2) {
                    v0 = v0 > 0.f ? v0 : expm1f(v0);
                    v1 = v1 > 0.f ? v1 : expm1f(v1);
                    v2 = v2 > 0.f ? v2 : expm1f(v2);
                    v3 = v3 > 0.f ? v3 : expm1f(v3);
                }
            }
            if (OFMT == 0) {
                *reinterpret_cast<float2*>(Cf + (size_t)row * ldc + coff + col)       = make_float2(v0, v1);
                *reinterpret_cast<float2*>(Cf + (size_t)(row + 8) * ldc + coff + col) = make_float2(v2, v3);
            } else if (OFMT == 1) {
                unsigned h, l;
                split2(v0, v1, h, l);
                Ch[(size_t)row * ldc + (col >> 1)] = h;
                Cl[(size_t)row * ldc + (col >> 1)] = l;
                split2(v2, v3, h, l);
                Ch[(size_t)(row + 8) * ldc + (col >> 1)] = h;
                Cl[(size_t)(row + 8) * ldc + (col >> 1)] = l;
            } else if (OFMT == 2) {
                Ch[(size_t)row * ldc + (col >> 1)]       = packh2(v0, v1);
                Ch[(size_t)(row + 8) * ldc + (col >> 1)] = packh2(v2, v3);
            } else {
                unsigned h, l;
                splith2(v0, v1, h, l);
                Ch[(size_t)row * ldc + (col >> 1)] = h;
                Cl[(size_t)row * ldc + (col >> 1)] = l;
                splith2(v2, v3, h, l);
                Ch[(size_t)(row + 8) * ldc + (col >> 1)] = h;
                Cl[(size_t)(row + 8) * ldc + (col >> 1)] = l;
            }
        }
    }
}

// ------------------------------ softmax ------------------------------------
__global__ void __launch_bounds__(256, 1)
softmax_rows(const float* __restrict__ S, unsigned* __restrict__ Sh)
{
    const int row = blockIdx.x;
    const float4* p = reinterpret_cast<const float4*>(S + (size_t)row * 8192);
    const int tid = threadIdx.x;

    float4 v[8];
    #pragma unroll
    for (int i = 0; i < 8; i++) v[i] = p[tid + 256 * i];

    float m = -3.402823e38f;
    #pragma unroll
    for (int i = 0; i < 8; i++)
        m = fmaxf(m, fmaxf(fmaxf(v[i].x, v[i].y), fmaxf(v[i].z, v[i].w)));

    __shared__ float red[8];
    #pragma unroll
    for (int o = 16; o; o >>= 1) m = fmaxf(m, __shfl_xor_sync(0xffffffffu, m, o));
    if ((tid & 31) == 0) red[tid >> 5] = m;
    __syncthreads();
    float mm = red[0];
    #pragma unroll
    for (int i = 1; i < 8; i++) mm = fmaxf(mm, red[i]);

    float s = 0.f;
    #pragma unroll
    for (int i = 0; i < 8; i++) {
        v[i].x = __expf(v[i].x - mm); s += v[i].x;
        v[i].y = __expf(v[i].y - mm); s += v[i].y;
        v[i].z = __expf(v[i].z - mm); s += v[i].z;
        v[i].w = __expf(v[i].w - mm); s += v[i].w;
    }
    #pragma unroll
    for (int o = 16; o; o >>= 1) s += __shfl_xor_sync(0xffffffffu, s, o);
    __syncthreads();
    if ((tid & 31) == 0) red[tid >> 5] = s;
    __syncthreads();
    float st = 0.f;
    #pragma unroll
    for (int i = 0; i < 8; i++) st += red[i];
    const float inv = 1.0f / st;

    unsigned* q = Sh + (size_t)row * 4096;
    #pragma unroll
    for (int i = 0; i < 8; i++) {
        uint2 w;
        w.x = packh2(v[i].x * inv, v[i].y * inv);
        w.y = packh2(v[i].z * inv, v[i].w * inv);
        *reinterpret_cast<uint2*>(q + (tid + 256 * i) * 2) = w;
    }
}

// ------------------------------ launcher -----------------------------------
extern "C" void kernel_launch(void* const* d_in, const int* in_sizes, int n_in,
                              void* d_out, int out_size)
{
    const float* za = (const float*)d_in[0];
    const float* zb = (const float*)d_in[1];
    const float* W1 = (const float*)d_in[2];
    const float* b1 = (const float*)d_in[3];
    const float* W2 = (const float*)d_in[4];
    const float* b2 = (const float*)d_in[5];
    const float* Wq = (const float*)d_in[6];
    const float* bq = (const float*)d_in[7];
    const float* Wk = (const float*)d_in[8];
    const float* bk = (const float*)d_in[9];
    const float* Wv = (const float*)d_in[10];
    const float* bv = (const float*)d_in[11];
    float* out = (float*)d_out;

    unsigned *Zh, *Zl, *Hh, *Hl, *Ph, *Pl, *Qh, *Kh, *Kl, *Vh, *VT;
    unsigned *W1h, *W1l, *W2h, *W2l, *Wqh, *Wql, *Wkh, *Wkl, *Wvh, *Wvl, *Sh;
    float *S;
    cudaGetSymbolAddress((void**)&Zh,  g_Zh);  cudaGetSymbolAddress((void**)&Zl,  g_Zl);
    cudaGetSymbolAddress((void**)&Hh,  g_Hh);  cudaGetSymbolAddress((void**)&Hl,  g_Hl);
    cudaGetSymbolAddress((void**)&Ph,  g_Ph);  cudaGetSymbolAddress((void**)&Pl,  g_Pl);
    cudaGetSymbolAddress((void**)&Qh,  g_Qh);
    cudaGetSymbolAddress((void**)&Kh,  g_Kh);  cudaGetSymbolAddress((void**)&Kl,  g_Kl);
    cudaGetSymbolAddress((void**)&Vh,  g_Vh);  cudaGetSymbolAddress((void**)&VT,  g_VT);
    cudaGetSymbolAddress((void**)&W1h, g_W1h); cudaGetSymbolAddress((void**)&W1l, g_W1l);
    cudaGetSymbolAddress((void**)&W2h, g_W2h); cudaGetSymbolAddress((void**)&W2l, g_W2l);
    cudaGetSymbolAddress((void**)&Wqh, g_Wqh); cudaGetSymbolAddress((void**)&Wql, g_Wql);
    cudaGetSymbolAddress((void**)&Wkh, g_Wkh); cudaGetSymbolAddress((void**)&Wkl, g_Wkl);
    cudaGetSymbolAddress((void**)&Wvh, g_Wvh); cudaGetSymbolAddress((void**)&Wvl, g_Wvl);
    cudaGetSymbolAddress((void**)&S,   g_S);   cudaGetSymbolAddress((void**)&Sh,  g_Sh);

    const int smem_split  = 3 * 4 * (int)SLB;   // 99072 B (bf16 split-3)
    const int smem_sc     = 3 * 3 * (int)SLB;   // 74304 B (fp16 split-2)
    const int smem_single = 3 * 2 * (int)SLB;   // 49536 B (fp16 single)
    cudaFuncSetAttribute(gemm_mm<2,0,1>, cudaFuncAttributeMaxDynamicSharedMemorySize, smem_split);
    cudaFuncSetAttribute(gemm_mm<1,0,1>, cudaFuncAttributeMaxDynamicSharedMemorySize, smem_split);
    cudaFuncSetAttribute(gemm_mm<1,0,2>, cudaFuncAttributeMaxDynamicSharedMemorySize, smem_split);
    cudaFuncSetAttribute(gemm_mm<1,0,3>, cudaFuncAttributeMaxDynamicSharedMemorySize, smem_split);
    cudaFuncSetAttribute(gemm_mm<0,2,0>, cudaFuncAttributeMaxDynamicSharedMemorySize, smem_sc);
    cudaFuncSetAttribute(gemm_mm<0,1,0>, cudaFuncAttributeMaxDynamicSharedMemorySize, smem_single);

    const dim3 blk(256);
    const dim3 tblk(32, 8);
    const float inv_scale = 1.0f / 16.0f;   // 1/sqrt(OUT/2)
    const size_t HALFW = (size_t)8192 * 256;
    const size_t HVTW  = (size_t)512 * 4096;

    // launches 1-3, so captured launch #4 is the proj-L1 split GEMM
    split_in<<<16384, blk>>>(za, zb, Zh, Zl);
    transpose_split<<<dim3(32, 32), tblk>>>(W1, W1h, W1l, 1024, 1024);
    transpose_split<<<dim3(16, 32), tblk>>>(W2, W2h, W2l, 1024, 512);

    // #4: proj layer 1: H = ELU(Z @ W1^T + b1)   [16384 x 1024]
    gemm_mm<2,0,1><<<dim3(8, 128), blk, smem_split>>>(
        Zh, Zl, W1h, W1l, b1, nullptr, Hh, Hl, 16384, 1024, 1024, 512, 0, 1.f);

    transpose_split<<<dim3(16, 16), tblk>>>(Wq, Wqh, Wql, 512, 512);
    transpose_split<<<dim3(16, 16), tblk>>>(Wk, Wkh, Wkl, 512, 512);
    transpose_split<<<dim3(16, 16), tblk>>>(Wv, Wvh, Wvl, 512, 512);

    // proj layer 2: P = H @ W2^T + b2            [16384 x 512]
    gemm_mm<1,0,1><<<dim3(4, 128), blk, smem_split>>>(
        Hh, Hl, W2h, W2l, b2, nullptr, Ph, Pl, 16384, 512, 1024, 256, 0, 1.f);
    // Q (fp16 single), K (fp16 hi/lo), V (fp16 single)
    gemm_mm<1,0,2><<<dim3(4, 128), blk, smem_split>>>(
        Ph, Pl, Wqh, Wql, bq, nullptr, Qh, nullptr, 16384, 512, 512, 256, 0, 1.f);
    gemm_mm<1,0,3><<<dim3(4, 128), blk, smem_split>>>(
        Ph, Pl, Wkh, Wkl, bk, nullptr, Kh, Kl, 16384, 512, 512, 256, 0, 1.f);
    gemm_mm<1,0,2><<<dim3(4, 128), blk, smem_split>>>(
        Ph, Pl, Wvh, Wvl, bv, nullptr, Vh, nullptr, 16384, 512, 512, 256, 0, 1.f);
    // V^T per half (fp16)
    transpose_h<<<dim3(16, 256), tblk>>>(Vh,         VT,        8192, 512);
    transpose_h<<<dim3(16, 256), tblk>>>(Vh + HALFW, VT + HVTW, 8192, 512);

    // direction A: out[:, 0:512] = softmax(Qa @ Kb^T / 16) @ Vb
    gemm_mm<0,2,0><<<dim3(64, 64), blk, smem_sc>>>(
        Qh, nullptr, Kh + HALFW, Kl + HALFW, nullptr, S, nullptr, nullptr,
        8192, 8192, 512, 8192, 0, inv_scale);
    softmax_rows<<<8192, blk>>>(S, Sh);
    gemm_mm<0,1,0><<<dim3(4, 64), blk, smem_single>>>(
        Sh, nullptr, VT + HVTW, nullptr, nullptr, out, nullptr, nullptr,
        8192, 512, 8192, 1024, 0, 1.f);

    // direction B: out[:, 512:1024] = softmax(Qb @ Ka^T / 16) @ Va
    gemm_mm<0,2,0><<<dim3(64, 64), blk, smem_sc>>>(
        Qh + HALFW, nullptr, Kh, Kl, nullptr, S, nullptr, nullptr,
        8192, 8192, 512, 8192, 0, inv_scale);
    softmax_rows<<<8192, blk>>>(S, Sh);
    gemm_mm<0,1,0><<<dim3(4, 64), blk, smem_single>>>(
        Sh, nullptr, VT, nullptr, nullptr, out, nullptr, nullptr,
        8192, 512, 8192, 1024, 512, 1.f);
}

// round 9
// speedup vs baseline: 1.5530x; 1.1668x over previous
#include <cuda_runtime.h>
#include <cuda_bf16.h>
#include <cuda_fp16.h>
#include <math.h>

// ---------------------------------------------------------------------------
// Contrast on legacy mma.sync m16n8k16 (baseline PTX; harness targets sm_103).
// proj/QKV: bf16 split-3 (near-exact). Scores: fp16 single (Q,K fp16).
// AV: fp16 single. 3-stage cp.async ring, ldmatrix fragments.
// Directions A/B fused per phase via DUAL kernels.
// ---------------------------------------------------------------------------

namespace {
constexpr int KBLK  = 1032;            // u32 words per k16-block: 128*8 + 8 pad
constexpr unsigned SLB = 2u * KBLK * 4u;   // bytes per matrix-half per BK=32 tile
}

// ------------------------------ scratch (u32 words) -------------------------
__device__ unsigned g_Zh [8388608], g_Zl [8388608];   // split(za|zb) 16384x1024
__device__ unsigned g_Hh [8388608], g_Hl [8388608];   // H split     16384x1024
__device__ unsigned g_Ph [4194304], g_Pl [4194304];   // P split     16384x512
__device__ unsigned g_Qh [4194304];                   // Q fp16      16384x512
__device__ unsigned g_Kh [4194304];                   // K fp16      16384x512
__device__ unsigned g_Vh [4194304];                   // V fp16      16384x512
__device__ unsigned g_VT [4194304];                   // V^T fp16 per half [512,8192]
__device__ unsigned g_W1h[524288],  g_W1l[524288];
__device__ unsigned g_W2h[262144],  g_W2l[262144];
__device__ unsigned g_Wqh[131072],  g_Wql[131072];
__device__ unsigned g_Wkh[131072],  g_Wkl[131072];
__device__ unsigned g_Wvh[131072],  g_Wvl[131072];
__device__ float    g_S  [134217728];                 // fp32 scores 16384x8192
__device__ unsigned g_Sh [67108864];                  // fp16 softmaxed 16384x4096w

// ------------------------------ helpers ------------------------------------
__device__ __forceinline__ void mma_bf16(float* c, const unsigned* a,
                                         unsigned b0, unsigned b1) {
    asm volatile(
        "mma.sync.aligned.m16n8k16.row.col.f32.bf16.bf16.f32 "
        "{%0,%1,%2,%3}, {%4,%5,%6,%7}, {%8,%9}, {%0,%1,%2,%3};"
        : "+f"(c[0]), "+f"(c[1]), "+f"(c[2]), "+f"(c[3])
        : "r"(a[0]), "r"(a[1]), "r"(a[2]), "r"(a[3]), "r"(b0), "r"(b1));
}

__device__ __forceinline__ void mma_fp16(float* c, const unsigned* a,
                                         unsigned b0, unsigned b1) {
    asm volatile(
        "mma.sync.aligned.m16n8k16.row.col.f32.f16.f16.f32 "
        "{%0,%1,%2,%3}, {%4,%5,%6,%7}, {%8,%9}, {%0,%1,%2,%3};"
        : "+f"(c[0]), "+f"(c[1]), "+f"(c[2]), "+f"(c[3])
        : "r"(a[0]), "r"(a[1]), "r"(a[2]), "r"(a[3]), "r"(b0), "r"(b1));
}

__device__ __forceinline__ void ldsm_x4(unsigned* r, unsigned addr) {
    asm volatile("ldmatrix.sync.aligned.m8n8.x4.shared.b16 {%0,%1,%2,%3}, [%4];"
        : "=r"(r[0]), "=r"(r[1]), "=r"(r[2]), "=r"(r[3]) : "r"(addr));
}

__device__ __forceinline__ void cp16(unsigned dst, const void* src) {
    asm volatile("cp.async.cg.shared.global [%0], [%1], 16;" :: "r"(dst), "l"(src));
}

__device__ __forceinline__ unsigned smem_u32(const void* p) {
    unsigned a;
    asm("{ .reg .u64 t; cvta.to.shared.u64 t, %1; cvt.u32.u64 %0, t; }"
        : "=r"(a) : "l"(p));
    return a;
}

__device__ __forceinline__ void split2(float x, float y, unsigned& hi, unsigned& lo) {
    __nv_bfloat16 hx = __float2bfloat16(x);
    __nv_bfloat16 hy = __float2bfloat16(y);
    __nv_bfloat16 lx = __float2bfloat16(x - __bfloat162float(hx));
    __nv_bfloat16 ly = __float2bfloat16(y - __bfloat162float(hy));
    hi = ((unsigned)__bfloat16_as_ushort(hy) << 16) | (unsigned)__bfloat16_as_ushort(hx);
    lo = ((unsigned)__bfloat16_as_ushort(ly) << 16) | (unsigned)__bfloat16_as_ushort(lx);
}

__device__ __forceinline__ unsigned packh2(float x, float y) {
    __half2 h = __floats2half2_rn(x, y);
    return *reinterpret_cast<unsigned*>(&h);
}

// --------------------------- input split -----------------------------------
__global__ void __launch_bounds__(256, 8)
split_in(const float* __restrict__ za, const float* __restrict__ zb,
         unsigned* __restrict__ Zh, unsigned* __restrict__ Zl)
{
    const size_t t = (size_t)blockIdx.x * 256 + threadIdx.x;
    const size_t f = t * 4;
    const float4 v = (f < (size_t)8388608)
        ? *reinterpret_cast<const float4*>(za + f)
        : *reinterpret_cast<const float4*>(zb + (f - 8388608));
    uint2 h, l;
    split2(v.x, v.y, h.x, l.x);
    split2(v.z, v.w, h.y, l.y);
    *reinterpret_cast<uint2*>(Zh + t * 2) = h;
    *reinterpret_cast<uint2*>(Zl + t * 2) = l;
}

// --------------------------- weight transpose + split -----------------------
__global__ void __launch_bounds__(256, 4)
transpose_split(const float* __restrict__ src, unsigned* __restrict__ dh,
                unsigned* __restrict__ dl, int R, int C)
{
    __shared__ float t[32][33];
    const int bx = blockIdx.x * 32;
    const int by = blockIdx.y * 32;
    const int x  = bx + threadIdx.x;
    #pragma unroll
    for (int i = threadIdx.y; i < 32; i += 8)
        t[i][threadIdx.x] = src[(size_t)(by + i) * C + x];
    __syncthreads();
    const int xo = by + threadIdx.x;
    unsigned short* ph = reinterpret_cast<unsigned short*>(dh);
    unsigned short* pl = reinterpret_cast<unsigned short*>(dl);
    #pragma unroll
    for (int i = threadIdx.y; i < 32; i += 8) {
        const float v = t[threadIdx.x][i];
        const __nv_bfloat16 h = __float2bfloat16(v);
        const __nv_bfloat16 l = __float2bfloat16(v - __bfloat162float(h));
        ph[(size_t)(bx + i) * R + xo] = __bfloat16_as_ushort(h);
        pl[(size_t)(bx + i) * R + xo] = __bfloat16_as_ushort(l);
    }
}

// --------------------------- fp16 transpose --------------------------------
__global__ void __launch_bounds__(256, 4)
transpose_h(const unsigned* __restrict__ srcw, unsigned* __restrict__ dstw, int R, int C)
{
    __shared__ unsigned short t[32][34];
    const unsigned short* src = reinterpret_cast<const unsigned short*>(srcw);
    unsigned short* dst = reinterpret_cast<unsigned short*>(dstw);
    const int bx = blockIdx.x * 32;
    const int by = blockIdx.y * 32;
    const int x  = bx + threadIdx.x;
    #pragma unroll
    for (int i = threadIdx.y; i < 32; i += 8)
        t[i][threadIdx.x] = src[(size_t)(by + i) * C + x];
    __syncthreads();
    const int xo = by + threadIdx.x;
    #pragma unroll
    for (int i = threadIdx.y; i < 32; i += 8)
        dst[(size_t)(bx + i) * R + xo] = t[threadIdx.x][i];
}

// ------------------------------ GEMM ---------------------------------------
// C = epi(A[M,K] @ B[N,K]^T), operands pre-packed 16-bit (u32 pitch K/2).
// PREC 0: bf16 split-3 (Ah/Al, Bh/Bl).  PREC 1: fp16 single (Ah, Bh).
// EPI 0: v*=scale ; EPI 1: v+=bias ; EPI 2: elu(v+bias)
// OFMT 0: f32 Cf ; OFMT 1: split bf16 Ch/Cl ; OFMT 2: fp16 Ch
// DUAL 0: none ; 1: second M-half uses Bh2 (out rows unchanged)
//      2: second M-half uses Bh2+coff2 and out rows fold by M/2
template <int EPI, int PREC, int OFMT, int DUAL>
__global__ void __launch_bounds__(256, 2)
gemm_mm(const unsigned* __restrict__ Ah, const unsigned* __restrict__ Al,
        const unsigned* __restrict__ Bh, const unsigned* __restrict__ Bl,
        const float* __restrict__ bias,
        float* __restrict__ Cf, unsigned* __restrict__ Ch, unsigned* __restrict__ Cl,
        int M, int N, int K, int ldc, int coff, float scale,
        const unsigned* __restrict__ Bh2, int coff2)
{
    extern __shared__ unsigned sm[];
    const unsigned tilesb = smem_u32(sm);
    constexpr unsigned YOFFB = (PREC == 0) ? 2u * SLB : SLB;    // B-hi offset
    constexpr unsigned BUFB  = (PREC == 0) ? 4u * SLB : 2u * SLB;

    const int tid  = threadIdx.x;
    const int bm   = blockIdx.y * 128;
    const int bn   = blockIdx.x * 128;
    const int warp = tid >> 5;
    const int lane = tid & 31;
    const int wm   = (warp >> 2) * 64;
    const int wn   = (warp & 3) * 32;
    const int g    = lane >> 2;
    const int t2   = (lane & 3) * 2;

    // DUAL selection (whole CTA is in one half)
    const bool second = (DUAL != 0) && (bm >= (M >> 1));
    const unsigned* Bu = second ? Bh2 : Bh;
    const int co   = (DUAL == 2 && second) ? coff2 : coff;
    const int rfold = (DUAL == 2 && second) ? (M >> 1) : 0;

    // ldmatrix relative addresses (buffer 0, k-block 0)
    const int mi = lane >> 3;
    const int rl = (lane & 7) + ((mi & 1) << 3);
    const int kg = mi >> 1;
    unsigned relA[4], relB[2];
    #pragma unroll
    for (int mf = 0; mf < 4; mf++) {
        const int row = wm + mf * 16 + rl;
        const int w   = (kg << 2) ^ (((row >> 2) & 1) << 2);
        relA[mf] = tilesb + 4u * (unsigned)(row * 8 + w);
    }
    #pragma unroll
    for (int p = 0; p < 2; p++) {
        const int nf  = 2 * p + (mi >> 1);
        const int row = wn + nf * 8 + (lane & 7);
        const int w   = ((mi & 1) << 2) ^ (((row >> 2) & 1) << 2);
        relB[p] = tilesb + YOFFB + 4u * (unsigned)(row * 8 + w);
    }

    // staging mapping: 4 threads per 128-row, 2 row-passes
    const int srow  = tid >> 2;               // 0..63 (+64)
    const int scol8 = (tid & 3) * 8;          // 0,8,16,24
    const int sblk  = scol8 >> 4;             // k16-block 0..1
    const int sw0   = ((scol8 & 15) >> 1) ^ (((srow >> 2) & 1) * 4);
    const unsigned sidx0 = (unsigned)(sblk * KBLK + srow * 8 + sw0);
    const int kw = K >> 1;

    float acc[4][4][4];
    #pragma unroll
    for (int i = 0; i < 4; i++)
        #pragma unroll
        for (int j = 0; j < 4; j++)
            #pragma unroll
            for (int e = 0; e < 4; e++) acc[i][j][e] = 0.f;

    auto stage = [&](int kt, unsigned bufb) {
        const int w0 = kt * 16 + (scol8 >> 1);
        const unsigned d0 = tilesb + bufb + 4u * sidx0;
        #pragma unroll
        for (int i = 0; i < 2; i++) {
            const size_t ro = (size_t)(bm + srow + 64 * i) * kw + w0;
            cp16(d0 + 2048u * i, Ah + ro);
            if (PREC == 0) cp16(d0 + 2048u * i + SLB, Al + ro);
        }
        #pragma unroll
        for (int i = 0; i < 2; i++) {
            const size_t ro = (size_t)(bn + srow + 64 * i) * kw + w0;
            cp16(d0 + 2048u * i + YOFFB, Bu + ro);
            if (PREC == 0) cp16(d0 + 2048u * i + YOFFB + SLB, Bl + ro);
        }
        asm volatile("cp.async.commit_group;" ::: "memory");
    };

    auto compute = [&](unsigned bufb) {
        #pragma unroll
        for (int blk = 0; blk < 2; blk++) {
            const unsigned off = bufb + (unsigned)(blk * (KBLK * 4));
            unsigned a[4][4], b[2][4];
            #pragma unroll
            for (int mf = 0; mf < 4; mf++) ldsm_x4(a[mf], relA[mf] + off);
            #pragma unroll
            for (int p = 0; p < 2; p++)    ldsm_x4(b[p],  relB[p] + off);
            #pragma unroll
            for (int mf = 0; mf < 4; mf++)
                #pragma unroll
                for (int nf = 0; nf < 4; nf++) {
                    const unsigned b0 = b[nf >> 1][(nf & 1) * 2];
                    const unsigned b1 = b[nf >> 1][(nf & 1) * 2 + 1];
                    if (PREC == 0) mma_bf16(acc[mf][nf], a[mf], b0, b1);
                    else           mma_fp16(acc[mf][nf], a[mf], b0, b1);
                }
            if (PREC == 0) {
                unsigned bl2[2][4];
                #pragma unroll
                for (int p = 0; p < 2; p++) ldsm_x4(bl2[p], relB[p] + off + SLB);
                #pragma unroll
                for (int mf = 0; mf < 4; mf++)
                    #pragma unroll
                    for (int nf = 0; nf < 4; nf++)
                        mma_bf16(acc[mf][nf], a[mf],
                                 bl2[nf >> 1][(nf & 1) * 2], bl2[nf >> 1][(nf & 1) * 2 + 1]);
                unsigned al2[4][4];
                #pragma unroll
                for (int mf = 0; mf < 4; mf++) ldsm_x4(al2[mf], relA[mf] + off + SLB);
                #pragma unroll
                for (int mf = 0; mf < 4; mf++)
                    #pragma unroll
                    for (int nf = 0; nf < 4; nf++)
                        mma_bf16(acc[mf][nf], al2[mf],
                                 b[nf >> 1][(nf & 1) * 2], b[nf >> 1][(nf & 1) * 2 + 1]);
            }
        }
    };

    const int ktiles = K / 32;
    stage(0, 0u);
    stage(1, BUFB);
    for (int kt = 0; kt < ktiles; kt++) {
        if (kt + 1 < ktiles) asm volatile("cp.async.wait_group 1;" ::: "memory");
        else                 asm volatile("cp.async.wait_group 0;" ::: "memory");
        __syncthreads();
        if (kt + 2 < ktiles) stage(kt + 2, (unsigned)((kt + 2) % 3) * BUFB);
        compute((unsigned)(kt % 3) * BUFB);
    }

    // epilogue
    #pragma unroll
    for (int mf = 0; mf < 4; mf++) {
        #pragma unroll
        for (int nf = 0; nf < 4; nf++) {
            const int row = bm + wm + mf * 16 + g - rfold;
            const int col = bn + wn + nf * 8 + t2;
            float v0 = acc[mf][nf][0], v1 = acc[mf][nf][1];
            float v2 = acc[mf][nf][2], v3 = acc[mf][nf][3];
            if (EPI == 0) {
                v0 *= scale; v1 *= scale; v2 *= scale; v3 *= scale;
            } else {
                const float bb0 = bias[col], bb1 = bias[col + 1];
                v0 += bb0; v1 += bb1; v2 += bb0; v3 += bb1;
                if (EPI == 2) {
                    v0 = v0 > 0.f ? v0 : expm1f(v0);
                    v1 = v1 > 0.f ? v1 : expm1f(v1);
                    v2 = v2 > 0.f ? v2 : expm1f(v2);
                    v3 = v3 > 0.f ? v3 : expm1f(v3);
                }
            }
            if (OFMT == 0) {
                *reinterpret_cast<float2*>(Cf + (size_t)row * ldc + co + col)       = make_float2(v0, v1);
                *reinterpret_cast<float2*>(Cf + (size_t)(row + 8) * ldc + co + col) = make_float2(v2, v3);
            } else if (OFMT == 1) {
                unsigned h, l;
                split2(v0, v1, h, l);
                Ch[(size_t)row * ldc + (col >> 1)] = h;
                Cl[(size_t)row * ldc + (col >> 1)] = l;
                split2(v2, v3, h, l);
                Ch[(size_t)(row + 8) * ldc + (col >> 1)] = h;
                Cl[(size_t)(row + 8) * ldc + (col >> 1)] = l;
            } else {
                Ch[(size_t)row * ldc + (col >> 1)]       = packh2(v0, v1);
                Ch[(size_t)(row + 8) * ldc + (col >> 1)] = packh2(v2, v3);
            }
        }
    }
}

// ------------------------------ softmax ------------------------------------
__global__ void __launch_bounds__(256, 1)
softmax_rows(const float* __restrict__ S, unsigned* __restrict__ Sh)
{
    const int row = blockIdx.x;
    const float4* p = reinterpret_cast<const float4*>(S + (size_t)row * 8192);
    const int tid = threadIdx.x;

    float4 v[8];
    #pragma unroll
    for (int i = 0; i < 8; i++) v[i] = p[tid + 256 * i];

    float m = -3.402823e38f;
    #pragma unroll
    for (int i = 0; i < 8; i++)
        m = fmaxf(m, fmaxf(fmaxf(v[i].x, v[i].y), fmaxf(v[i].z, v[i].w)));

    __shared__ float red[8];
    #pragma unroll
    for (int o = 16; o; o >>= 1) m = fmaxf(m, __shfl_xor_sync(0xffffffffu, m, o));
    if ((tid & 31) == 0) red[tid >> 5] = m;
    __syncthreads();
    float mm = red[0];
    #pragma unroll
    for (int i = 1; i < 8; i++) mm = fmaxf(mm, red[i]);

    float s = 0.f;
    #pragma unroll
    for (int i = 0; i < 8; i++) {
        v[i].x = __expf(v[i].x - mm); s += v[i].x;
        v[i].y = __expf(v[i].y - mm); s += v[i].y;
        v[i].z = __expf(v[i].z - mm); s += v[i].z;
        v[i].w = __expf(v[i].w - mm); s += v[i].w;
    }
    #pragma unroll
    for (int o = 16; o; o >>= 1) s += __shfl_xor_sync(0xffffffffu, s, o);
    __syncthreads();
    if ((tid & 31) == 0) red[tid >> 5] = s;
    __syncthreads();
    float st = 0.f;
    #pragma unroll
    for (int i = 0; i < 8; i++) st += red[i];
    const float inv = 1.0f / st;

    unsigned* q = Sh + (size_t)row * 4096;
    #pragma unroll
    for (int i = 0; i < 8; i++) {
        uint2 w;
        w.x = packh2(v[i].x * inv, v[i].y * inv);
        w.y = packh2(v[i].z * inv, v[i].w * inv);
        *reinterpret_cast<uint2*>(q + (tid + 256 * i) * 2) = w;
    }
}

// ------------------------------ launcher -----------------------------------
extern "C" void kernel_launch(void* const* d_in, const int* in_sizes, int n_in,
                              void* d_out, int out_size)
{
    const float* za = (const float*)d_in[0];
    const float* zb = (const float*)d_in[1];
    const float* W1 = (const float*)d_in[2];
    const float* b1 = (const float*)d_in[3];
    const float* W2 = (const float*)d_in[4];
    const float* b2 = (const float*)d_in[5];
    const float* Wq = (const float*)d_in[6];
    const float* bq = (const float*)d_in[7];
    const float* Wk = (const float*)d_in[8];
    const float* bk = (const float*)d_in[9];
    const float* Wv = (const float*)d_in[10];
    const float* bv = (const float*)d_in[11];
    float* out = (float*)d_out;

    unsigned *Zh, *Zl, *Hh, *Hl, *Ph, *Pl, *Qh, *Kh, *Vh, *VT;
    unsigned *W1h, *W1l, *W2h, *W2l, *Wqh, *Wql, *Wkh, *Wkl, *Wvh, *Wvl, *Sh;
    float *S;
    cudaGetSymbolAddress((void**)&Zh,  g_Zh);  cudaGetSymbolAddress((void**)&Zl,  g_Zl);
    cudaGetSymbolAddress((void**)&Hh,  g_Hh);  cudaGetSymbolAddress((void**)&Hl,  g_Hl);
    cudaGetSymbolAddress((void**)&Ph,  g_Ph);  cudaGetSymbolAddress((void**)&Pl,  g_Pl);
    cudaGetSymbolAddress((void**)&Qh,  g_Qh);  cudaGetSymbolAddress((void**)&Kh,  g_Kh);
    cudaGetSymbolAddress((void**)&Vh,  g_Vh);  cudaGetSymbolAddress((void**)&VT,  g_VT);
    cudaGetSymbolAddress((void**)&W1h, g_W1h); cudaGetSymbolAddress((void**)&W1l, g_W1l);
    cudaGetSymbolAddress((void**)&W2h, g_W2h); cudaGetSymbolAddress((void**)&W2l, g_W2l);
    cudaGetSymbolAddress((void**)&Wqh, g_Wqh); cudaGetSymbolAddress((void**)&Wql, g_Wql);
    cudaGetSymbolAddress((void**)&Wkh, g_Wkh); cudaGetSymbolAddress((void**)&Wkl, g_Wkl);
    cudaGetSymbolAddress((void**)&Wvh, g_Wvh); cudaGetSymbolAddress((void**)&Wvl, g_Wvl);
    cudaGetSymbolAddress((void**)&S,   g_S);   cudaGetSymbolAddress((void**)&Sh,  g_Sh);

    const int smem_split  = 3 * 4 * (int)SLB;   // 99072 B (bf16 split-3)
    const int smem_single = 3 * 2 * (int)SLB;   // 49536 B (fp16 single)
    cudaFuncSetAttribute(gemm_mm<2,0,1,0>, cudaFuncAttributeMaxDynamicSharedMemorySize, smem_split);
    cudaFuncSetAttribute(gemm_mm<1,0,1,0>, cudaFuncAttributeMaxDynamicSharedMemorySize, smem_split);
    cudaFuncSetAttribute(gemm_mm<1,0,2,0>, cudaFuncAttributeMaxDynamicSharedMemorySize, smem_split);
    cudaFuncSetAttribute(gemm_mm<0,1,0,1>, cudaFuncAttributeMaxDynamicSharedMemorySize, smem_single);
    cudaFuncSetAttribute(gemm_mm<0,1,0,2>, cudaFuncAttributeMaxDynamicSharedMemorySize, smem_single);

    const dim3 blk(256);
    const dim3 tblk(32, 8);
    const float inv_scale = 1.0f / 16.0f;   // 1/sqrt(OUT/2)
    const size_t HALFW = (size_t)8192 * 256;
    const size_t HVTW  = (size_t)512 * 4096;

    // launches 1-3, captured launch #4 is the proj-L1 split GEMM
    split_in<<<16384, blk>>>(za, zb, Zh, Zl);
    transpose_split<<<dim3(32, 32), tblk>>>(W1, W1h, W1l, 1024, 1024);
    transpose_split<<<dim3(16, 32), tblk>>>(W2, W2h, W2l, 1024, 512);

    // #4: proj layer 1: H = ELU(Z @ W1^T + b1)   [16384 x 1024]
    gemm_mm<2,0,1,0><<<dim3(8, 128), blk, smem_split>>>(
        Zh, Zl, W1h, W1l, b1, nullptr, Hh, Hl, 16384, 1024, 1024, 512, 0, 1.f,
        nullptr, 0);

    transpose_split<<<dim3(16, 16), tblk>>>(Wq, Wqh, Wql, 512, 512);
    transpose_split<<<dim3(16, 16), tblk>>>(Wk, Wkh, Wkl, 512, 512);
    transpose_split<<<dim3(16, 16), tblk>>>(Wv, Wvh, Wvl, 512, 512);

    // proj layer 2: P = H @ W2^T + b2            [16384 x 512]
    gemm_mm<1,0,1,0><<<dim3(4, 128), blk, smem_split>>>(
        Hh, Hl, W2h, W2l, b2, nullptr, Ph, Pl, 16384, 512, 1024, 256, 0, 1.f,
        nullptr, 0);
    // Q, K, V all fp16 single outputs
    gemm_mm<1,0,2,0><<<dim3(4, 128), blk, smem_split>>>(
        Ph, Pl, Wqh, Wql, bq, nullptr, Qh, nullptr, 16384, 512, 512, 256, 0, 1.f,
        nullptr, 0);
    gemm_mm<1,0,2,0><<<dim3(4, 128), blk, smem_split>>>(
        Ph, Pl, Wkh, Wkl, bk, nullptr, Kh, nullptr, 16384, 512, 512, 256, 0, 1.f,
        nullptr, 0);
    gemm_mm<1,0,2,0><<<dim3(4, 128), blk, smem_split>>>(
        Ph, Pl, Wvh, Wvl, bv, nullptr, Vh, nullptr, 16384, 512, 512, 256, 0, 1.f,
        nullptr, 0);
    // V^T per half (fp16)
    transpose_h<<<dim3(16, 256), tblk>>>(Vh,         VT,        8192, 512);
    transpose_h<<<dim3(16, 256), tblk>>>(Vh + HALFW, VT + HVTW, 8192, 512);

    // fused scores: rows 0-8191 = Qa @ Kb^T, rows 8192-16383 = Qb @ Ka^T
    gemm_mm<0,1,0,1><<<dim3(64, 128), blk, smem_single>>>(
        Qh, nullptr, Kh + HALFW, nullptr, nullptr, S, nullptr, nullptr,
        16384, 8192, 512, 8192, 0, inv_scale, Kh, 0);
    // fused softmax over all 16384 rows
    softmax_rows<<<16384, blk>>>(S, Sh);
    // fused AV: rows 0-8191 -> out[:,0:512] (Vb), rows 8192-16383 -> out[:,512:1024] (Va)
    gemm_mm<0,1,0,2><<<dim3(4, 128), blk, smem_single>>>(
        Sh, nullptr, VT + HVTW, nullptr, nullptr, out, nullptr, nullptr,
        16384, 512, 8192, 1024, 0, 1.f, VT, 512);
}

// round 10
// speedup vs baseline: 1.6922x; 1.0896x over previous
#include <cuda_runtime.h>
#include <cuda_bf16.h>
#include <cuda_fp16.h>
#include <math.h>

// ---------------------------------------------------------------------------
// Contrast on legacy mma.sync m16n8k16 (baseline PTX; harness targets sm_103).
// L1: bf16 split-3 -> H fp16. L2/QKV: A fp16 x B fp16-split-2 -> fp16.
// Scores/AV: fp16 single. 3-stage cp.async ring + ldmatrix. A/B dirs fused.
// ---------------------------------------------------------------------------

namespace {
constexpr int KBLK  = 1032;            // u32 words per k16-block: 128*8 + 8 pad
constexpr unsigned SLB = 2u * KBLK * 4u;   // bytes per matrix-half per BK=32 tile
}

// ------------------------------ scratch (u32 words) -------------------------
__device__ unsigned g_Zh [8388608], g_Zl [8388608];   // split(za|zb) 16384x1024 bf16
__device__ unsigned g_Hh [8388608];                   // H fp16   16384x1024
__device__ unsigned g_Ph [4194304];                   // P fp16   16384x512
__device__ unsigned g_Qh [4194304];                   // Q fp16
__device__ unsigned g_Kh [4194304];                   // K fp16
__device__ unsigned g_Vh [4194304];                   // V fp16
__device__ unsigned g_VT [4194304];                   // V^T fp16 per half [512,8192]
__device__ unsigned g_W1h[524288],  g_W1l[524288];    // W1^T bf16 hi/lo [1024,1024]
__device__ unsigned g_W2h[262144],  g_W2l[262144];    // W2^T fp16 hi/lo [512,1024]
__device__ unsigned g_W3h[393216],  g_W3l[393216];    // [Wq;Wk;Wv]^T fp16 hi/lo [1536,512]
__device__ float    g_bqkv[1536];                     // concat biases
__device__ float    g_S  [134217728];                 // fp32 scores 16384x8192
__device__ unsigned g_Sh [67108864];                  // fp16 softmaxed 16384x4096w

// ------------------------------ helpers ------------------------------------
__device__ __forceinline__ void mma_bf16(float* c, const unsigned* a,
                                         unsigned b0, unsigned b1) {
    asm volatile(
        "mma.sync.aligned.m16n8k16.row.col.f32.bf16.bf16.f32 "
        "{%0,%1,%2,%3}, {%4,%5,%6,%7}, {%8,%9}, {%0,%1,%2,%3};"
        : "+f"(c[0]), "+f"(c[1]), "+f"(c[2]), "+f"(c[3])
        : "r"(a[0]), "r"(a[1]), "r"(a[2]), "r"(a[3]), "r"(b0), "r"(b1));
}

__device__ __forceinline__ void mma_fp16(float* c, const unsigned* a,
                                         unsigned b0, unsigned b1) {
    asm volatile(
        "mma.sync.aligned.m16n8k16.row.col.f32.f16.f16.f32 "
        "{%0,%1,%2,%3}, {%4,%5,%6,%7}, {%8,%9}, {%0,%1,%2,%3};"
        : "+f"(c[0]), "+f"(c[1]), "+f"(c[2]), "+f"(c[3])
        : "r"(a[0]), "r"(a[1]), "r"(a[2]), "r"(a[3]), "r"(b0), "r"(b1));
}

__device__ __forceinline__ void ldsm_x4(unsigned* r, unsigned addr) {
    asm volatile("ldmatrix.sync.aligned.m8n8.x4.shared.b16 {%0,%1,%2,%3}, [%4];"
        : "=r"(r[0]), "=r"(r[1]), "=r"(r[2]), "=r"(r[3]) : "r"(addr));
}

__device__ __forceinline__ void cp16(unsigned dst, const void* src) {
    asm volatile("cp.async.cg.shared.global [%0], [%1], 16;" :: "r"(dst), "l"(src));
}

__device__ __forceinline__ unsigned smem_u32(const void* p) {
    unsigned a;
    asm("{ .reg .u64 t; cvta.to.shared.u64 t, %1; cvt.u32.u64 %0, t; }"
        : "=r"(a) : "l"(p));
    return a;
}

__device__ __forceinline__ void split2(float x, float y, unsigned& hi, unsigned& lo) {
    __nv_bfloat16 hx = __float2bfloat16(x);
    __nv_bfloat16 hy = __float2bfloat16(y);
    __nv_bfloat16 lx = __float2bfloat16(x - __bfloat162float(hx));
    __nv_bfloat16 ly = __float2bfloat16(y - __bfloat162float(hy));
    hi = ((unsigned)__bfloat16_as_ushort(hy) << 16) | (unsigned)__bfloat16_as_ushort(hx);
    lo = ((unsigned)__bfloat16_as_ushort(ly) << 16) | (unsigned)__bfloat16_as_ushort(lx);
}

__device__ __forceinline__ unsigned packh2(float x, float y) {
    __half2 h = __floats2half2_rn(x, y);
    return *reinterpret_cast<unsigned*>(&h);
}

// --------------------------- input split (bf16) -----------------------------
__global__ void __launch_bounds__(256, 8)
split_in(const float* __restrict__ za, const float* __restrict__ zb,
         unsigned* __restrict__ Zh, unsigned* __restrict__ Zl)
{
    const size_t t = (size_t)blockIdx.x * 256 + threadIdx.x;
    const size_t f = t * 4;
    const float4 v = (f < (size_t)8388608)
        ? *reinterpret_cast<const float4*>(za + f)
        : *reinterpret_cast<const float4*>(zb + (f - 8388608));
    uint2 h, l;
    split2(v.x, v.y, h.x, l.x);
    split2(v.z, v.w, h.y, l.y);
    *reinterpret_cast<uint2*>(Zh + t * 2) = h;
    *reinterpret_cast<uint2*>(Zl + t * 2) = l;
}

// ----------------------- weight transpose + bf16 split ----------------------
__global__ void __launch_bounds__(256, 4)
transpose_split(const float* __restrict__ src, unsigned* __restrict__ dh,
                unsigned* __restrict__ dl, int R, int C)
{
    __shared__ float t[32][33];
    const int bx = blockIdx.x * 32;
    const int by = blockIdx.y * 32;
    const int x  = bx + threadIdx.x;
    #pragma unroll
    for (int i = threadIdx.y; i < 32; i += 8)
        t[i][threadIdx.x] = src[(size_t)(by + i) * C + x];
    __syncthreads();
    const int xo = by + threadIdx.x;
    unsigned short* ph = reinterpret_cast<unsigned short*>(dh);
    unsigned short* pl = reinterpret_cast<unsigned short*>(dl);
    #pragma unroll
    for (int i = threadIdx.y; i < 32; i += 8) {
        const float v = t[threadIdx.x][i];
        const __nv_bfloat16 h = __float2bfloat16(v);
        const __nv_bfloat16 l = __float2bfloat16(v - __bfloat162float(h));
        ph[(size_t)(bx + i) * R + xo] = __bfloat16_as_ushort(h);
        pl[(size_t)(bx + i) * R + xo] = __bfloat16_as_ushort(l);
    }
}

// ----------------------- weight transpose + fp16 split ----------------------
__global__ void __launch_bounds__(256, 4)
transpose_splith(const float* __restrict__ src, unsigned* __restrict__ dh,
                 unsigned* __restrict__ dl, int R, int C)
{
    __shared__ float t[32][33];
    const int bx = blockIdx.x * 32;
    const int by = blockIdx.y * 32;
    const int x  = bx + threadIdx.x;
    #pragma unroll
    for (int i = threadIdx.y; i < 32; i += 8)
        t[i][threadIdx.x] = src[(size_t)(by + i) * C + x];
    __syncthreads();
    const int xo = by + threadIdx.x;
    unsigned short* ph = reinterpret_cast<unsigned short*>(dh);
    unsigned short* pl = reinterpret_cast<unsigned short*>(dl);
    #pragma unroll
    for (int i = threadIdx.y; i < 32; i += 8) {
        const float v = t[threadIdx.x][i];
        const __half h = __float2half_rn(v);
        const __half l = __float2half_rn(v - __half2float(h));
        ph[(size_t)(bx + i) * R + xo] = __half_as_ushort(h);
        pl[(size_t)(bx + i) * R + xo] = __half_as_ushort(l);
    }
}

// --------------------------- fp16 transpose --------------------------------
__global__ void __launch_bounds__(256, 4)
transpose_h(const unsigned* __restrict__ srcw, unsigned* __restrict__ dstw, int R, int C)
{
    __shared__ unsigned short t[32][34];
    const unsigned short* src = reinterpret_cast<const unsigned short*>(srcw);
    unsigned short* dst = reinterpret_cast<unsigned short*>(dstw);
    const int bx = blockIdx.x * 32;
    const int by = blockIdx.y * 32;
    const int x  = bx + threadIdx.x;
    #pragma unroll
    for (int i = threadIdx.y; i < 32; i += 8)
        t[i][threadIdx.x] = src[(size_t)(by + i) * C + x];
    __syncthreads();
    const int xo = by + threadIdx.x;
    #pragma unroll
    for (int i = threadIdx.y; i < 32; i += 8)
        dst[(size_t)(bx + i) * R + xo] = t[threadIdx.x][i];
}

// ------------------------------ GEMM ---------------------------------------
// C = epi(A[M,K] @ B[N,K]^T), operands pre-packed 16-bit (u32 pitch K/2).
// PREC 0: bf16 split-3 (Ah/Al x Bh/Bl, 3 products)
// PREC 1: fp16 single  (Ah x Bh)
// PREC 2: fp16 A-single x B-split-2 (Ah x (Bh + Bl))
// EPI 0: v*=scale ; EPI 1: v+=bias[col] ; EPI 2: elu(v+bias[col])
// OFMT 0: f32 Cf (+coff) ; OFMT 2: fp16 Ch ; OFMT 4: fp16 Q/K/V triple (Ch/Cl/Cv)
// DUAL 0: none ; 1: second M-half uses Bh2 ; 2: second M-half Bh2+coff2, rows fold
template <int EPI, int PREC, int OFMT, int DUAL>
__global__ void __launch_bounds__(256, 2)
gemm_mm(const unsigned* __restrict__ Ah, const unsigned* __restrict__ Al,
        const unsigned* __restrict__ Bh, const unsigned* __restrict__ Bl,
        const float* __restrict__ bias,
        float* __restrict__ Cf, unsigned* __restrict__ Ch, unsigned* __restrict__ Cl,
        unsigned* __restrict__ Cv,
        int M, int N, int K, int ldc, int coff, float scale,
        const unsigned* __restrict__ Bh2, int coff2)
{
    extern __shared__ unsigned sm[];
    const unsigned tilesb = smem_u32(sm);
    constexpr unsigned YOFFB = (PREC == 0) ? 2u * SLB : SLB;
    constexpr unsigned BUFB  = (PREC == 0) ? 4u * SLB
                             : (PREC == 2) ? 3u * SLB : 2u * SLB;

    const int tid  = threadIdx.x;
    const int bm   = blockIdx.y * 128;
    const int bn   = blockIdx.x * 128;
    const int warp = tid >> 5;
    const int lane = tid & 31;
    const int wm   = (warp >> 2) * 64;
    const int wn   = (warp & 3) * 32;
    const int g    = lane >> 2;
    const int t2   = (lane & 3) * 2;

    const bool second = (DUAL != 0) && (bm >= (M >> 1));
    const unsigned* Bu = second ? Bh2 : Bh;
    const int co    = (DUAL == 2 && second) ? coff2 : coff;
    const int rfold = (DUAL == 2 && second) ? (M >> 1) : 0;

    // ldmatrix relative addresses (buffer 0, k-block 0)
    const int mi = lane >> 3;
    const int rl = (lane & 7) + ((mi & 1) << 3);
    const int kg = mi >> 1;
    unsigned relA[4], relB[2];
    #pragma unroll
    for (int mf = 0; mf < 4; mf++) {
        const int row = wm + mf * 16 + rl;
        const int w   = (kg << 2) ^ (((row >> 2) & 1) << 2);
        relA[mf] = tilesb + 4u * (unsigned)(row * 8 + w);
    }
    #pragma unroll
    for (int p = 0; p < 2; p++) {
        const int nf  = 2 * p + (mi >> 1);
        const int row = wn + nf * 8 + (lane & 7);
        const int w   = ((mi & 1) << 2) ^ (((row >> 2) & 1) << 2);
        relB[p] = tilesb + YOFFB + 4u * (unsigned)(row * 8 + w);
    }

    // staging mapping: 4 threads per 128-row, 2 row-passes
    const int srow  = tid >> 2;               // 0..63 (+64)
    const int scol8 = (tid & 3) * 8;          // 0,8,16,24
    const int sblk  = scol8 >> 4;             // k16-block 0..1
    const int sw0   = ((scol8 & 15) >> 1) ^ (((srow >> 2) & 1) * 4);
    const unsigned sidx0 = (unsigned)(sblk * KBLK + srow * 8 + sw0);
    const int kw = K >> 1;

    float acc[4][4][4];
    #pragma unroll
    for (int i = 0; i < 4; i++)
        #pragma unroll
        for (int j = 0; j < 4; j++)
            #pragma unroll
            for (int e = 0; e < 4; e++) acc[i][j][e] = 0.f;

    auto stage = [&](int kt, unsigned bufb) {
        const int w0 = kt * 16 + (scol8 >> 1);
        const unsigned d0 = tilesb + bufb + 4u * sidx0;
        #pragma unroll
        for (int i = 0; i < 2; i++) {
            const size_t ro = (size_t)(bm + srow + 64 * i) * kw + w0;
            cp16(d0 + 2048u * i, Ah + ro);
            if (PREC == 0) cp16(d0 + 2048u * i + SLB, Al + ro);
        }
        #pragma unroll
        for (int i = 0; i < 2; i++) {
            const size_t ro = (size_t)(bn + srow + 64 * i) * kw + w0;
            cp16(d0 + 2048u * i + YOFFB, Bu + ro);
            if (PREC == 0 || PREC == 2) cp16(d0 + 2048u * i + YOFFB + SLB, Bl + ro);
        }
        asm volatile("cp.async.commit_group;" ::: "memory");
    };

    auto compute = [&](unsigned bufb) {
        #pragma unroll
        for (int blk = 0; blk < 2; blk++) {
            const unsigned off = bufb + (unsigned)(blk * (KBLK * 4));
            unsigned a[4][4], b[2][4];
            #pragma unroll
            for (int mf = 0; mf < 4; mf++) ldsm_x4(a[mf], relA[mf] + off);
            #pragma unroll
            for (int p = 0; p < 2; p++)    ldsm_x4(b[p],  relB[p] + off);
            #pragma unroll
            for (int mf = 0; mf < 4; mf++)
                #pragma unroll
                for (int nf = 0; nf < 4; nf++) {
                    const unsigned b0 = b[nf >> 1][(nf & 1) * 2];
                    const unsigned b1 = b[nf >> 1][(nf & 1) * 2 + 1];
                    if (PREC == 0) mma_bf16(acc[mf][nf], a[mf], b0, b1);
                    else           mma_fp16(acc[mf][nf], a[mf], b0, b1);
                }
            if (PREC == 0 || PREC == 2) {
                unsigned bl2[2][4];
                #pragma unroll
                for (int p = 0; p < 2; p++) ldsm_x4(bl2[p], relB[p] + off + SLB);
                #pragma unroll
                for (int mf = 0; mf < 4; mf++)
                    #pragma unroll
                    for (int nf = 0; nf < 4; nf++) {
                        const unsigned b0 = bl2[nf >> 1][(nf & 1) * 2];
                        const unsigned b1 = bl2[nf >> 1][(nf & 1) * 2 + 1];
                        if (PREC == 0) mma_bf16(acc[mf][nf], a[mf], b0, b1);
                        else           mma_fp16(acc[mf][nf], a[mf], b0, b1);
                    }
            }
            if (PREC == 0) {
                unsigned al2[4][4];
                #pragma unroll
                for (int mf = 0; mf < 4; mf++) ldsm_x4(al2[mf], relA[mf] + off + SLB);
                #pragma unroll
                for (int mf = 0; mf < 4; mf++)
                    #pragma unroll
                    for (int nf = 0; nf < 4; nf++)
                        mma_bf16(acc[mf][nf], al2[mf],
                                 b[nf >> 1][(nf & 1) * 2], b[nf >> 1][(nf & 1) * 2 + 1]);
            }
        }
    };

    const int ktiles = K / 32;
    stage(0, 0u);
    stage(1, BUFB);
    for (int kt = 0; kt < ktiles; kt++) {
        if (kt + 1 < ktiles) asm volatile("cp.async.wait_group 1;" ::: "memory");
        else                 asm volatile("cp.async.wait_group 0;" ::: "memory");
        __syncthreads();
        if (kt + 2 < ktiles) stage(kt + 2, (unsigned)((kt + 2) % 3) * BUFB);
        compute((unsigned)(kt % 3) * BUFB);
    }

    // epilogue
    #pragma unroll
    for (int mf = 0; mf < 4; mf++) {
        #pragma unroll
        for (int nf = 0; nf < 4; nf++) {
            const int row = bm + wm + mf * 16 + g - rfold;
            const int col = bn + wn + nf * 8 + t2;
            float v0 = acc[mf][nf][0], v1 = acc[mf][nf][1];
            float v2 = acc[mf][nf][2], v3 = acc[mf][nf][3];
            if (EPI == 0) {
                v0 *= scale; v1 *= scale; v2 *= scale; v3 *= scale;
            } else {
                const float bb0 = bias[col], bb1 = bias[col + 1];
                v0 += bb0; v1 += bb1; v2 += bb0; v3 += bb1;
                if (EPI == 2) {
                    v0 = v0 > 0.f ? v0 : __expf(v0) - 1.f;
                    v1 = v1 > 0.f ? v1 : __expf(v1) - 1.f;
                    v2 = v2 > 0.f ? v2 : __expf(v2) - 1.f;
                    v3 = v3 > 0.f ? v3 : __expf(v3) - 1.f;
                }
            }
            if (OFMT == 0) {
                *reinterpret_cast<float2*>(Cf + (size_t)row * ldc + co + col)       = make_float2(v0, v1);
                *reinterpret_cast<float2*>(Cf + (size_t)(row + 8) * ldc + co + col) = make_float2(v2, v3);
            } else if (OFMT == 2) {
                Ch[(size_t)row * ldc + (col >> 1)]       = packh2(v0, v1);
                Ch[(size_t)(row + 8) * ldc + (col >> 1)] = packh2(v2, v3);
            } else {    // OFMT 4: Q/K/V triple by global column
                unsigned* dst; int cc;
                if (col < 512)       { dst = Ch; cc = col; }
                else if (col < 1024) { dst = Cl; cc = col - 512; }
                else                 { dst = Cv; cc = col - 1024; }
                dst[(size_t)row * ldc + (cc >> 1)]       = packh2(v0, v1);
                dst[(size_t)(row + 8) * ldc + (cc >> 1)] = packh2(v2, v3);
            }
        }
    }
}

// ------------------------------ softmax ------------------------------------
__global__ void __launch_bounds__(256, 1)
softmax_rows(const float* __restrict__ S, unsigned* __restrict__ Sh)
{
    const int row = blockIdx.x;
    const float4* p = reinterpret_cast<const float4*>(S + (size_t)row * 8192);
    const int tid = threadIdx.x;

    float4 v[8];
    #pragma unroll
    for (int i = 0; i < 8; i++) v[i] = p[tid + 256 * i];

    float m = -3.402823e38f;
    #pragma unroll
    for (int i = 0; i < 8; i++)
        m = fmaxf(m, fmaxf(fmaxf(v[i].x, v[i].y), fmaxf(v[i].z, v[i].w)));

    __shared__ float red[8];
    #pragma unroll
    for (int o = 16; o; o >>= 1) m = fmaxf(m, __shfl_xor_sync(0xffffffffu, m, o));
    if ((tid & 31) == 0) red[tid >> 5] = m;
    __syncthreads();
    float mm = red[0];
    #pragma unroll
    for (int i = 1; i < 8; i++) mm = fmaxf(mm, red[i]);

    float s = 0.f;
    #pragma unroll
    for (int i = 0; i < 8; i++) {
        v[i].x = __expf(v[i].x - mm); s += v[i].x;
        v[i].y = __expf(v[i].y - mm); s += v[i].y;
        v[i].z = __expf(v[i].z - mm); s += v[i].z;
        v[i].w = __expf(v[i].w - mm); s += v[i].w;
    }
    #pragma unroll
    for (int o = 16; o; o >>= 1) s += __shfl_xor_sync(0xffffffffu, s, o);
    __syncthreads();
    if ((tid & 31) == 0) red[tid >> 5] = s;
    __syncthreads();
    float st = 0.f;
    #pragma unroll
    for (int i = 0; i < 8; i++) st += red[i];
    const float inv = 1.0f / st;

    unsigned* q = Sh + (size_t)row * 4096;
    #pragma unroll
    for (int i = 0; i < 8; i++) {
        uint2 w;
        w.x = packh2(v[i].x * inv, v[i].y * inv);
        w.y = packh2(v[i].z * inv, v[i].w * inv);
        *reinterpret_cast<uint2*>(q + (tid + 256 * i) * 2) = w;
    }
}

// ------------------------------ launcher -----------------------------------
extern "C" void kernel_launch(void* const* d_in, const int* in_sizes, int n_in,
                              void* d_out, int out_size)
{
    const float* za = (const float*)d_in[0];
    const float* zb = (const float*)d_in[1];
    const float* W1 = (const float*)d_in[2];
    const float* b1 = (const float*)d_in[3];
    const float* W2 = (const float*)d_in[4];
    const float* b2 = (const float*)d_in[5];
    const float* Wq = (const float*)d_in[6];
    const float* bq = (const float*)d_in[7];
    const float* Wk = (const float*)d_in[8];
    const float* bk = (const float*)d_in[9];
    const float* Wv = (const float*)d_in[10];
    const float* bv = (const float*)d_in[11];
    float* out = (float*)d_out;

    unsigned *Zh, *Zl, *Hh, *Ph, *Qh, *Kh, *Vh, *VT;
    unsigned *W1h, *W1l, *W2h, *W2l, *W3h, *W3l, *Sh;
    float *S, *bqkv;
    cudaGetSymbolAddress((void**)&Zh,  g_Zh);  cudaGetSymbolAddress((void**)&Zl,  g_Zl);
    cudaGetSymbolAddress((void**)&Hh,  g_Hh);  cudaGetSymbolAddress((void**)&Ph,  g_Ph);
    cudaGetSymbolAddress((void**)&Qh,  g_Qh);  cudaGetSymbolAddress((void**)&Kh,  g_Kh);
    cudaGetSymbolAddress((void**)&Vh,  g_Vh);  cudaGetSymbolAddress((void**)&VT,  g_VT);
    cudaGetSymbolAddress((void**)&W1h, g_W1h); cudaGetSymbolAddress((void**)&W1l, g_W1l);
    cudaGetSymbolAddress((void**)&W2h, g_W2h); cudaGetSymbolAddress((void**)&W2l, g_W2l);
    cudaGetSymbolAddress((void**)&W3h, g_W3h); cudaGetSymbolAddress((void**)&W3l, g_W3l);
    cudaGetSymbolAddress((void**)&S,   g_S);   cudaGetSymbolAddress((void**)&Sh,  g_Sh);
    cudaGetSymbolAddress((void**)&bqkv, g_bqkv);

    const int smem_p0 = 3 * 4 * (int)SLB;   // 99072 B
    const int smem_p2 = 3 * 3 * (int)SLB;   // 74304 B
    const int smem_p1 = 3 * 2 * (int)SLB;   // 49536 B
    cudaFuncSetAttribute(gemm_mm<2,0,2,0>, cudaFuncAttributeMaxDynamicSharedMemorySize, smem_p0);
    cudaFuncSetAttribute(gemm_mm<1,2,2,0>, cudaFuncAttributeMaxDynamicSharedMemorySize, smem_p2);
    cudaFuncSetAttribute(gemm_mm<1,2,4,0>, cudaFuncAttributeMaxDynamicSharedMemorySize, smem_p2);
    cudaFuncSetAttribute(gemm_mm<0,1,0,1>, cudaFuncAttributeMaxDynamicSharedMemorySize, smem_p1);
    cudaFuncSetAttribute(gemm_mm<0,1,0,2>, cudaFuncAttributeMaxDynamicSharedMemorySize, smem_p1);

    const dim3 blk(256);
    const dim3 tblk(32, 8);
    const float inv_scale = 1.0f / 16.0f;   // 1/sqrt(OUT/2)
    const size_t HALFW = (size_t)8192 * 256;   // half of Q/K/V word arrays
    const size_t HVTW  = (size_t)512 * 4096;   // half of VT

    // kernel launches 1-3 (capture slot #4 = L1 GEMM)
    split_in<<<16384, blk>>>(za, zb, Zh, Zl);
    transpose_split <<<dim3(32, 32), tblk>>>(W1, W1h, W1l, 1024, 1024);
    transpose_splith<<<dim3(16, 32), tblk>>>(W2, W2h, W2l, 1024, 512);

    // #4: proj L1: H = ELU(Z @ W1^T + b1), fp16 out   [16384 x 1024]
    gemm_mm<2,0,2,0><<<dim3(8, 128), blk, smem_p0>>>(
        Zh, Zl, W1h, W1l, b1, nullptr, Hh, nullptr, nullptr,
        16384, 1024, 1024, 512, 0, 1.f, nullptr, 0);

    // QKV weight concat transposes + bias concat
    transpose_splith<<<dim3(16, 16), tblk>>>(Wq, W3h,          W3l,          512, 512);
    transpose_splith<<<dim3(16, 16), tblk>>>(Wk, W3h + 131072, W3l + 131072, 512, 512);
    transpose_splith<<<dim3(16, 16), tblk>>>(Wv, W3h + 262144, W3l + 262144, 512, 512);
    cudaMemcpyAsync(bqkv,        bq, 512 * sizeof(float), cudaMemcpyDeviceToDevice);
    cudaMemcpyAsync(bqkv + 512,  bk, 512 * sizeof(float), cudaMemcpyDeviceToDevice);
    cudaMemcpyAsync(bqkv + 1024, bv, 512 * sizeof(float), cudaMemcpyDeviceToDevice);

    // proj L2: P = H @ W2^T + b2, fp16 out            [16384 x 512]
    gemm_mm<1,2,2,0><<<dim3(4, 128), blk, smem_p2>>>(
        Hh, nullptr, W2h, W2l, b2, nullptr, Ph, nullptr, nullptr,
        16384, 512, 1024, 256, 0, 1.f, nullptr, 0);

    // fused QKV: [Q|K|V] = P @ [Wq;Wk;Wv]^T + bqkv    [16384 x 1536]
    gemm_mm<1,2,4,0><<<dim3(12, 128), blk, smem_p2>>>(
        Ph, nullptr, W3h, W3l, bqkv, nullptr, Qh, Kh, Vh,
        16384, 1536, 512, 256, 0, 1.f, nullptr, 0);

    // V^T per half (fp16)
    transpose_h<<<dim3(16, 256), tblk>>>(Vh,         VT,        8192, 512);
    transpose_h<<<dim3(16, 256), tblk>>>(Vh + HALFW, VT + HVTW, 8192, 512);

    // fused scores: rows 0-8191 = Qa @ Kb^T, rows 8192-16383 = Qb @ Ka^T
    gemm_mm<0,1,0,1><<<dim3(64, 128), blk, smem_p1>>>(
        Qh, nullptr, Kh + HALFW, nullptr, nullptr, S, nullptr, nullptr, nullptr,
        16384, 8192, 512, 8192, 0, inv_scale, Kh, 0);
    // fused softmax over all 16384 rows
    softmax_rows<<<16384, blk>>>(S, Sh);
    // fused AV: rows 0-8191 -> out[:,0:512] (Vb), rows 8192-16383 -> out[:,512:1024] (Va)
    gemm_mm<0,1,0,2><<<dim3(4, 128), blk, smem_p1>>>(
        Sh, nullptr, VT + HVTW, nullptr, nullptr, out, nullptr, nullptr, nullptr,
        16384, 512, 8192, 1024, 0, 1.f, VT, 512);
}

// round 11
// speedup vs baseline: 1.7090x; 1.0100x over previous
#include <cuda_runtime.h>
#include <cuda_bf16.h>
#include <cuda_fp16.h>
#include <math.h>

// ---------------------------------------------------------------------------
// Contrast on legacy mma.sync m16n8k16 (baseline PTX; harness targets sm_103).
// L1: bf16 split-3 -> H fp16. L2/QKV: A fp16 x B fp16-split-2 -> fp16.
// Scores/AV: fp16 single, BK=64 3-stage ring. S fp16 end-to-end (in-place
// softmax). A/B directions fused per phase.
// ---------------------------------------------------------------------------

namespace {
constexpr int KBLK = 1032;             // u32 words per k16-block: 128*8 + 8 pad
}

// ------------------------------ scratch (u32 words) -------------------------
__device__ unsigned g_Zh [8388608], g_Zl [8388608];   // split(za|zb) 16384x1024 bf16
__device__ unsigned g_Hh [8388608];                   // H fp16   16384x1024
__device__ unsigned g_Ph [4194304];                   // P fp16   16384x512
__device__ unsigned g_Qh [4194304];                   // Q fp16
__device__ unsigned g_Kh [4194304];                   // K fp16
__device__ unsigned g_Vh [4194304];                   // V fp16
__device__ unsigned g_VT [4194304];                   // V^T fp16 per half [512,8192]
__device__ unsigned g_W1h[524288],  g_W1l[524288];    // W1^T bf16 hi/lo [1024,1024]
__device__ unsigned g_W2h[262144],  g_W2l[262144];    // W2^T fp16 hi/lo [512,1024]
__device__ unsigned g_W3h[393216],  g_W3l[393216];    // [Wq;Wk;Wv]^T fp16 hi/lo
__device__ float    g_bqkv[1536];                     // concat biases
__device__ unsigned g_Sh [67108864];                  // fp16 scores 16384x4096w (in-place softmax)

// ------------------------------ helpers ------------------------------------
__device__ __forceinline__ void mma_bf16(float* c, const unsigned* a,
                                         unsigned b0, unsigned b1) {
    asm volatile(
        "mma.sync.aligned.m16n8k16.row.col.f32.bf16.bf16.f32 "
        "{%0,%1,%2,%3}, {%4,%5,%6,%7}, {%8,%9}, {%0,%1,%2,%3};"
        : "+f"(c[0]), "+f"(c[1]), "+f"(c[2]), "+f"(c[3])
        : "r"(a[0]), "r"(a[1]), "r"(a[2]), "r"(a[3]), "r"(b0), "r"(b1));
}

__device__ __forceinline__ void mma_fp16(float* c, const unsigned* a,
                                         unsigned b0, unsigned b1) {
    asm volatile(
        "mma.sync.aligned.m16n8k16.row.col.f32.f16.f16.f32 "
        "{%0,%1,%2,%3}, {%4,%5,%6,%7}, {%8,%9}, {%0,%1,%2,%3};"
        : "+f"(c[0]), "+f"(c[1]), "+f"(c[2]), "+f"(c[3])
        : "r"(a[0]), "r"(a[1]), "r"(a[2]), "r"(a[3]), "r"(b0), "r"(b1));
}

__device__ __forceinline__ void ldsm_x4(unsigned* r, unsigned addr) {
    asm volatile("ldmatrix.sync.aligned.m8n8.x4.shared.b16 {%0,%1,%2,%3}, [%4];"
        : "=r"(r[0]), "=r"(r[1]), "=r"(r[2]), "=r"(r[3]) : "r"(addr));
}

__device__ __forceinline__ void cp16(unsigned dst, const void* src) {
    asm volatile("cp.async.cg.shared.global [%0], [%1], 16;" :: "r"(dst), "l"(src));
}

__device__ __forceinline__ unsigned smem_u32(const void* p) {
    unsigned a;
    asm("{ .reg .u64 t; cvta.to.shared.u64 t, %1; cvt.u32.u64 %0, t; }"
        : "=r"(a) : "l"(p));
    return a;
}

__device__ __forceinline__ void split2(float x, float y, unsigned& hi, unsigned& lo) {
    __nv_bfloat16 hx = __float2bfloat16(x);
    __nv_bfloat16 hy = __float2bfloat16(y);
    __nv_bfloat16 lx = __float2bfloat16(x - __bfloat162float(hx));
    __nv_bfloat16 ly = __float2bfloat16(y - __bfloat162float(hy));
    hi = ((unsigned)__bfloat16_as_ushort(hy) << 16) | (unsigned)__bfloat16_as_ushort(hx);
    lo = ((unsigned)__bfloat16_as_ushort(ly) << 16) | (unsigned)__bfloat16_as_ushort(lx);
}

__device__ __forceinline__ unsigned packh2(float x, float y) {
    __half2 h = __floats2half2_rn(x, y);
    return *reinterpret_cast<unsigned*>(&h);
}

// --------------------------- input split (bf16) -----------------------------
__global__ void __launch_bounds__(256, 8)
split_in(const float* __restrict__ za, const float* __restrict__ zb,
         unsigned* __restrict__ Zh, unsigned* __restrict__ Zl)
{
    const size_t t = (size_t)blockIdx.x * 256 + threadIdx.x;
    const size_t f = t * 4;
    const float4 v = (f < (size_t)8388608)
        ? *reinterpret_cast<const float4*>(za + f)
        : *reinterpret_cast<const float4*>(zb + (f - 8388608));
    uint2 h, l;
    split2(v.x, v.y, h.x, l.x);
    split2(v.z, v.w, h.y, l.y);
    *reinterpret_cast<uint2*>(Zh + t * 2) = h;
    *reinterpret_cast<uint2*>(Zl + t * 2) = l;
}

// ----------------------- weight transpose + bf16 split ----------------------
__global__ void __launch_bounds__(256, 4)
transpose_split(const float* __restrict__ src, unsigned* __restrict__ dh,
                unsigned* __restrict__ dl, int R, int C)
{
    __shared__ float t[32][33];
    const int bx = blockIdx.x * 32;
    const int by = blockIdx.y * 32;
    const int x  = bx + threadIdx.x;
    #pragma unroll
    for (int i = threadIdx.y; i < 32; i += 8)
        t[i][threadIdx.x] = src[(size_t)(by + i) * C + x];
    __syncthreads();
    const int xo = by + threadIdx.x;
    unsigned short* ph = reinterpret_cast<unsigned short*>(dh);
    unsigned short* pl = reinterpret_cast<unsigned short*>(dl);
    #pragma unroll
    for (int i = threadIdx.y; i < 32; i += 8) {
        const float v = t[threadIdx.x][i];
        const __nv_bfloat16 h = __float2bfloat16(v);
        const __nv_bfloat16 l = __float2bfloat16(v - __bfloat162float(h));
        ph[(size_t)(bx + i) * R + xo] = __bfloat16_as_ushort(h);
        pl[(size_t)(bx + i) * R + xo] = __bfloat16_as_ushort(l);
    }
}

// ----------------------- weight transpose + fp16 split ----------------------
__global__ void __launch_bounds__(256, 4)
transpose_splith(const float* __restrict__ src, unsigned* __restrict__ dh,
                 unsigned* __restrict__ dl, int R, int C)
{
    __shared__ float t[32][33];
    const int bx = blockIdx.x * 32;
    const int by = blockIdx.y * 32;
    const int x  = bx + threadIdx.x;
    #pragma unroll
    for (int i = threadIdx.y; i < 32; i += 8)
        t[i][threadIdx.x] = src[(size_t)(by + i) * C + x];
    __syncthreads();
    const int xo = by + threadIdx.x;
    unsigned short* ph = reinterpret_cast<unsigned short*>(dh);
    unsigned short* pl = reinterpret_cast<unsigned short*>(dl);
    #pragma unroll
    for (int i = threadIdx.y; i < 32; i += 8) {
        const float v = t[threadIdx.x][i];
        const __half h = __float2half_rn(v);
        const __half l = __float2half_rn(v - __half2float(h));
        ph[(size_t)(bx + i) * R + xo] = __half_as_ushort(h);
        pl[(size_t)(bx + i) * R + xo] = __half_as_ushort(l);
    }
}

// --------------------------- fp16 transpose --------------------------------
__global__ void __launch_bounds__(256, 4)
transpose_h(const unsigned* __restrict__ srcw, unsigned* __restrict__ dstw, int R, int C)
{
    __shared__ unsigned short t[32][34];
    const unsigned short* src = reinterpret_cast<const unsigned short*>(srcw);
    unsigned short* dst = reinterpret_cast<unsigned short*>(dstw);
    const int bx = blockIdx.x * 32;
    const int by = blockIdx.y * 32;
    const int x  = bx + threadIdx.x;
    #pragma unroll
    for (int i = threadIdx.y; i < 32; i += 8)
        t[i][threadIdx.x] = src[(size_t)(by + i) * C + x];
    __syncthreads();
    const int xo = by + threadIdx.x;
    #pragma unroll
    for (int i = threadIdx.y; i < 32; i += 8)
        dst[(size_t)(bx + i) * R + xo] = t[threadIdx.x][i];
}

// ------------------------------ GEMM ---------------------------------------
// C = epi(A[M,K] @ B[N,K]^T), operands pre-packed 16-bit (u32 pitch K/2).
// PREC 0: bf16 split-3. PREC 1: fp16 single. PREC 2: fp16 A-single x B-split-2.
// EPI 0: v*=scale ; EPI 1: v+=bias[col] ; EPI 2: elu(v+bias[col])
// OFMT 0: f32 Cf (+coff) ; OFMT 2: fp16 Ch ; OFMT 4: fp16 Q/K/V triple
// DUAL 0: none ; 1: second M-half uses Bh2 ; 2: second M-half Bh2+coff2, rows fold
// KT: k16-blocks per tile (BK = 16*KT)
template <int EPI, int PREC, int OFMT, int DUAL, int KT>
__global__ void __launch_bounds__(256, 2)
gemm_mm(const unsigned* __restrict__ Ah, const unsigned* __restrict__ Al,
        const unsigned* __restrict__ Bh, const unsigned* __restrict__ Bl,
        const float* __restrict__ bias,
        float* __restrict__ Cf, unsigned* __restrict__ Ch, unsigned* __restrict__ Cl,
        unsigned* __restrict__ Cv,
        int M, int N, int K, int ldc, int coff, float scale,
        const unsigned* __restrict__ Bh2, int coff2)
{
    extern __shared__ unsigned sm[];
    const unsigned tilesb = smem_u32(sm);
    constexpr unsigned SLBK  = (unsigned)KT * KBLK * 4u;   // bytes per half per tile
    constexpr unsigned YOFFB = (PREC == 0) ? 2u * SLBK : SLBK;
    constexpr unsigned BUFB  = ((PREC == 0) ? 4u : (PREC == 2) ? 3u : 2u) * SLBK;

    const int tid  = threadIdx.x;
    const int bm   = blockIdx.y * 128;
    const int bn   = blockIdx.x * 128;
    const int warp = tid >> 5;
    const int lane = tid & 31;
    const int wm   = (warp >> 2) * 64;
    const int wn   = (warp & 3) * 32;
    const int g    = lane >> 2;
    const int t2   = (lane & 3) * 2;

    const bool second = (DUAL != 0) && (bm >= (M >> 1));
    const unsigned* Bu = second ? Bh2 : Bh;
    const int co    = (DUAL == 2 && second) ? coff2 : coff;
    const int rfold = (DUAL == 2 && second) ? (M >> 1) : 0;

    // ldmatrix relative addresses (buffer 0, k-block 0)
    const int mi = lane >> 3;
    const int rl = (lane & 7) + ((mi & 1) << 3);
    const int kg = mi >> 1;
    unsigned relA[4], relB[2];
    #pragma unroll
    for (int mf = 0; mf < 4; mf++) {
        const int row = wm + mf * 16 + rl;
        const int w   = (kg << 2) ^ (((row >> 2) & 1) << 2);
        relA[mf] = tilesb + 4u * (unsigned)(row * 8 + w);
    }
    #pragma unroll
    for (int p = 0; p < 2; p++) {
        const int nf  = 2 * p + (mi >> 1);
        const int row = wn + nf * 8 + (lane & 7);
        const int w   = ((mi & 1) << 2) ^ (((row >> 2) & 1) << 2);
        relB[p] = tilesb + YOFFB + 4u * (unsigned)(row * 8 + w);
    }

    // staging mapping: 2*KT threads per 128-row, KT row-passes of 128/KT rows
    constexpr int TPR    = 2 * KT;
    constexpr int RSTRIDE = 128 / KT;                 // rows per pass
    constexpr unsigned PBYTES = (unsigned)RSTRIDE * 32u;  // smem bytes per pass
    const int srow  = tid / TPR;
    const int scol8 = (tid % TPR) * 8;
    const int sblk  = scol8 >> 4;
    const int sw0   = ((scol8 & 15) >> 1) ^ (((srow >> 2) & 1) * 4);
    const unsigned sidx0 = (unsigned)(sblk * KBLK + srow * 8 + sw0);
    const int kw = K >> 1;

    float acc[4][4][4];
    #pragma unroll
    for (int i = 0; i < 4; i++)
        #pragma unroll
        for (int j = 0; j < 4; j++)
            #pragma unroll
            for (int e = 0; e < 4; e++) acc[i][j][e] = 0.f;

    auto stage = [&](int kt, unsigned bufb) {
        const int w0 = kt * (8 * KT) + (scol8 >> 1);
        const unsigned d0 = tilesb + bufb + 4u * sidx0;
        #pragma unroll
        for (int i = 0; i < KT; i++) {
            const size_t ro = (size_t)(bm + srow + RSTRIDE * i) * kw + w0;
            cp16(d0 + PBYTES * i, Ah + ro);
            if (PREC == 0) cp16(d0 + PBYTES * i + SLBK, Al + ro);
        }
        #pragma unroll
        for (int i = 0; i < KT; i++) {
            const size_t ro = (size_t)(bn + srow + RSTRIDE * i) * kw + w0;
            cp16(d0 + PBYTES * i + YOFFB, Bu + ro);
            if (PREC == 0 || PREC == 2) cp16(d0 + PBYTES * i + YOFFB + SLBK, Bl + ro);
        }
        asm volatile("cp.async.commit_group;" ::: "memory");
    };

    auto compute = [&](unsigned bufb) {
        #pragma unroll
        for (int blk = 0; blk < KT; blk++) {
            const unsigned off = bufb + (unsigned)(blk * (KBLK * 4));
            unsigned a[4][4], b[2][4];
            #pragma unroll
            for (int mf = 0; mf < 4; mf++) ldsm_x4(a[mf], relA[mf] + off);
            #pragma unroll
            for (int p = 0; p < 2; p++)    ldsm_x4(b[p],  relB[p] + off);
            #pragma unroll
            for (int mf = 0; mf < 4; mf++)
                #pragma unroll
                for (int nf = 0; nf < 4; nf++) {
                    const unsigned b0 = b[nf >> 1][(nf & 1) * 2];
                    const unsigned b1 = b[nf >> 1][(nf & 1) * 2 + 1];
                    if (PREC == 0) mma_bf16(acc[mf][nf], a[mf], b0, b1);
                    else           mma_fp16(acc[mf][nf], a[mf], b0, b1);
                }
            if (PREC == 0 || PREC == 2) {
                unsigned bl2[2][4];
                #pragma unroll
                for (int p = 0; p < 2; p++) ldsm_x4(bl2[p], relB[p] + off + SLBK);
                #pragma unroll
                for (int mf = 0; mf < 4; mf++)
                    #pragma unroll
                    for (int nf = 0; nf < 4; nf++) {
                        const unsigned b0 = bl2[nf >> 1][(nf & 1) * 2];
                        const unsigned b1 = bl2[nf >> 1][(nf & 1) * 2 + 1];
                        if (PREC == 0) mma_bf16(acc[mf][nf], a[mf], b0, b1);
                        else           mma_fp16(acc[mf][nf], a[mf], b0, b1);
                    }
            }
            if (PREC == 0) {
                unsigned al2[4][4];
                #pragma unroll
                for (int mf = 0; mf < 4; mf++) ldsm_x4(al2[mf], relA[mf] + off + SLBK);
                #pragma unroll
                for (int mf = 0; mf < 4; mf++)
                    #pragma unroll
                    for (int nf = 0; nf < 4; nf++)
                        mma_bf16(acc[mf][nf], al2[mf],
                                 b[nf >> 1][(nf & 1) * 2], b[nf >> 1][(nf & 1) * 2 + 1]);
            }
        }
    };

    const int ktiles = K / (16 * KT);
    stage(0, 0u);
    stage(1, BUFB);
    for (int kt = 0; kt < ktiles; kt++) {
        if (kt + 1 < ktiles) asm volatile("cp.async.wait_group 1;" ::: "memory");
        else                 asm volatile("cp.async.wait_group 0;" ::: "memory");
        __syncthreads();
        if (kt + 2 < ktiles) stage(kt + 2, (unsigned)((kt + 2) % 3) * BUFB);
        compute((unsigned)(kt % 3) * BUFB);
    }

    // epilogue
    #pragma unroll
    for (int mf = 0; mf < 4; mf++) {
        #pragma unroll
        for (int nf = 0; nf < 4; nf++) {
            const int row = bm + wm + mf * 16 + g - rfold;
            const int col = bn + wn + nf * 8 + t2;
            float v0 = acc[mf][nf][0], v1 = acc[mf][nf][1];
            float v2 = acc[mf][nf][2], v3 = acc[mf][nf][3];
            if (EPI == 0) {
                v0 *= scale; v1 *= scale; v2 *= scale; v3 *= scale;
            } else {
                const float bb0 = bias[col], bb1 = bias[col + 1];
                v0 += bb0; v1 += bb1; v2 += bb0; v3 += bb1;
                if (EPI == 2) {
                    v0 = v0 > 0.f ? v0 : __expf(v0) - 1.f;
                    v1 = v1 > 0.f ? v1 : __expf(v1) - 1.f;
                    v2 = v2 > 0.f ? v2 : __expf(v2) - 1.f;
                    v3 = v3 > 0.f ? v3 : __expf(v3) - 1.f;
                }
            }
            if (OFMT == 0) {
                *reinterpret_cast<float2*>(Cf + (size_t)row * ldc + co + col)       = make_float2(v0, v1);
                *reinterpret_cast<float2*>(Cf + (size_t)(row + 8) * ldc + co + col) = make_float2(v2, v3);
            } else if (OFMT == 2) {
                Ch[(size_t)row * ldc + (col >> 1)]       = packh2(v0, v1);
                Ch[(size_t)(row + 8) * ldc + (col >> 1)] = packh2(v2, v3);
            } else {    // OFMT 4: Q/K/V triple by global column
                unsigned* dst; int cc;
                if (col < 512)       { dst = Ch; cc = col; }
                else if (col < 1024) { dst = Cl; cc = col - 512; }
                else                 { dst = Cv; cc = col - 1024; }
                dst[(size_t)row * ldc + (cc >> 1)]       = packh2(v0, v1);
                dst[(size_t)(row + 8) * ldc + (cc >> 1)] = packh2(v2, v3);
            }
        }
    }
}

// ------------------------- softmax (fp16 in-place) --------------------------
__global__ void __launch_bounds__(256, 1)
softmax_h(unsigned* __restrict__ Sh)
{
    const int row = blockIdx.x;
    uint4* p = reinterpret_cast<uint4*>(Sh + (size_t)row * 4096);
    const int tid = threadIdx.x;

    uint4 w[4];
    #pragma unroll
    for (int i = 0; i < 4; i++) w[i] = p[tid + 256 * i];

    float f[32];
    #pragma unroll
    for (int i = 0; i < 4; i++) {
        const unsigned* u = reinterpret_cast<const unsigned*>(&w[i]);
        #pragma unroll
        for (int j = 0; j < 4; j++) {
            float2 d = __half22float2(*reinterpret_cast<const __half2*>(&u[j]));
            f[i * 8 + j * 2]     = d.x;
            f[i * 8 + j * 2 + 1] = d.y;
        }
    }

    float m = -3.402823e38f;
    #pragma unroll
    for (int i = 0; i < 32; i++) m = fmaxf(m, f[i]);

    __shared__ float red[8];
    #pragma unroll
    for (int o = 16; o; o >>= 1) m = fmaxf(m, __shfl_xor_sync(0xffffffffu, m, o));
    if ((tid & 31) == 0) red[tid >> 5] = m;
    __syncthreads();
    float mm = red[0];
    #pragma unroll
    for (int i = 1; i < 8; i++) mm = fmaxf(mm, red[i]);

    float s = 0.f;
    #pragma unroll
    for (int i = 0; i < 32; i++) { f[i] = __expf(f[i] - mm); s += f[i]; }
    #pragma unroll
    for (int o = 16; o; o >>= 1) s += __shfl_xor_sync(0xffffffffu, s, o);
    __syncthreads();
    if ((tid & 31) == 0) red[tid >> 5] = s;
    __syncthreads();
    float st = 0.f;
    #pragma unroll
    for (int i = 0; i < 8; i++) st += red[i];
    const float inv = 1.0f / st;

    #pragma unroll
    for (int i = 0; i < 4; i++) {
        unsigned* u = reinterpret_cast<unsigned*>(&w[i]);
        #pragma unroll
        for (int j = 0; j < 4; j++)
            u[j] = packh2(f[i * 8 + j * 2] * inv, f[i * 8 + j * 2 + 1] * inv);
    }
    #pragma unroll
    for (int i = 0; i < 4; i++) p[tid + 256 * i] = w[i];
}

// ------------------------------ launcher -----------------------------------
extern "C" void kernel_launch(void* const* d_in, const int* in_sizes, int n_in,
                              void* d_out, int out_size)
{
    const float* za = (const float*)d_in[0];
    const float* zb = (const float*)d_in[1];
    const float* W1 = (const float*)d_in[2];
    const float* b1 = (const float*)d_in[3];
    const float* W2 = (const float*)d_in[4];
    const float* b2 = (const float*)d_in[5];
    const float* Wq = (const float*)d_in[6];
    const float* bq = (const float*)d_in[7];
    const float* Wk = (const float*)d_in[8];
    const float* bk = (const float*)d_in[9];
    const float* Wv = (const float*)d_in[10];
    const float* bv = (const float*)d_in[11];
    float* out = (float*)d_out;

    unsigned *Zh, *Zl, *Hh, *Ph, *Qh, *Kh, *Vh, *VT;
    unsigned *W1h, *W1l, *W2h, *W2l, *W3h, *W3l, *Sh;
    float *bqkv;
    cudaGetSymbolAddress((void**)&Zh,  g_Zh);  cudaGetSymbolAddress((void**)&Zl,  g_Zl);
    cudaGetSymbolAddress((void**)&Hh,  g_Hh);  cudaGetSymbolAddress((void**)&Ph,  g_Ph);
    cudaGetSymbolAddress((void**)&Qh,  g_Qh);  cudaGetSymbolAddress((void**)&Kh,  g_Kh);
    cudaGetSymbolAddress((void**)&Vh,  g_Vh);  cudaGetSymbolAddress((void**)&VT,  g_VT);
    cudaGetSymbolAddress((void**)&W1h, g_W1h); cudaGetSymbolAddress((void**)&W1l, g_W1l);
    cudaGetSymbolAddress((void**)&W2h, g_W2h); cudaGetSymbolAddress((void**)&W2l, g_W2l);
    cudaGetSymbolAddress((void**)&W3h, g_W3h); cudaGetSymbolAddress((void**)&W3l, g_W3l);
    cudaGetSymbolAddress((void**)&Sh,  g_Sh);  cudaGetSymbolAddress((void**)&bqkv, g_bqkv);

    const int smem_p0   = 3 * 4 * (2 * KBLK * 4);   // 99072 B  (split-3, KT=2)
    const int smem_p2   = 3 * 3 * (2 * KBLK * 4);   // 74304 B  (fp16 split-2, KT=2)
    const int smem_p1k4 = 3 * 2 * (4 * KBLK * 4);   // 99072 B  (fp16 single, KT=4)
    cudaFuncSetAttribute(gemm_mm<2,0,2,0,2>, cudaFuncAttributeMaxDynamicSharedMemorySize, smem_p0);
    cudaFuncSetAttribute(gemm_mm<1,2,2,0,2>, cudaFuncAttributeMaxDynamicSharedMemorySize, smem_p2);
    cudaFuncSetAttribute(gemm_mm<1,2,4,0,2>, cudaFuncAttributeMaxDynamicSharedMemorySize, smem_p2);
    cudaFuncSetAttribute(gemm_mm<0,1,2,1,4>, cudaFuncAttributeMaxDynamicSharedMemorySize, smem_p1k4);
    cudaFuncSetAttribute(gemm_mm<0,1,0,2,4>, cudaFuncAttributeMaxDynamicSharedMemorySize, smem_p1k4);

    const dim3 blk(256);
    const dim3 tblk(32, 8);
    const float inv_scale = 1.0f / 16.0f;   // 1/sqrt(OUT/2)
    const size_t HALFW = (size_t)8192 * 256;   // half of Q/K/V word arrays
    const size_t HVTW  = (size_t)512 * 4096;   // half of VT

    // kernel launches 1-3 (capture slot #4 = L1 GEMM, control)
    split_in<<<16384, blk>>>(za, zb, Zh, Zl);
    transpose_split <<<dim3(32, 32), tblk>>>(W1, W1h, W1l, 1024, 1024);
    transpose_splith<<<dim3(16, 32), tblk>>>(W2, W2h, W2l, 1024, 512);

    // #4: proj L1: H = ELU(Z @ W1^T + b1), fp16 out   [16384 x 1024]
    gemm_mm<2,0,2,0,2><<<dim3(8, 128), blk, smem_p0>>>(
        Zh, Zl, W1h, W1l, b1, nullptr, Hh, nullptr, nullptr,
        16384, 1024, 1024, 512, 0, 1.f, nullptr, 0);

    // QKV weight concat transposes + bias concat
    transpose_splith<<<dim3(16, 16), tblk>>>(Wq, W3h,          W3l,          512, 512);
    transpose_splith<<<dim3(16, 16), tblk>>>(Wk, W3h + 131072, W3l + 131072, 512, 512);
    transpose_splith<<<dim3(16, 16), tblk>>>(Wv, W3h + 262144, W3l + 262144, 512, 512);
    cudaMemcpyAsync(bqkv,        bq, 512 * sizeof(float), cudaMemcpyDeviceToDevice);
    cudaMemcpyAsync(bqkv + 512,  bk, 512 * sizeof(float), cudaMemcpyDeviceToDevice);
    cudaMemcpyAsync(bqkv + 1024, bv, 512 * sizeof(float), cudaMemcpyDeviceToDevice);

    // proj L2: P = H @ W2^T + b2, fp16 out            [16384 x 512]
    gemm_mm<1,2,2,0,2><<<dim3(4, 128), blk, smem_p2>>>(
        Hh, nullptr, W2h, W2l, b2, nullptr, Ph, nullptr, nullptr,
        16384, 512, 1024, 256, 0, 1.f, nullptr, 0);

    // fused QKV: [Q|K|V] = P @ [Wq;Wk;Wv]^T + bqkv    [16384 x 1536]
    gemm_mm<1,2,4,0,2><<<dim3(12, 128), blk, smem_p2>>>(
        Ph, nullptr, W3h, W3l, bqkv, nullptr, Qh, Kh, Vh,
        16384, 1536, 512, 256, 0, 1.f, nullptr, 0);

    // V^T per half (fp16)
    transpose_h<<<dim3(16, 256), tblk>>>(Vh,         VT,        8192, 512);
    transpose_h<<<dim3(16, 256), tblk>>>(Vh + HALFW, VT + HVTW, 8192, 512);

    // fused scores (fp16 out): rows 0-8191 = Qa@Kb^T/16, rows 8192.. = Qb@Ka^T/16
    gemm_mm<0,1,2,1,4><<<dim3(64, 128), blk, smem_p1k4>>>(
        Qh, nullptr, Kh + HALFW, nullptr, nullptr, nullptr, Sh, nullptr, nullptr,
        16384, 8192, 512, 4096, 0, inv_scale, Kh, 0);
    // fused in-place fp16 softmax over all 16384 rows
    softmax_h<<<16384, blk>>>(Sh);
    // fused AV: rows 0-8191 -> out[:,0:512] (Vb), rows 8192-16383 -> out[:,512:1024] (Va)
    gemm_mm<0,1,0,2,4><<<dim3(4, 128), blk, smem_p1k4>>>(
        Sh, nullptr, VT + HVTW, nullptr, nullptr, out, nullptr, nullptr, nullptr,
        16384, 512, 8192, 1024, 0, 1.f, VT, 512);
}

// round 12
// speedup vs baseline: 1.7911x; 1.0480x over previous
#include <cuda_runtime.h>
#include <cuda_bf16.h>
#include <cuda_fp16.h>
#include <math.h>

// ---------------------------------------------------------------------------
// Contrast on legacy mma.sync m16n8k16 (baseline PTX; harness targets sm_103).
// All activations fp16; all weights fp16 hi/lo split-2 (near-exact GEMM arith).
// Scores/AV: fp16 single, BK=64 3-stage ring. S fp16 end-to-end, in-place
// softmax (scale folded into exp). A/B directions fused per phase.
// ---------------------------------------------------------------------------

namespace {
constexpr int KBLK = 1032;             // u32 words per k16-block: 128*8 + 8 pad
}

// ------------------------------ scratch (u32 words) -------------------------
__device__ unsigned g_Zh [8388608];                   // (za|zb) fp16 16384x1024
__device__ unsigned g_Hh [8388608];                   // H fp16   16384x1024
__device__ unsigned g_Ph [4194304];                   // P fp16   16384x512
__device__ unsigned g_Qh [4194304];                   // Q fp16
__device__ unsigned g_Kh [4194304];                   // K fp16
__device__ unsigned g_Vh [4194304];                   // V fp16
__device__ unsigned g_VT [4194304];                   // V^T fp16 per half [512,8192]
__device__ unsigned g_W1h[524288],  g_W1l[524288];    // W1^T fp16 hi/lo [1024,1024]
__device__ unsigned g_W2h[262144],  g_W2l[262144];    // W2^T fp16 hi/lo [512,1024]
__device__ unsigned g_W3h[393216],  g_W3l[393216];    // [Wq;Wk;Wv]^T fp16 hi/lo
__device__ float    g_bqkv[1536];                     // concat biases
__device__ unsigned g_Sh [67108864];                  // fp16 scores 16384x4096w

// ------------------------------ helpers ------------------------------------
__device__ __forceinline__ void mma_fp16(float* c, const unsigned* a,
                                         unsigned b0, unsigned b1) {
    asm volatile(
        "mma.sync.aligned.m16n8k16.row.col.f32.f16.f16.f32 "
        "{%0,%1,%2,%3}, {%4,%5,%6,%7}, {%8,%9}, {%0,%1,%2,%3};"
        : "+f"(c[0]), "+f"(c[1]), "+f"(c[2]), "+f"(c[3])
        : "r"(a[0]), "r"(a[1]), "r"(a[2]), "r"(a[3]), "r"(b0), "r"(b1));
}

__device__ __forceinline__ void ldsm_x4(unsigned* r, unsigned addr) {
    asm volatile("ldmatrix.sync.aligned.m8n8.x4.shared.b16 {%0,%1,%2,%3}, [%4];"
        : "=r"(r[0]), "=r"(r[1]), "=r"(r[2]), "=r"(r[3]) : "r"(addr));
}

__device__ __forceinline__ void cp16(unsigned dst, const void* src) {
    asm volatile("cp.async.cg.shared.global [%0], [%1], 16;" :: "r"(dst), "l"(src));
}

__device__ __forceinline__ unsigned smem_u32(const void* p) {
    unsigned a;
    asm("{ .reg .u64 t; cvta.to.shared.u64 t, %1; cvt.u32.u64 %0, t; }"
        : "=r"(a) : "l"(p));
    return a;
}

__device__ __forceinline__ unsigned packh2(float x, float y) {
    __half2 h = __floats2half2_rn(x, y);
    return *reinterpret_cast<unsigned*>(&h);
}

// --------------------------- input pack (fp16) ------------------------------
__global__ void __launch_bounds__(256, 8)
pack_in(const float* __restrict__ za, const float* __restrict__ zb,
        unsigned* __restrict__ Zh)
{
    const size_t t = (size_t)blockIdx.x * 256 + threadIdx.x;
    const size_t f = t * 4;
    const float4 v = (f < (size_t)8388608)
        ? *reinterpret_cast<const float4*>(za + f)
        : *reinterpret_cast<const float4*>(zb + (f - 8388608));
    *reinterpret_cast<uint2*>(Zh + t * 2) =
        make_uint2(packh2(v.x, v.y), packh2(v.z, v.w));
}

// ----------------------- weight transpose + fp16 split ----------------------
__global__ void __launch_bounds__(256, 4)
transpose_splith(const float* __restrict__ src, unsigned* __restrict__ dh,
                 unsigned* __restrict__ dl, int R, int C)
{
    __shared__ float t[32][33];
    const int bx = blockIdx.x * 32;
    const int by = blockIdx.y * 32;
    const int x  = bx + threadIdx.x;
    #pragma unroll
    for (int i = threadIdx.y; i < 32; i += 8)
        t[i][threadIdx.x] = src[(size_t)(by + i) * C + x];
    __syncthreads();
    const int xo = by + threadIdx.x;
    unsigned short* ph = reinterpret_cast<unsigned short*>(dh);
    unsigned short* pl = reinterpret_cast<unsigned short*>(dl);
    #pragma unroll
    for (int i = threadIdx.y; i < 32; i += 8) {
        const float v = t[threadIdx.x][i];
        const __half h = __float2half_rn(v);
        const __half l = __float2half_rn(v - __half2float(h));
        ph[(size_t)(bx + i) * R + xo] = __half_as_ushort(h);
        pl[(size_t)(bx + i) * R + xo] = __half_as_ushort(l);
    }
}

// --------------------------- fp16 transpose --------------------------------
__global__ void __launch_bounds__(256, 4)
transpose_h(const unsigned* __restrict__ srcw, unsigned* __restrict__ dstw, int R, int C)
{
    __shared__ unsigned short t[32][34];
    const unsigned short* src = reinterpret_cast<const unsigned short*>(srcw);
    unsigned short* dst = reinterpret_cast<unsigned short*>(dstw);
    const int bx = blockIdx.x * 32;
    const int by = blockIdx.y * 32;
    const int x  = bx + threadIdx.x;
    #pragma unroll
    for (int i = threadIdx.y; i < 32; i += 8)
        t[i][threadIdx.x] = src[(size_t)(by + i) * C + x];
    __syncthreads();
    const int xo = by + threadIdx.x;
    #pragma unroll
    for (int i = threadIdx.y; i < 32; i += 8)
        dst[(size_t)(bx + i) * R + xo] = t[threadIdx.x][i];
}

// ------------------------------ GEMM ---------------------------------------
// C = epi(A[M,K] @ B[N,K]^T), operands fp16-packed (u32 pitch K/2).
// PREC 1: fp16 single (Ah x Bh). PREC 2: fp16 A-single x B-split-2.
// EPI 0: v*=scale ; EPI 1: v+=bias[col] ; EPI 2: elu(v+bias[col])
// OFMT 0: f32 Cf (+coff) ; OFMT 2: fp16 Ch ; OFMT 4: fp16 Q/K/V triple
// DUAL 0: none ; 1: second M-half uses Bh2 ; 2: second M-half Bh2+coff2, rows fold
// KT: k16-blocks per tile (BK = 16*KT)
template <int EPI, int PREC, int OFMT, int DUAL, int KT>
__global__ void __launch_bounds__(256, 2)
gemm_mm(const unsigned* __restrict__ Ah,
        const unsigned* __restrict__ Bh, const unsigned* __restrict__ Bl,
        const float* __restrict__ bias,
        float* __restrict__ Cf, unsigned* __restrict__ Ch, unsigned* __restrict__ Cl,
        unsigned* __restrict__ Cv,
        int M, int N, int K, int ldc, int coff, float scale,
        const unsigned* __restrict__ Bh2, int coff2)
{
    extern __shared__ unsigned sm[];
    const unsigned tilesb = smem_u32(sm);
    constexpr unsigned SLBK  = (unsigned)KT * KBLK * 4u;   // bytes per half per tile
    constexpr unsigned YOFFB = SLBK;
    constexpr unsigned BUFB  = ((PREC == 2) ? 3u : 2u) * SLBK;

    const int tid  = threadIdx.x;
    const int bm   = blockIdx.y * 128;
    const int bn   = blockIdx.x * 128;
    const int warp = tid >> 5;
    const int lane = tid & 31;
    const int wm   = (warp >> 2) * 64;
    const int wn   = (warp & 3) * 32;
    const int g    = lane >> 2;
    const int t2   = (lane & 3) * 2;

    const bool second = (DUAL != 0) && (bm >= (M >> 1));
    const unsigned* Bu = second ? Bh2 : Bh;
    const int co    = (DUAL == 2 && second) ? coff2 : coff;
    const int rfold = (DUAL == 2 && second) ? (M >> 1) : 0;

    // ldmatrix relative addresses (buffer 0, k-block 0)
    const int mi = lane >> 3;
    const int rl = (lane & 7) + ((mi & 1) << 3);
    const int kg = mi >> 1;
    unsigned relA[4], relB[2];
    #pragma unroll
    for (int mf = 0; mf < 4; mf++) {
        const int row = wm + mf * 16 + rl;
        const int w   = (kg << 2) ^ (((row >> 2) & 1) << 2);
        relA[mf] = tilesb + 4u * (unsigned)(row * 8 + w);
    }
    #pragma unroll
    for (int p = 0; p < 2; p++) {
        const int nf  = 2 * p + (mi >> 1);
        const int row = wn + nf * 8 + (lane & 7);
        const int w   = ((mi & 1) << 2) ^ (((row >> 2) & 1) << 2);
        relB[p] = tilesb + YOFFB + 4u * (unsigned)(row * 8 + w);
    }

    // staging mapping: 2*KT threads per 128-row, KT row-passes
    constexpr int TPR     = 2 * KT;
    constexpr int RSTRIDE = 128 / KT;
    constexpr unsigned PBYTES = (unsigned)RSTRIDE * 32u;
    const int srow  = tid / TPR;
    const int scol8 = (tid % TPR) * 8;
    const int sblk  = scol8 >> 4;
    const int sw0   = ((scol8 & 15) >> 1) ^ (((srow >> 2) & 1) * 4);
    const unsigned sidx0 = (unsigned)(sblk * KBLK + srow * 8 + sw0);
    const int kw = K >> 1;

    float acc[4][4][4];
    #pragma unroll
    for (int i = 0; i < 4; i++)
        #pragma unroll
        for (int j = 0; j < 4; j++)
            #pragma unroll
            for (int e = 0; e < 4; e++) acc[i][j][e] = 0.f;

    auto stage = [&](int kt, unsigned bufb) {
        const int w0 = kt * (8 * KT) + (scol8 >> 1);
        const unsigned d0 = tilesb + bufb + 4u * sidx0;
        #pragma unroll
        for (int i = 0; i < KT; i++) {
            const size_t ro = (size_t)(bm + srow + RSTRIDE * i) * kw + w0;
            cp16(d0 + PBYTES * i, Ah + ro);
        }
        #pragma unroll
        for (int i = 0; i < KT; i++) {
            const size_t ro = (size_t)(bn + srow + RSTRIDE * i) * kw + w0;
            cp16(d0 + PBYTES * i + YOFFB, Bu + ro);
            if (PREC == 2) cp16(d0 + PBYTES * i + YOFFB + SLBK, Bl + ro);
        }
        asm volatile("cp.async.commit_group;" ::: "memory");
    };

    auto compute = [&](unsigned bufb) {
        #pragma unroll
        for (int blk = 0; blk < KT; blk++) {
            const unsigned off = bufb + (unsigned)(blk * (KBLK * 4));
            unsigned a[4][4], b[2][4];
            #pragma unroll
            for (int mf = 0; mf < 4; mf++) ldsm_x4(a[mf], relA[mf] + off);
            #pragma unroll
            for (int p = 0; p < 2; p++)    ldsm_x4(b[p],  relB[p] + off);
            #pragma unroll
            for (int mf = 0; mf < 4; mf++)
                #pragma unroll
                for (int nf = 0; nf < 4; nf++)
                    mma_fp16(acc[mf][nf], a[mf],
                             b[nf >> 1][(nf & 1) * 2], b[nf >> 1][(nf & 1) * 2 + 1]);
            if (PREC == 2) {
                unsigned bl2[2][4];
                #pragma unroll
                for (int p = 0; p < 2; p++) ldsm_x4(bl2[p], relB[p] + off + SLBK);
                #pragma unroll
                for (int mf = 0; mf < 4; mf++)
                    #pragma unroll
                    for (int nf = 0; nf < 4; nf++)
                        mma_fp16(acc[mf][nf], a[mf],
                                 bl2[nf >> 1][(nf & 1) * 2], bl2[nf >> 1][(nf & 1) * 2 + 1]);
            }
        }
    };

    const int ktiles = K / (16 * KT);
    stage(0, 0u);
    stage(1, BUFB);
    for (int kt = 0; kt < ktiles; kt++) {
        if (kt + 1 < ktiles) asm volatile("cp.async.wait_group 1;" ::: "memory");
        else                 asm volatile("cp.async.wait_group 0;" ::: "memory");
        __syncthreads();
        if (kt + 2 < ktiles) stage(kt + 2, (unsigned)((kt + 2) % 3) * BUFB);
        compute((unsigned)(kt % 3) * BUFB);
    }

    // epilogue
    #pragma unroll
    for (int mf = 0; mf < 4; mf++) {
        #pragma unroll
        for (int nf = 0; nf < 4; nf++) {
            const int row = bm + wm + mf * 16 + g - rfold;
            const int col = bn + wn + nf * 8 + t2;
            float v0 = acc[mf][nf][0], v1 = acc[mf][nf][1];
            float v2 = acc[mf][nf][2], v3 = acc[mf][nf][3];
            if (EPI == 0) {
                v0 *= scale; v1 *= scale; v2 *= scale; v3 *= scale;
            } else {
                const float bb0 = bias[col], bb1 = bias[col + 1];
                v0 += bb0; v1 += bb1; v2 += bb0; v3 += bb1;
                if (EPI == 2) {
                    v0 = v0 > 0.f ? v0 : __expf(v0) - 1.f;
                    v1 = v1 > 0.f ? v1 : __expf(v1) - 1.f;
                    v2 = v2 > 0.f ? v2 : __expf(v2) - 1.f;
                    v3 = v3 > 0.f ? v3 : __expf(v3) - 1.f;
                }
            }
            if (OFMT == 0) {
                *reinterpret_cast<float2*>(Cf + (size_t)row * ldc + co + col)       = make_float2(v0, v1);
                *reinterpret_cast<float2*>(Cf + (size_t)(row + 8) * ldc + co + col) = make_float2(v2, v3);
            } else if (OFMT == 2) {
                Ch[(size_t)row * ldc + (col >> 1)]       = packh2(v0, v1);
                Ch[(size_t)(row + 8) * ldc + (col >> 1)] = packh2(v2, v3);
            } else {    // OFMT 4: Q/K/V triple by global column
                unsigned* dst; int cc;
                if (col < 512)       { dst = Ch; cc = col; }
                else if (col < 1024) { dst = Cl; cc = col - 512; }
                else                 { dst = Cv; cc = col - 1024; }
                dst[(size_t)row * ldc + (cc >> 1)]       = packh2(v0, v1);
                dst[(size_t)(row + 8) * ldc + (cc >> 1)] = packh2(v2, v3);
            }
        }
    }
}

// ------------------- softmax (fp16 in-place, folded scale) ------------------
__global__ void __launch_bounds__(256, 1)
softmax_h(unsigned* __restrict__ Sh, float inv_scale)
{
    const int row = blockIdx.x;
    uint4* p = reinterpret_cast<uint4*>(Sh + (size_t)row * 4096);
    const int tid = threadIdx.x;

    uint4 w[4];
    #pragma unroll
    for (int i = 0; i < 4; i++) w[i] = p[tid + 256 * i];

    float f[32];
    #pragma unroll
    for (int i = 0; i < 4; i++) {
        const unsigned* u = reinterpret_cast<const unsigned*>(&w[i]);
        #pragma unroll
        for (int j = 0; j < 4; j++) {
            float2 d = __half22float2(*reinterpret_cast<const __half2*>(&u[j]));
            f[i * 8 + j * 2]     = d.x;
            f[i * 8 + j * 2 + 1] = d.y;
        }
    }

    float m = -3.402823e38f;
    #pragma unroll
    for (int i = 0; i < 32; i++) m = fmaxf(m, f[i]);

    __shared__ float red[8];
    #pragma unroll
    for (int o = 16; o; o >>= 1) m = fmaxf(m, __shfl_xor_sync(0xffffffffu, m, o));
    if ((tid & 31) == 0) red[tid >> 5] = m;
    __syncthreads();
    float mm = red[0];
    #pragma unroll
    for (int i = 1; i < 8; i++) mm = fmaxf(mm, red[i]);

    float s = 0.f;
    #pragma unroll
    for (int i = 0; i < 32; i++) { f[i] = __expf((f[i] - mm) * inv_scale); s += f[i]; }
    #pragma unroll
    for (int o = 16; o; o >>= 1) s += __shfl_xor_sync(0xffffffffu, s, o);
    __syncthreads();
    if ((tid & 31) == 0) red[tid >> 5] = s;
    __syncthreads();
    float st = 0.f;
    #pragma unroll
    for (int i = 0; i < 8; i++) st += red[i];
    const float inv = 1.0f / st;

    #pragma unroll
    for (int i = 0; i < 4; i++) {
        unsigned* u = reinterpret_cast<unsigned*>(&w[i]);
        #pragma unroll
        for (int j = 0; j < 4; j++)
            u[j] = packh2(f[i * 8 + j * 2] * inv, f[i * 8 + j * 2 + 1] * inv);
    }
    #pragma unroll
    for (int i = 0; i < 4; i++) p[tid + 256 * i] = w[i];
}

// ------------------------------ launcher -----------------------------------
extern "C" void kernel_launch(void* const* d_in, const int* in_sizes, int n_in,
                              void* d_out, int out_size)
{
    const float* za = (const float*)d_in[0];
    const float* zb = (const float*)d_in[1];
    const float* W1 = (const float*)d_in[2];
    const float* b1 = (const float*)d_in[3];
    const float* W2 = (const float*)d_in[4];
    const float* b2 = (const float*)d_in[5];
    const float* Wq = (const float*)d_in[6];
    const float* bq = (const float*)d_in[7];
    const float* Wk = (const float*)d_in[8];
    const float* bk = (const float*)d_in[9];
    const float* Wv = (const float*)d_in[10];
    const float* bv = (const float*)d_in[11];
    float* out = (float*)d_out;

    unsigned *Zh, *Hh, *Ph, *Qh, *Kh, *Vh, *VT;
    unsigned *W1h, *W1l, *W2h, *W2l, *W3h, *W3l, *Sh;
    float *bqkv;
    cudaGetSymbolAddress((void**)&Zh,  g_Zh);
    cudaGetSymbolAddress((void**)&Hh,  g_Hh);  cudaGetSymbolAddress((void**)&Ph,  g_Ph);
    cudaGetSymbolAddress((void**)&Qh,  g_Qh);  cudaGetSymbolAddress((void**)&Kh,  g_Kh);
    cudaGetSymbolAddress((void**)&Vh,  g_Vh);  cudaGetSymbolAddress((void**)&VT,  g_VT);
    cudaGetSymbolAddress((void**)&W1h, g_W1h); cudaGetSymbolAddress((void**)&W1l, g_W1l);
    cudaGetSymbolAddress((void**)&W2h, g_W2h); cudaGetSymbolAddress((void**)&W2l, g_W2l);
    cudaGetSymbolAddress((void**)&W3h, g_W3h); cudaGetSymbolAddress((void**)&W3l, g_W3l);
    cudaGetSymbolAddress((void**)&Sh,  g_Sh);  cudaGetSymbolAddress((void**)&bqkv, g_bqkv);

    const int smem_p2   = 3 * 3 * (2 * KBLK * 4);   // 74304 B  (fp16 split-2, KT=2)
    const int smem_p1k4 = 3 * 2 * (4 * KBLK * 4);   // 99072 B  (fp16 single, KT=4)
    cudaFuncSetAttribute(gemm_mm<2,2,2,0,2>, cudaFuncAttributeMaxDynamicSharedMemorySize, smem_p2);
    cudaFuncSetAttribute(gemm_mm<1,2,2,0,2>, cudaFuncAttributeMaxDynamicSharedMemorySize, smem_p2);
    cudaFuncSetAttribute(gemm_mm<1,2,4,0,2>, cudaFuncAttributeMaxDynamicSharedMemorySize, smem_p2);
    cudaFuncSetAttribute(gemm_mm<0,1,2,1,4>, cudaFuncAttributeMaxDynamicSharedMemorySize, smem_p1k4);
    cudaFuncSetAttribute(gemm_mm<0,1,0,2,4>, cudaFuncAttributeMaxDynamicSharedMemorySize, smem_p1k4);

    const dim3 blk(256);
    const dim3 tblk(32, 8);
    const float inv_scale = 1.0f / 16.0f;   // 1/sqrt(OUT/2)
    const size_t HALFW = (size_t)8192 * 256;   // half of Q/K/V word arrays
    const size_t HVTW  = (size_t)512 * 4096;   // half of VT

    // kernel launches 1-3 (capture slot #4 = L1 GEMM)
    pack_in<<<16384, blk>>>(za, zb, Zh);
    transpose_splith<<<dim3(32, 32), tblk>>>(W1, W1h, W1l, 1024, 1024);
    transpose_splith<<<dim3(16, 32), tblk>>>(W2, W2h, W2l, 1024, 512);

    // #4: proj L1: H = ELU(Z @ W1^T + b1), fp16 out   [16384 x 1024]
    gemm_mm<2,2,2,0,2><<<dim3(8, 128), blk, smem_p2>>>(
        Zh, W1h, W1l, b1, nullptr, Hh, nullptr, nullptr,
        16384, 1024, 1024, 512, 0, 1.f, nullptr, 0);

    // QKV weight concat transposes + bias concat
    transpose_splith<<<dim3(16, 16), tblk>>>(Wq, W3h,          W3l,          512, 512);
    transpose_splith<<<dim3(16, 16), tblk>>>(Wk, W3h + 131072, W3l + 131072, 512, 512);
    transpose_splith<<<dim3(16, 16), tblk>>>(Wv, W3h + 262144, W3l + 262144, 512, 512);
    cudaMemcpyAsync(bqkv,        bq, 512 * sizeof(float), cudaMemcpyDeviceToDevice);
    cudaMemcpyAsync(bqkv + 512,  bk, 512 * sizeof(float), cudaMemcpyDeviceToDevice);
    cudaMemcpyAsync(bqkv + 1024, bv, 512 * sizeof(float), cudaMemcpyDeviceToDevice);

    // proj L2: P = H @ W2^T + b2, fp16 out            [16384 x 512]
    gemm_mm<1,2,2,0,2><<<dim3(4, 128), blk, smem_p2>>>(
        Hh, W2h, W2l, b2, nullptr, Ph, nullptr, nullptr,
        16384, 512, 1024, 256, 0, 1.f, nullptr, 0);

    // fused QKV: [Q|K|V] = P @ [Wq;Wk;Wv]^T + bqkv    [16384 x 1536]
    gemm_mm<1,2,4,0,2><<<dim3(12, 128), blk, smem_p2>>>(
        Ph, W3h, W3l, bqkv, nullptr, Qh, Kh, Vh,
        16384, 1536, 512, 256, 0, 1.f, nullptr, 0);

    // V^T per half (fp16)
    transpose_h<<<dim3(16, 256), tblk>>>(Vh,         VT,        8192, 512);
    transpose_h<<<dim3(16, 256), tblk>>>(Vh + HALFW, VT + HVTW, 8192, 512);

    // fused scores (fp16 raw logits): rows 0-8191 = Qa@Kb^T, rows 8192.. = Qb@Ka^T
    gemm_mm<0,1,2,1,4><<<dim3(64, 128), blk, smem_p1k4>>>(
        Qh, Kh + HALFW, nullptr, nullptr, nullptr, Sh, nullptr, nullptr,
        16384, 8192, 512, 4096, 0, 1.f, Kh, 0);
    // fused in-place fp16 softmax (scale folded into exp)
    softmax_h<<<16384, blk>>>(Sh, inv_scale);
    // fused AV: rows 0-8191 -> out[:,0:512] (Vb), rows 8192-16383 -> out[:,512:1024] (Va)
    gemm_mm<0,1,0,2,4><<<dim3(4, 128), blk, smem_p1k4>>>(
        Sh, VT + HVTW, nullptr, nullptr, out, nullptr, nullptr, nullptr,
        16384, 512, 8192, 1024, 0, 1.f, VT, 512);
}

// round 13
// speedup vs baseline: 2.0212x; 1.1285x over previous
#include <cuda_runtime.h>
#include <cuda_fp16.h>
#include <math.h>

// ---------------------------------------------------------------------------
// Contrast on legacy mma.sync m16n8k16 (baseline PTX; harness targets sm_103).
// Everything fp16 single-product: activations and weights fp16, fp32 accum.
// All GEMMs: BK=64, 3-stage cp.async ring, ldmatrix fragments, 2 CTAs/SM.
// S fp16 end-to-end with in-place softmax (scale folded into exp).
// A/B directions fused per phase.
// ---------------------------------------------------------------------------

namespace {
constexpr int KBLK = 1032;             // u32 words per k16-block: 128*8 + 8 pad
}

// ------------------------------ scratch (u32 words) -------------------------
__device__ unsigned g_Zh [8388608];                   // (za|zb) fp16 16384x1024
__device__ unsigned g_Hh [8388608];                   // H fp16   16384x1024
__device__ unsigned g_Ph [4194304];                   // P fp16   16384x512
__device__ unsigned g_Qh [4194304];                   // Q fp16
__device__ unsigned g_Kh [4194304];                   // K fp16
__device__ unsigned g_Vh [4194304];                   // V fp16
__device__ unsigned g_VT [4194304];                   // V^T fp16 per half [512,8192]
__device__ unsigned g_W1h[524288];                    // W1^T fp16 [1024,1024]
__device__ unsigned g_W2h[262144];                    // W2^T fp16 [512,1024]
__device__ unsigned g_W3h[393216];                    // [Wq;Wk;Wv]^T fp16 [1536,512]
__device__ float    g_bqkv[1536];                     // concat biases
__device__ unsigned g_Sh [67108864];                  // fp16 scores 16384x4096w

// ------------------------------ helpers ------------------------------------
__device__ __forceinline__ void mma_fp16(float* c, const unsigned* a,
                                         unsigned b0, unsigned b1) {
    asm volatile(
        "mma.sync.aligned.m16n8k16.row.col.f32.f16.f16.f32 "
        "{%0,%1,%2,%3}, {%4,%5,%6,%7}, {%8,%9}, {%0,%1,%2,%3};"
        : "+f"(c[0]), "+f"(c[1]), "+f"(c[2]), "+f"(c[3])
        : "r"(a[0]), "r"(a[1]), "r"(a[2]), "r"(a[3]), "r"(b0), "r"(b1));
}

__device__ __forceinline__ void ldsm_x4(unsigned* r, unsigned addr) {
    asm volatile("ldmatrix.sync.aligned.m8n8.x4.shared.b16 {%0,%1,%2,%3}, [%4];"
        : "=r"(r[0]), "=r"(r[1]), "=r"(r[2]), "=r"(r[3]) : "r"(addr));
}

__device__ __forceinline__ void cp16(unsigned dst, const void* src) {
    asm volatile("cp.async.cg.shared.global [%0], [%1], 16;" :: "r"(dst), "l"(src));
}

__device__ __forceinline__ unsigned smem_u32(const void* p) {
    unsigned a;
    asm("{ .reg .u64 t; cvta.to.shared.u64 t, %1; cvt.u32.u64 %0, t; }"
        : "=r"(a) : "l"(p));
    return a;
}

__device__ __forceinline__ unsigned packh2(float x, float y) {
    __half2 h = __floats2half2_rn(x, y);
    return *reinterpret_cast<unsigned*>(&h);
}

// --------------------------- input pack (fp16) ------------------------------
__global__ void __launch_bounds__(256, 8)
pack_in(const float* __restrict__ za, const float* __restrict__ zb,
        unsigned* __restrict__ Zh)
{
    const size_t t = (size_t)blockIdx.x * 256 + threadIdx.x;
    const size_t f = t * 4;
    const float4 v = (f < (size_t)8388608)
        ? *reinterpret_cast<const float4*>(za + f)
        : *reinterpret_cast<const float4*>(zb + (f - 8388608));
    *reinterpret_cast<uint2*>(Zh + t * 2) =
        make_uint2(packh2(v.x, v.y), packh2(v.z, v.w));
}

// ----------------------- weight transpose + fp16 pack -----------------------
__global__ void __launch_bounds__(256, 4)
transpose_packh(const float* __restrict__ src, unsigned* __restrict__ dh, int R, int C)
{
    __shared__ float t[32][33];
    const int bx = blockIdx.x * 32;
    const int by = blockIdx.y * 32;
    const int x  = bx + threadIdx.x;
    #pragma unroll
    for (int i = threadIdx.y; i < 32; i += 8)
        t[i][threadIdx.x] = src[(size_t)(by + i) * C + x];
    __syncthreads();
    const int xo = by + threadIdx.x;
    unsigned short* ph = reinterpret_cast<unsigned short*>(dh);
    #pragma unroll
    for (int i = threadIdx.y; i < 32; i += 8)
        ph[(size_t)(bx + i) * R + xo] =
            __half_as_ushort(__float2half_rn(t[threadIdx.x][i]));
}

// --------------------------- fp16 transpose --------------------------------
__global__ void __launch_bounds__(256, 4)
transpose_h(const unsigned* __restrict__ srcw, unsigned* __restrict__ dstw, int R, int C)
{
    __shared__ unsigned short t[32][34];
    const unsigned short* src = reinterpret_cast<const unsigned short*>(srcw);
    unsigned short* dst = reinterpret_cast<unsigned short*>(dstw);
    const int bx = blockIdx.x * 32;
    const int by = blockIdx.y * 32;
    const int x  = bx + threadIdx.x;
    #pragma unroll
    for (int i = threadIdx.y; i < 32; i += 8)
        t[i][threadIdx.x] = src[(size_t)(by + i) * C + x];
    __syncthreads();
    const int xo = by + threadIdx.x;
    #pragma unroll
    for (int i = threadIdx.y; i < 32; i += 8)
        dst[(size_t)(bx + i) * R + xo] = t[threadIdx.x][i];
}

// ------------------------------ GEMM ---------------------------------------
// C = epi(A[M,K] @ B[N,K]^T), operands fp16-packed (u32 pitch K/2), fp32 accum.
// EPI 0: v*=scale ; EPI 1: v+=bias[col] ; EPI 2: elu(v+bias[col])
// OFMT 0: f32 Cf (+coff) ; OFMT 2: fp16 Ch ; OFMT 4: fp16 Q/K/V triple
// DUAL 0: none ; 1: second M-half uses Bh2 ; 2: second M-half Bh2+coff2, rows fold
// BK=64 (KT=4), 3-stage cp.async ring.
template <int EPI, int OFMT, int DUAL>
__global__ void __launch_bounds__(256, 2)
gemm_mm(const unsigned* __restrict__ Ah, const unsigned* __restrict__ Bh,
        const float* __restrict__ bias,
        float* __restrict__ Cf, unsigned* __restrict__ Ch, unsigned* __restrict__ Cl,
        unsigned* __restrict__ Cv,
        int M, int N, int K, int ldc, int coff, float scale,
        const unsigned* __restrict__ Bh2, int coff2)
{
    constexpr int KT = 4;
    extern __shared__ unsigned sm[];
    const unsigned tilesb = smem_u32(sm);
    constexpr unsigned SLBK  = (unsigned)KT * KBLK * 4u;   // 16512 B per half
    constexpr unsigned YOFFB = SLBK;
    constexpr unsigned BUFB  = 2u * SLBK;

    const int tid  = threadIdx.x;
    const int bm   = blockIdx.y * 128;
    const int bn   = blockIdx.x * 128;
    const int warp = tid >> 5;
    const int lane = tid & 31;
    const int wm   = (warp >> 2) * 64;
    const int wn   = (warp & 3) * 32;
    const int g    = lane >> 2;
    const int t2   = (lane & 3) * 2;

    const bool second = (DUAL != 0) && (bm >= (M >> 1));
    const unsigned* Bu = second ? Bh2 : Bh;
    const int co    = (DUAL == 2 && second) ? coff2 : coff;
    const int rfold = (DUAL == 2 && second) ? (M >> 1) : 0;

    // ldmatrix relative addresses (buffer 0, k-block 0)
    const int mi = lane >> 3;
    const int rl = (lane & 7) + ((mi & 1) << 3);
    const int kg = mi >> 1;
    unsigned relA[4], relB[2];
    #pragma unroll
    for (int mf = 0; mf < 4; mf++) {
        const int row = wm + mf * 16 + rl;
        const int w   = (kg << 2) ^ (((row >> 2) & 1) << 2);
        relA[mf] = tilesb + 4u * (unsigned)(row * 8 + w);
    }
    #pragma unroll
    for (int p = 0; p < 2; p++) {
        const int nf  = 2 * p + (mi >> 1);
        const int row = wn + nf * 8 + (lane & 7);
        const int w   = ((mi & 1) << 2) ^ (((row >> 2) & 1) << 2);
        relB[p] = tilesb + YOFFB + 4u * (unsigned)(row * 8 + w);
    }

    // staging mapping: 8 threads per 128-row, 4 row-passes of 32 rows
    constexpr int TPR     = 2 * KT;                // 8
    constexpr int RSTRIDE = 128 / KT;              // 32
    constexpr unsigned PBYTES = (unsigned)RSTRIDE * 32u;  // 1024
    const int srow  = tid / TPR;
    const int scol8 = (tid % TPR) * 8;
    const int sblk  = scol8 >> 4;
    const int sw0   = ((scol8 & 15) >> 1) ^ (((srow >> 2) & 1) * 4);
    const unsigned sidx0 = (unsigned)(sblk * KBLK + srow * 8 + sw0);
    const int kw = K >> 1;

    float acc[4][4][4];
    #pragma unroll
    for (int i = 0; i < 4; i++)
        #pragma unroll
        for (int j = 0; j < 4; j++)
            #pragma unroll
            for (int e = 0; e < 4; e++) acc[i][j][e] = 0.f;

    auto stage = [&](int kt, unsigned bufb) {
        const int w0 = kt * (8 * KT) + (scol8 >> 1);
        const unsigned d0 = tilesb + bufb + 4u * sidx0;
        #pragma unroll
        for (int i = 0; i < KT; i++)
            cp16(d0 + PBYTES * i, Ah + (size_t)(bm + srow + RSTRIDE * i) * kw + w0);
        #pragma unroll
        for (int i = 0; i < KT; i++)
            cp16(d0 + PBYTES * i + YOFFB, Bu + (size_t)(bn + srow + RSTRIDE * i) * kw + w0);
        asm volatile("cp.async.commit_group;" ::: "memory");
    };

    auto compute = [&](unsigned bufb) {
        #pragma unroll
        for (int blk = 0; blk < KT; blk++) {
            const unsigned off = bufb + (unsigned)(blk * (KBLK * 4));
            unsigned a[4][4], b[2][4];
            #pragma unroll
            for (int mf = 0; mf < 4; mf++) ldsm_x4(a[mf], relA[mf] + off);
            #pragma unroll
            for (int p = 0; p < 2; p++)    ldsm_x4(b[p],  relB[p] + off);
            #pragma unroll
            for (int mf = 0; mf < 4; mf++)
                #pragma unroll
                for (int nf = 0; nf < 4; nf++)
                    mma_fp16(acc[mf][nf], a[mf],
                             b[nf >> 1][(nf & 1) * 2], b[nf >> 1][(nf & 1) * 2 + 1]);
        }
    };

    const int ktiles = K / (16 * KT);
    stage(0, 0u);
    stage(1, BUFB);
    for (int kt = 0; kt < ktiles; kt++) {
        if (kt + 1 < ktiles) asm volatile("cp.async.wait_group 1;" ::: "memory");
        else                 asm volatile("cp.async.wait_group 0;" ::: "memory");
        __syncthreads();
        if (kt + 2 < ktiles) stage(kt + 2, (unsigned)((kt + 2) % 3) * BUFB);
        compute((unsigned)(kt % 3) * BUFB);
    }

    // epilogue
    #pragma unroll
    for (int mf = 0; mf < 4; mf++) {
        #pragma unroll
        for (int nf = 0; nf < 4; nf++) {
            const int row = bm + wm + mf * 16 + g - rfold;
            const int col = bn + wn + nf * 8 + t2;
            float v0 = acc[mf][nf][0], v1 = acc[mf][nf][1];
            float v2 = acc[mf][nf][2], v3 = acc[mf][nf][3];
            if (EPI == 0) {
                v0 *= scale; v1 *= scale; v2 *= scale; v3 *= scale;
            } else {
                const float bb0 = bias[col], bb1 = bias[col + 1];
                v0 += bb0; v1 += bb1; v2 += bb0; v3 += bb1;
                if (EPI == 2) {
                    v0 = v0 > 0.f ? v0 : __expf(v0) - 1.f;
                    v1 = v1 > 0.f ? v1 : __expf(v1) - 1.f;
                    v2 = v2 > 0.f ? v2 : __expf(v2) - 1.f;
                    v3 = v3 > 0.f ? v3 : __expf(v3) - 1.f;
                }
            }
            if (OFMT == 0) {
                *reinterpret_cast<float2*>(Cf + (size_t)row * ldc + co + col)       = make_float2(v0, v1);
                *reinterpret_cast<float2*>(Cf + (size_t)(row + 8) * ldc + co + col) = make_float2(v2, v3);
            } else if (OFMT == 2) {
                Ch[(size_t)row * ldc + (col >> 1)]       = packh2(v0, v1);
                Ch[(size_t)(row + 8) * ldc + (col >> 1)] = packh2(v2, v3);
            } else {    // OFMT 4: Q/K/V triple by global column
                unsigned* dst; int cc;
                if (col < 512)       { dst = Ch; cc = col; }
                else if (col < 1024) { dst = Cl; cc = col - 512; }
                else                 { dst = Cv; cc = col - 1024; }
                dst[(size_t)row * ldc + (cc >> 1)]       = packh2(v0, v1);
                dst[(size_t)(row + 8) * ldc + (cc >> 1)] = packh2(v2, v3);
            }
        }
    }
}

// ------------------- softmax (fp16 in-place, folded scale) ------------------
__global__ void __launch_bounds__(256, 1)
softmax_h(unsigned* __restrict__ Sh, float inv_scale)
{
    const int row = blockIdx.x;
    uint4* p = reinterpret_cast<uint4*>(Sh + (size_t)row * 4096);
    const int tid = threadIdx.x;

    uint4 w[4];
    #pragma unroll
    for (int i = 0; i < 4; i++) w[i] = p[tid + 256 * i];

    float f[32];
    #pragma unroll
    for (int i = 0; i < 4; i++) {
        const unsigned* u = reinterpret_cast<const unsigned*>(&w[i]);
        #pragma unroll
        for (int j = 0; j < 4; j++) {
            float2 d = __half22float2(*reinterpret_cast<const __half2*>(&u[j]));
            f[i * 8 + j * 2]     = d.x;
            f[i * 8 + j * 2 + 1] = d.y;
        }
    }

    float m = -3.402823e38f;
    #pragma unroll
    for (int i = 0; i < 32; i++) m = fmaxf(m, f[i]);

    __shared__ float red[8];
    #pragma unroll
    for (int o = 16; o; o >>= 1) m = fmaxf(m, __shfl_xor_sync(0xffffffffu, m, o));
    if ((tid & 31) == 0) red[tid >> 5] = m;
    __syncthreads();
    float mm = red[0];
    #pragma unroll
    for (int i = 1; i < 8; i++) mm = fmaxf(mm, red[i]);

    float s = 0.f;
    #pragma unroll
    for (int i = 0; i < 32; i++) { f[i] = __expf((f[i] - mm) * inv_scale); s += f[i]; }
    #pragma unroll
    for (int o = 16; o; o >>= 1) s += __shfl_xor_sync(0xffffffffu, s, o);
    __syncthreads();
    if ((tid & 31) == 0) red[tid >> 5] = s;
    __syncthreads();
    float st = 0.f;
    #pragma unroll
    for (int i = 0; i < 8; i++) st += red[i];
    const float inv = 1.0f / st;

    #pragma unroll
    for (int i = 0; i < 4; i++) {
        unsigned* u = reinterpret_cast<unsigned*>(&w[i]);
        #pragma unroll
        for (int j = 0; j < 4; j++)
            u[j] = packh2(f[i * 8 + j * 2] * inv, f[i * 8 + j * 2 + 1] * inv);
    }
    #pragma unroll
    for (int i = 0; i < 4; i++) p[tid + 256 * i] = w[i];
}

// ------------------------------ launcher -----------------------------------
extern "C" void kernel_launch(void* const* d_in, const int* in_sizes, int n_in,
                              void* d_out, int out_size)
{
    const float* za = (const float*)d_in[0];
    const float* zb = (const float*)d_in[1];
    const float* W1 = (const float*)d_in[2];
    const float* b1 = (const float*)d_in[3];
    const float* W2 = (const float*)d_in[4];
    const float* b2 = (const float*)d_in[5];
    const float* Wq = (const float*)d_in[6];
    const float* bq = (const float*)d_in[7];
    const float* Wk = (const float*)d_in[8];
    const float* bk = (const float*)d_in[9];
    const float* Wv = (const float*)d_in[10];
    const float* bv = (const float*)d_in[11];
    float* out = (float*)d_out;

    unsigned *Zh, *Hh, *Ph, *Qh, *Kh, *Vh, *VT, *W1h, *W2h, *W3h, *Sh;
    float *bqkv;
    cudaGetSymbolAddress((void**)&Zh,  g_Zh);
    cudaGetSymbolAddress((void**)&Hh,  g_Hh);  cudaGetSymbolAddress((void**)&Ph,  g_Ph);
    cudaGetSymbolAddress((void**)&Qh,  g_Qh);  cudaGetSymbolAddress((void**)&Kh,  g_Kh);
    cudaGetSymbolAddress((void**)&Vh,  g_Vh);  cudaGetSymbolAddress((void**)&VT,  g_VT);
    cudaGetSymbolAddress((void**)&W1h, g_W1h); cudaGetSymbolAddress((void**)&W2h, g_W2h);
    cudaGetSymbolAddress((void**)&W3h, g_W3h);
    cudaGetSymbolAddress((void**)&Sh,  g_Sh);  cudaGetSymbolAddress((void**)&bqkv, g_bqkv);

    const int smem_g = 3 * 2 * (4 * KBLK * 4);   // 99072 B (fp16 single, KT=4)
    cudaFuncSetAttribute(gemm_mm<2,2,0>, cudaFuncAttributeMaxDynamicSharedMemorySize, smem_g);
    cudaFuncSetAttribute(gemm_mm<1,2,0>, cudaFuncAttributeMaxDynamicSharedMemorySize, smem_g);
    cudaFuncSetAttribute(gemm_mm<1,4,0>, cudaFuncAttributeMaxDynamicSharedMemorySize, smem_g);
    cudaFuncSetAttribute(gemm_mm<0,2,1>, cudaFuncAttributeMaxDynamicSharedMemorySize, smem_g);
    cudaFuncSetAttribute(gemm_mm<0,0,2>, cudaFuncAttributeMaxDynamicSharedMemorySize, smem_g);

    const dim3 blk(256);
    const dim3 tblk(32, 8);
    const float inv_scale = 1.0f / 16.0f;   // 1/sqrt(OUT/2)
    const size_t HALFW = (size_t)8192 * 256;   // half of Q/K/V word arrays
    const size_t HVTW  = (size_t)512 * 4096;   // half of VT

    // kernel launches 1-3 (capture slot #4 = L1 GEMM)
    pack_in<<<16384, blk>>>(za, zb, Zh);
    transpose_packh<<<dim3(32, 32), tblk>>>(W1, W1h, 1024, 1024);
    transpose_packh<<<dim3(16, 32), tblk>>>(W2, W2h, 1024, 512);

    // #4: proj L1: H = ELU(Z @ W1^T + b1), fp16 out   [16384 x 1024]
    gemm_mm<2,2,0><<<dim3(8, 128), blk, smem_g>>>(
        Zh, W1h, b1, nullptr, Hh, nullptr, nullptr,
        16384, 1024, 1024, 512, 0, 1.f, nullptr, 0);

    // QKV weight concat transposes + bias concat
    transpose_packh<<<dim3(16, 16), tblk>>>(Wq, W3h,          512, 512);
    transpose_packh<<<dim3(16, 16), tblk>>>(Wk, W3h + 131072, 512, 512);
    transpose_packh<<<dim3(16, 16), tblk>>>(Wv, W3h + 262144, 512, 512);
    cudaMemcpyAsync(bqkv,        bq, 512 * sizeof(float), cudaMemcpyDeviceToDevice);
    cudaMemcpyAsync(bqkv + 512,  bk, 512 * sizeof(float), cudaMemcpyDeviceToDevice);
    cudaMemcpyAsync(bqkv + 1024, bv, 512 * sizeof(float), cudaMemcpyDeviceToDevice);

    // proj L2: P = H @ W2^T + b2, fp16 out            [16384 x 512]
    gemm_mm<1,2,0><<<dim3(4, 128), blk, smem_g>>>(
        Hh, W2h, b2, nullptr, Ph, nullptr, nullptr,
        16384, 512, 1024, 256, 0, 1.f, nullptr, 0);

    // fused QKV: [Q|K|V] = P @ [Wq;Wk;Wv]^T + bqkv    [16384 x 1536]
    gemm_mm<1,4,0><<<dim3(12, 128), blk, smem_g>>>(
        Ph, W3h, bqkv, nullptr, Qh, Kh, Vh,
        16384, 1536, 512, 256, 0, 1.f, nullptr, 0);

    // V^T per half (fp16)
    transpose_h<<<dim3(16, 256), tblk>>>(Vh,         VT,        8192, 512);
    transpose_h<<<dim3(16, 256), tblk>>>(Vh + HALFW, VT + HVTW, 8192, 512);

    // fused scores (fp16 raw logits): rows 0-8191 = Qa@Kb^T, rows 8192.. = Qb@Ka^T
    gemm_mm<0,2,1><<<dim3(64, 128), blk, smem_g>>>(
        Qh, Kh + HALFW, nullptr, nullptr, Sh, nullptr, nullptr,
        16384, 8192, 512, 4096, 0, 1.f, Kh, 0);
    // fused in-place fp16 softmax (scale folded into exp)
    softmax_h<<<16384, blk>>>(Sh, inv_scale);
    // fused AV: rows 0-8191 -> out[:,0:512] (Vb), rows 8192-16383 -> out[:,512:1024] (Va)
    gemm_mm<0,0,2><<<dim3(4, 128), blk, smem_g>>>(
        Sh, VT + HVTW, nullptr, out, nullptr, nullptr, nullptr,
        16384, 512, 8192, 1024, 0, 1.f, VT, 512);
}